// round 8
// baseline (speedup 1.0000x reference)
#include <cuda_runtime.h>
#include <cstdint>

// Problem constants
#define B_ 4
#define L_ 4096
#define DIM_ 1024
#define H_ 16
#define NCHUNK_ 64
#define CHUNK_ 64
#define M_ (B_ * L_)          // 16384

// ---------------------------------------------------------------------------
// Device scratch (allocation-free contract: __device__ globals)
// ---------------------------------------------------------------------------
__device__ float g_q[(size_t)B_ * L_ * 1024];
__device__ float g_k[(size_t)B_ * L_ * 1024];
__device__ float g_v[(size_t)B_ * L_ * 1024];
__device__ float g_o[(size_t)B_ * L_ * 1024];   // scan writes tf32 bits directly
__device__ float g_xt[(size_t)B_ * L_ * 1024];  // tf32(x)
__device__ float g_wt[4u * 1024u * 1024u];      // tf32(Wq,Wk,Wv,Wo)
__device__ float g_lrwd[B_ * NCHUNK_ * 64];

// ---------------------------------------------------------------------------
// PTX helpers
// ---------------------------------------------------------------------------
__device__ __forceinline__ float cvt_tf32f(float f) {
    uint32_t u;
    asm("cvt.rna.tf32.f32 %0, %1;" : "=r"(u) : "f"(f));
    return __uint_as_float(u);
}

__device__ __forceinline__ void cp16(void* smem, const void* gmem) {
    uint32_t s = (uint32_t)__cvta_generic_to_shared(smem);
    asm volatile("cp.async.cg.shared.global [%0], [%1], 16;" :: "r"(s), "l"(gmem));
}
__device__ __forceinline__ void cp_commit() {
    asm volatile("cp.async.commit_group;");
}
template <int N>
__device__ __forceinline__ void cp_wait() {
    asm volatile("cp.async.wait_group %0;" :: "n"(N));
}

__device__ __forceinline__ void mma_tf32(float c[4],
                                         uint32_t a0, uint32_t a1, uint32_t a2, uint32_t a3,
                                         uint32_t b0, uint32_t b1) {
    asm volatile(
        "mma.sync.aligned.m16n8k8.row.col.f32.tf32.tf32.f32 "
        "{%0,%1,%2,%3}, {%4,%5,%6,%7}, {%8,%9}, {%0,%1,%2,%3};"
        : "+f"(c[0]), "+f"(c[1]), "+f"(c[2]), "+f"(c[3])
        : "r"(a0), "r"(a1), "r"(a2), "r"(a3), "r"(b0), "r"(b1));
}

__device__ __forceinline__ uint32_t mapa_u32(uint32_t addr, uint32_t rank) {
    uint32_t r;
    asm("mapa.shared::cluster.u32 %0, %1, %2;" : "=r"(r) : "r"(addr), "r"(rank));
    return r;
}
__device__ __forceinline__ float ld_dsmem(uint32_t addr) {
    float v;
    asm volatile("ld.shared::cluster.f32 %0, [%1];" : "=f"(v) : "r"(addr));
    return v;
}
#define CLUSTER_SYNC() do { \
    asm volatile("barrier.cluster.arrive.aligned;" ::: "memory"); \
    asm volatile("barrier.cluster.wait.aligned;" ::: "memory"); } while (0)

// ---------------------------------------------------------------------------
// tf32 pre-convert
// ---------------------------------------------------------------------------
__global__ __launch_bounds__(256)
void cvt_kernel(const float* __restrict__ src, float* __restrict__ dst, int n4)
{
    int i = blockIdx.x * 256 + threadIdx.x;
    if (i < n4) {
        float4 v = ((const float4*)src)[i];
        v.x = cvt_tf32f(v.x); v.y = cvt_tf32f(v.y);
        v.z = cvt_tf32f(v.z); v.w = cvt_tf32f(v.w);
        ((float4*)dst)[i] = v;
    }
}

// ---------------------------------------------------------------------------
// TF32 tensor-core GEMM (NT), pre-converted inputs, 3-stage cp.async.
// ---------------------------------------------------------------------------
#define GEMM_SMEM_BYTES (3 * 2 * 128 * 20 * 4)

template <int ACT>
__global__ __launch_bounds__(256)
void gemm_tf32p(const float* __restrict__ A, const float* __restrict__ W,
                float* __restrict__ C, int M, int N, int K)
{
    extern __shared__ __align__(16) float gsm[];
    float (*As)[128][20] = (float (*)[128][20])gsm;
    float (*Bs)[128][20] = (float (*)[128][20])(gsm + 3 * 128 * 20);

    const int t    = threadIdx.x;
    const int bm   = blockIdx.y * 128;
    const int bn   = blockIdx.x * 128;
    const int w    = t >> 5;
    const int lane = t & 31;
    const int wm   = (w >> 2) * 64;
    const int wn   = (w & 3) * 32;
    const int g    = lane >> 2;
    const int t4   = lane & 3;

    float acc[4][4][4];
#pragma unroll
    for (int mt = 0; mt < 4; mt++)
#pragma unroll
        for (int nt = 0; nt < 4; nt++)
#pragma unroll
            for (int c = 0; c < 4; c++) acc[mt][nt][c] = 0.f;

    const int KT = K >> 4;

    auto load_stage = [&](int kb, int buf) {
        const int k0 = kb * 16;
#pragma unroll
        for (int s = 0; s < 2; s++) {
            int j   = t + s * 256;
            int row = j >> 2;
            int c4  = (j & 3) * 4;
            cp16(&As[buf][row][c4], A + (size_t)(bm + row) * K + k0 + c4);
            cp16(&Bs[buf][row][c4], W + (size_t)(bn + row) * K + k0 + c4);
        }
    };

    load_stage(0, 0); cp_commit();
    load_stage(1, 1); cp_commit();

    for (int kb = 0; kb < KT; kb++) {
        cp_wait<1>();
        __syncthreads();
        if (kb + 2 < KT) { load_stage(kb + 2, (kb + 2) % 3); cp_commit(); }
        else             { cp_commit(); }
        const int buf = kb % 3;

#pragma unroll
        for (int ks = 0; ks < 2; ks++) {
            const int k0 = ks * 8;
            uint32_t bf[4][2];
#pragma unroll
            for (int nt = 0; nt < 4; nt++) {
                bf[nt][0] = __float_as_uint(Bs[buf][wn + nt * 8 + g][k0 + t4]);
                bf[nt][1] = __float_as_uint(Bs[buf][wn + nt * 8 + g][k0 + t4 + 4]);
            }
#pragma unroll
            for (int mt = 0; mt < 4; mt++) {
                uint32_t a0 = __float_as_uint(As[buf][wm + mt * 16 + g][k0 + t4]);
                uint32_t a1 = __float_as_uint(As[buf][wm + mt * 16 + g + 8][k0 + t4]);
                uint32_t a2 = __float_as_uint(As[buf][wm + mt * 16 + g][k0 + t4 + 4]);
                uint32_t a3 = __float_as_uint(As[buf][wm + mt * 16 + g + 8][k0 + t4 + 4]);
#pragma unroll
                for (int nt = 0; nt < 4; nt++)
                    mma_tf32(acc[mt][nt], a0, a1, a2, a3, bf[nt][0], bf[nt][1]);
            }
        }
        __syncthreads();
    }

#pragma unroll
    for (int mt = 0; mt < 4; mt++) {
#pragma unroll
        for (int nt = 0; nt < 4; nt++) {
            int m = bm + wm + mt * 16 + g;
            int n = bn + wn + nt * 8 + t4 * 2;
            float2 v0 = make_float2(acc[mt][nt][0], acc[mt][nt][1]);
            float2 v1 = make_float2(acc[mt][nt][2], acc[mt][nt][3]);
            if (ACT == 1) {
                v0.x = v0.x / (1.f + __expf(-v0.x));
                v0.y = v0.y / (1.f + __expf(-v0.y));
                v1.x = v1.x / (1.f + __expf(-v1.x));
                v1.y = v1.y / (1.f + __expf(-v1.y));
            }
            *(float2*)&C[(size_t)m * N + n]       = v0;
            *(float2*)&C[(size_t)(m + 8) * N + n] = v1;
        }
    }
}

// ---------------------------------------------------------------------------
// lr/wd chunk means
// ---------------------------------------------------------------------------
__global__ __launch_bounds__(256, 2)
void lrwd_kernel(const float* __restrict__ x,
                 const float* __restrict__ Wlr,
                 const float* __restrict__ Wbeta)
{
    __shared__ float xs[64][65];
    __shared__ float ws[64][65];
    __shared__ float red2[64 * 16];

    const int bc = blockIdx.x;
    const size_t xb = (size_t)bc * 64 * 1024;
    const int t  = threadIdx.x;
    const int r0 = t >> 4;
    const int c0 = t & 15;

    float acc[4][4];
#pragma unroll
    for (int i = 0; i < 4; i++)
#pragma unroll
        for (int j = 0; j < 4; j++) acc[i][j] = 0.f;

    for (int k0 = 0; k0 < 1024; k0 += 64) {
        for (int i = t; i < 4096; i += 256) {
            int n = i >> 6, d = i & 63;
            xs[n][d] = x[xb + (size_t)n * 1024 + k0 + d];
            ws[n][d] = (n < 32) ? Wlr[n * 1024 + k0 + d]
                                : Wbeta[(n - 32) * 1024 + k0 + d];
        }
        __syncthreads();
#pragma unroll 4
        for (int k = 0; k < 64; k++) {
            float a[4], b[4];
#pragma unroll
            for (int ii = 0; ii < 4; ii++) a[ii] = xs[r0 + 16 * ii][k];
#pragma unroll
            for (int jj = 0; jj < 4; jj++) b[jj] = ws[c0 + 16 * jj][k];
#pragma unroll
            for (int ii = 0; ii < 4; ii++)
#pragma unroll
                for (int jj = 0; jj < 4; jj++) acc[ii][jj] += a[ii] * b[jj];
        }
        __syncthreads();
    }

#pragma unroll
    for (int jj = 0; jj < 4; jj++) {
        int j = c0 + 16 * jj;
        float scale = (j < 32) ? 0.001f : 0.9f;
        float p = 0.f;
#pragma unroll
        for (int ii = 0; ii < 4; ii++)
            p += scale / (1.f + __expf(-acc[ii][jj]));
        red2[j * 16 + r0] = p;
    }
    __syncthreads();
    if (t < 64) {
        float s = 0.f;
        for (int r = 0; r < 16; r++) s += red2[t * 16 + r];
        g_lrwd[bc * 64 + t] = s * (1.f / 64.f);
    }
}

// ---------------------------------------------------------------------------
// Cluster-2 persistent scan, 512 threads/CTA (16 warps — latency hiding).
// ---------------------------------------------------------------------------
#define P64 65
#define P32 33
#define ST_ 512

#define OFF_WI   0                           // [32][65]
#define OFF_WO   (32 * P64)
#define OFF_Q    (2 * 32 * P64)              // [64][65]
#define OFF_K    (OFF_Q + 64 * P64)
#define OFF_V    (OFF_K + 64 * P64)
#define OFF_PQ   (OFF_V + 64 * P64)          // [64][33]
#define OFF_PK   (OFF_PQ + 64 * P32)
#define OFF_AM   (OFF_PK + 64 * P32)
#define OFF_OP   (OFF_AM + 64 * P32)         // [64][65]
#define OFF_SP   (OFF_OP + 64 * P64)
#define OFF_SS   (OFF_SP + 64)
#define OFF_RED  (OFF_SS + 64)               // [8][64]
#define OFF_CS   (OFF_RED + 512)
#define SCAN_SMEM_FLOATS (OFF_CS + 64)       // 27840 floats -> 111360 bytes

__global__ __launch_bounds__(ST_, 1) __cluster_dims__(2, 1, 1)
void scan_kernel(const float* __restrict__ Win0, const float* __restrict__ Wout0)
{
    extern __shared__ float sm[];
    float* Wi  = sm + OFF_WI;
    float* Wo_ = sm + OFF_WO;
    float* Q   = sm + OFF_Q;
    float* Kt  = sm + OFF_K;
    float* V   = sm + OFF_V;
    float* Pq  = sm + OFF_PQ;
    float* Pk  = sm + OFF_PK;
    float* Am  = sm + OFF_AM;
    float* op  = sm + OFF_OP;
    float* sp  = sm + OFF_SP;
    float* ss  = sm + OFF_SS;
    float* red = sm + OFF_RED;
    float* cs  = sm + OFF_CS;

    const int pair = blockIdx.x >> 1;
    const uint32_t rank = blockIdx.x & 1;
    const int b = pair >> 4;
    const int h = pair & 15;
    const int t = threadIdx.x;

    const int r8  = t >> 3, c8  = t & 7;    // 64x8  (logits: 1 q-row + 1 k-row, 4 cols)
    const int ro  = t >> 5, co  = t & 31;   // 16x32 (o: 4 rows x 2 cols)
    const int ra  = t >> 4, ca  = t & 15;   // 32x16 (a: 2 rows x 2 cols)
    const int rg2 = t >> 6, cg2 = t & 63;   // 8x64  (grads: 4 rows x 1 col)
    const int task = t & 63, sg = t >> 6;   // softmax: 64 col-tasks x 8 segments

    const uint32_t op_peer = mapa_u32((uint32_t)__cvta_generic_to_shared(op), rank ^ 1u);
    const uint32_t sp_peer = mapa_u32((uint32_t)__cvta_generic_to_shared(sp), rank ^ 1u);

    // init state halves
    for (int i = t; i < 2048; i += ST_) {
        int Dl = i >> 6, d = i & 63;
        int Dg = (int)rank * 32 + Dl;
        Wi [Dl * P64 + d] = Win0 [Dg * 1024 + h * 64 + d];
        Wo_[Dl * P64 + d] = Wout0[Dg * 1024 + h * 64 + d];
    }
    __syncthreads();

    for (int c = 0; c < NCHUNK_; c++) {
        const size_t base = ((size_t)b * L_ + (size_t)c * 64) * 1024 + h * 64;
        const int lb = (b * 64 + c) * 64;
        const float li  = g_lrwd[lb + h];
        const float lo  = g_lrwd[lb + 16 + h];
        const float wdi = g_lrwd[lb + 32 + h];
        const float wdo = g_lrwd[lb + 48 + h];

        // ---- P1: load q,k,v tiles (float4 LDG)
        for (int i = t; i < 1024; i += ST_) {
            int n = i >> 4, d4 = (i & 15) * 4;
            size_t gidx = base + (size_t)n * 1024 + d4;
            float4 a = *(const float4*)&g_q[gidx];
            float4 e = *(const float4*)&g_k[gidx];
            float4 f = *(const float4*)&g_v[gidx];
            Q [n * P64 + d4] = a.x; Q [n * P64 + d4 + 1] = a.y; Q [n * P64 + d4 + 2] = a.z; Q [n * P64 + d4 + 3] = a.w;
            Kt[n * P64 + d4] = e.x; Kt[n * P64 + d4 + 1] = e.y; Kt[n * P64 + d4 + 2] = e.z; Kt[n * P64 + d4 + 3] = e.w;
            V [n * P64 + d4] = f.x; V [n * P64 + d4 + 1] = f.y; V [n * P64 + d4 + 2] = f.z; V [n * P64 + d4 + 3] = f.w;
        }
        __syncthreads();

        // ---- P2: fused q/k logits vs Wi; thread = (row r8, 4 cols c8+8j)
        {
            float aq[4], ak[4];
#pragma unroll
            for (int j = 0; j < 4; j++) { aq[j] = 0.f; ak[j] = 0.f; }
#pragma unroll 4
            for (int k = 0; k < 64; k++) {
                float q0 = Q [r8 * P64 + k];
                float k0 = Kt[r8 * P64 + k];
                float bw[4];
#pragma unroll
                for (int j = 0; j < 4; j++) bw[j] = Wi[(c8 + 8 * j) * P64 + k];
#pragma unroll
                for (int j = 0; j < 4; j++) {
                    aq[j] += q0 * bw[j];
                    ak[j] += k0 * bw[j];
                }
            }
#pragma unroll
            for (int j = 0; j < 4; j++) {
                Pq[r8 * P32 + c8 + 8 * j] = aq[j];
                Pk[r8 * P32 + c8 + 8 * j] = ak[j];
            }
        }
        __syncthreads();

        // ---- P3: merged softmax (64 col-tasks: 32 Pq + 32 Pk; 8 segments of 8 rows)
        {
            float* Pp = (task < 32) ? Pq : Pk;
            const int D = task & 31;
            float m = -1e30f;
#pragma unroll
            for (int n = sg * 8; n < sg * 8 + 8; n++) m = fmaxf(m, Pp[n * P32 + D]);
            red[sg * 64 + task] = m;
            __syncthreads();
            if (t < 64) {
                float mm = red[t];
#pragma unroll
                for (int j = 1; j < 8; j++) mm = fmaxf(mm, red[j * 64 + t]);
                cs[t] = mm;
            }
            __syncthreads();
            float mm = cs[task], s = 0.f;
#pragma unroll
            for (int n = sg * 8; n < sg * 8 + 8; n++) {
                float e = __expf(Pp[n * P32 + D] - mm);
                Pp[n * P32 + D] = e;
                s += e;
            }
            red[sg * 64 + task] = s;
            __syncthreads();
            if (t < 64) {
                float s2 = 0.f;
#pragma unroll
                for (int j = 0; j < 8; j++) s2 += red[j * 64 + t];
                cs[t] = 1.f / s2;
            }
            __syncthreads();
            float inv = cs[task];
#pragma unroll
            for (int n = sg * 8; n < sg * 8 + 8; n++) Pp[n * P32 + D] *= inv;
        }
        __syncthreads();

        // ---- P4: op (partial o) and a, one phase
        {
            // op[n][d] = sum_Dl Pq[n][Dl]*Wo_[Dl][d]; thread = rows ro+16i, cols co+32j
            float acc[4][2];
#pragma unroll
            for (int i = 0; i < 4; i++) { acc[i][0] = 0.f; acc[i][1] = 0.f; }
#pragma unroll 4
            for (int k = 0; k < 32; k++) {
                float a[4];
#pragma unroll
                for (int i = 0; i < 4; i++) a[i] = Pq[(ro + 16 * i) * P32 + k];
                float b0 = Wo_[k * P64 + co], b1 = Wo_[k * P64 + co + 32];
#pragma unroll
                for (int i = 0; i < 4; i++) {
                    acc[i][0] += a[i] * b0;
                    acc[i][1] += a[i] * b1;
                }
            }
#pragma unroll
            for (int i = 0; i < 4; i++) {
                op[(ro + 16 * i) * P64 + co]      = acc[i][0];
                op[(ro + 16 * i) * P64 + co + 32] = acc[i][1];
            }

            // a[n][Dl] = sum_d V[n][d]*Wo_[Dl][d]; thread = rows ra, ra+32; cols ca, ca+16
            float av[2][2];
            av[0][0] = av[0][1] = av[1][0] = av[1][1] = 0.f;
#pragma unroll 4
            for (int k = 0; k < 64; k++) {
                float v0 = V[ra * P64 + k], v1 = V[(ra + 32) * P64 + k];
                float b0 = Wo_[ca * P64 + k], b1 = Wo_[(ca + 16) * P64 + k];
                av[0][0] += v0 * b0; av[0][1] += v0 * b1;
                av[1][0] += v1 * b0; av[1][1] += v1 * b1;
            }
            Am[ra * P32 + ca]             = av[0][0];
            Am[ra * P32 + ca + 16]        = av[0][1];
            Am[(ra + 32) * P32 + ca]      = av[1][0];
            Am[(ra + 32) * P32 + ca + 16] = av[1][1];
        }
        __syncthreads();
        CLUSTER_SYNC();

        // ---- P5: o = op_self + op_peer (tf32-converted at store); sp
        for (int i = t; i < 2048; i += ST_) {
            int n = (int)rank * 32 + (i >> 6), d = i & 63;
            float v2 = op[n * P64 + d] + ld_dsmem(op_peer + (uint32_t)(n * P64 + d) * 4u);
            g_o[base + (size_t)n * 1024 + d] = cvt_tf32f(v2);
        }
        if (t < 64) {
            float s = 0.f;
#pragma unroll 8
            for (int Dl = 0; Dl < 32; Dl++) s += Pk[t * P32 + Dl] * Am[t * P32 + Dl];
            sp[t] = s;
        }
        __syncthreads();
        CLUSTER_SYNC();

        // ---- P6: total s
        if (t < 64) ss[t] = sp[t] + ld_dsmem(sp_peer + (uint32_t)t * 4u);
        __syncthreads();

        // ---- P7: grads (g_z inline) + state update; thread = rows rg2+8i, col cg2
        {
            float gin[4], gout[4];
#pragma unroll
            for (int i = 0; i < 4; i++) { gin[i] = 0.f; gout[i] = 0.f; }
#pragma unroll 4
            for (int n = 0; n < 64; n++) {
                float ssn = ss[n];
                float kk = Kt[n * P64 + cg2];
                float vv = V [n * P64 + cg2];
#pragma unroll
                for (int i = 0; i < 4; i++) {
                    float pk = Pk[n * P32 + rg2 + 8 * i];
                    float am = Am[n * P32 + rg2 + 8 * i];
                    float gz = -pk * (am - ssn);
                    gin[i]  += gz * kk;
                    gout[i] += pk * vv;
                }
            }
#pragma unroll
            for (int i = 0; i < 4; i++) {
                int idx = (rg2 + 8 * i) * P64 + cg2;
                Wi [idx] = wdi * Wi [idx] - li * gin[i];
                Wo_[idx] = wdo * Wo_[idx] + lo * gout[i];
            }
        }
        __syncthreads();
    }
    CLUSTER_SYNC();   // keep smem alive for peer's in-flight DSMEM reads
}

// ---------------------------------------------------------------------------
// Launch
// ---------------------------------------------------------------------------
extern "C" void kernel_launch(void* const* d_in, const int* in_sizes, int n_in,
                              void* d_out, int out_size)
{
    (void)in_sizes; (void)n_in; (void)out_size;
    const float* x     = (const float*)d_in[0];
    const float* Wq    = (const float*)d_in[1];
    const float* Wk    = (const float*)d_in[2];
    const float* Wv    = (const float*)d_in[3];
    const float* Wlr   = (const float*)d_in[4];
    const float* Wbeta = (const float*)d_in[5];
    const float* Wo    = (const float*)d_in[6];
    const float* Win0  = (const float*)d_in[7];
    const float* Wout0 = (const float*)d_in[8];
    float* out = (float*)d_out;

    float *q, *k, *v, *om, *xt, *wt;
    cudaGetSymbolAddress((void**)&q,  g_q);
    cudaGetSymbolAddress((void**)&k,  g_k);
    cudaGetSymbolAddress((void**)&v,  g_v);
    cudaGetSymbolAddress((void**)&om, g_o);
    cudaGetSymbolAddress((void**)&xt, g_xt);
    cudaGetSymbolAddress((void**)&wt, g_wt);

    cudaFuncSetAttribute(gemm_tf32p<0>, cudaFuncAttributeMaxDynamicSharedMemorySize, GEMM_SMEM_BYTES);
    cudaFuncSetAttribute(gemm_tf32p<1>, cudaFuncAttributeMaxDynamicSharedMemorySize, GEMM_SMEM_BYTES);
    cudaFuncSetAttribute(scan_kernel,   cudaFuncAttributeMaxDynamicSharedMemorySize,
                         SCAN_SMEM_FLOATS * (int)sizeof(float));

    const int NX4 = (M_ * 1024) / 4;
    const int NW4 = (1024 * 1024) / 4;
    cvt_kernel<<<(NX4 + 255) / 256, 256>>>(x,  xt,            NX4);
    cvt_kernel<<<(NW4 + 255) / 256, 256>>>(Wq, wt + 0u * 1024u * 1024u, NW4);
    cvt_kernel<<<(NW4 + 255) / 256, 256>>>(Wk, wt + 1u * 1024u * 1024u, NW4);
    cvt_kernel<<<(NW4 + 255) / 256, 256>>>(Wv, wt + 2u * 1024u * 1024u, NW4);
    cvt_kernel<<<(NW4 + 255) / 256, 256>>>(Wo, wt + 3u * 1024u * 1024u, NW4);

    dim3 grid(1024 / 128, M_ / 128);
    gemm_tf32p<1><<<grid, 256, GEMM_SMEM_BYTES>>>(xt, wt + 0u * 1024u * 1024u, q, M_, 1024, 1024);
    gemm_tf32p<1><<<grid, 256, GEMM_SMEM_BYTES>>>(xt, wt + 1u * 1024u * 1024u, k, M_, 1024, 1024);
    gemm_tf32p<0><<<grid, 256, GEMM_SMEM_BYTES>>>(xt, wt + 2u * 1024u * 1024u, v, M_, 1024, 1024);
    lrwd_kernel<<<B_ * NCHUNK_, 256>>>(x, Wlr, Wbeta);

    const int smem_bytes = SCAN_SMEM_FLOATS * (int)sizeof(float);
    scan_kernel<<<128, ST_, smem_bytes>>>(Win0, Wout0);

    // g_o already holds tf32 bits — final GEMM reads it directly
    gemm_tf32p<0><<<grid, 256, GEMM_SMEM_BYTES>>>(om, wt + 3u * 1024u * 1024u, out, M_, 1024, 1024);
}

// round 10
// speedup vs baseline: 1.0587x; 1.0587x over previous
#include <cuda_runtime.h>
#include <cstdint>

// Problem constants
#define B_ 4
#define L_ 4096
#define DIM_ 1024
#define H_ 16
#define NCHUNK_ 64
#define CHUNK_ 64
#define M_ (B_ * L_)          // 16384

// ---------------------------------------------------------------------------
// Device scratch (allocation-free contract: __device__ globals)
// ---------------------------------------------------------------------------
__device__ float g_q[(size_t)B_ * L_ * 1024];
__device__ float g_k[(size_t)B_ * L_ * 1024];
__device__ float g_v[(size_t)B_ * L_ * 1024];
__device__ float g_o[(size_t)B_ * L_ * 1024];   // scan writes tf32 bits directly
__device__ float g_xt[(size_t)B_ * L_ * 1024];  // tf32(x)
__device__ float g_wt[4u * 1024u * 1024u];      // tf32(Wq,Wk,Wv,Wo)
__device__ float g_lrwd[B_ * NCHUNK_ * 64];

// ---------------------------------------------------------------------------
// PTX helpers
// ---------------------------------------------------------------------------
__device__ __forceinline__ float cvt_tf32f(float f) {
    uint32_t u;
    asm("cvt.rna.tf32.f32 %0, %1;" : "=r"(u) : "f"(f));
    return __uint_as_float(u);
}

__device__ __forceinline__ void cp16(void* smem, const void* gmem) {
    uint32_t s = (uint32_t)__cvta_generic_to_shared(smem);
    asm volatile("cp.async.cg.shared.global [%0], [%1], 16;" :: "r"(s), "l"(gmem));
}
__device__ __forceinline__ void cp_commit() {
    asm volatile("cp.async.commit_group;");
}
template <int N>
__device__ __forceinline__ void cp_wait() {
    asm volatile("cp.async.wait_group %0;" :: "n"(N));
}

__device__ __forceinline__ void mma_tf32(float c[4],
                                         uint32_t a0, uint32_t a1, uint32_t a2, uint32_t a3,
                                         uint32_t b0, uint32_t b1) {
    asm volatile(
        "mma.sync.aligned.m16n8k8.row.col.f32.tf32.tf32.f32 "
        "{%0,%1,%2,%3}, {%4,%5,%6,%7}, {%8,%9}, {%0,%1,%2,%3};"
        : "+f"(c[0]), "+f"(c[1]), "+f"(c[2]), "+f"(c[3])
        : "r"(a0), "r"(a1), "r"(a2), "r"(a3), "r"(b0), "r"(b1));
}

__device__ __forceinline__ uint32_t mapa_u32(uint32_t addr, uint32_t rank) {
    uint32_t r;
    asm("mapa.shared::cluster.u32 %0, %1, %2;" : "=r"(r) : "r"(addr), "r"(rank));
    return r;
}
__device__ __forceinline__ float ld_dsmem(uint32_t addr) {
    float v;
    asm volatile("ld.shared::cluster.f32 %0, [%1];" : "=f"(v) : "r"(addr));
    return v;
}
#define CLUSTER_SYNC() do { \
    asm volatile("barrier.cluster.arrive.aligned;" ::: "memory"); \
    asm volatile("barrier.cluster.wait.aligned;" ::: "memory"); } while (0)

// ---------------------------------------------------------------------------
// tf32 pre-convert
// ---------------------------------------------------------------------------
__global__ __launch_bounds__(256)
void cvt_kernel(const float* __restrict__ src, float* __restrict__ dst, int n4)
{
    int i = blockIdx.x * 256 + threadIdx.x;
    if (i < n4) {
        float4 v = ((const float4*)src)[i];
        v.x = cvt_tf32f(v.x); v.y = cvt_tf32f(v.y);
        v.z = cvt_tf32f(v.z); v.w = cvt_tf32f(v.w);
        ((float4*)dst)[i] = v;
    }
}

// ---------------------------------------------------------------------------
// TF32 tensor-core GEMM (NT), pre-converted inputs, 3-stage cp.async.
// ---------------------------------------------------------------------------
#define GEMM_SMEM_BYTES (3 * 2 * 128 * 20 * 4)

template <int ACT>
__global__ __launch_bounds__(256)
void gemm_tf32p(const float* __restrict__ A, const float* __restrict__ W,
                float* __restrict__ C, int M, int N, int K)
{
    extern __shared__ __align__(16) float gsm[];
    float (*As)[128][20] = (float (*)[128][20])gsm;
    float (*Bs)[128][20] = (float (*)[128][20])(gsm + 3 * 128 * 20);

    const int t    = threadIdx.x;
    const int bm   = blockIdx.y * 128;
    const int bn   = blockIdx.x * 128;
    const int w    = t >> 5;
    const int lane = t & 31;
    const int wm   = (w >> 2) * 64;
    const int wn   = (w & 3) * 32;
    const int g    = lane >> 2;
    const int t4   = lane & 3;

    float acc[4][4][4];
#pragma unroll
    for (int mt = 0; mt < 4; mt++)
#pragma unroll
        for (int nt = 0; nt < 4; nt++)
#pragma unroll
            for (int c = 0; c < 4; c++) acc[mt][nt][c] = 0.f;

    const int KT = K >> 4;

    auto load_stage = [&](int kb, int buf) {
        const int k0 = kb * 16;
#pragma unroll
        for (int s = 0; s < 2; s++) {
            int j   = t + s * 256;
            int row = j >> 2;
            int c4  = (j & 3) * 4;
            cp16(&As[buf][row][c4], A + (size_t)(bm + row) * K + k0 + c4);
            cp16(&Bs[buf][row][c4], W + (size_t)(bn + row) * K + k0 + c4);
        }
    };

    load_stage(0, 0); cp_commit();
    load_stage(1, 1); cp_commit();

    for (int kb = 0; kb < KT; kb++) {
        cp_wait<1>();
        __syncthreads();
        if (kb + 2 < KT) { load_stage(kb + 2, (kb + 2) % 3); cp_commit(); }
        else             { cp_commit(); }
        const int buf = kb % 3;

#pragma unroll
        for (int ks = 0; ks < 2; ks++) {
            const int k0 = ks * 8;
            uint32_t bf[4][2];
#pragma unroll
            for (int nt = 0; nt < 4; nt++) {
                bf[nt][0] = __float_as_uint(Bs[buf][wn + nt * 8 + g][k0 + t4]);
                bf[nt][1] = __float_as_uint(Bs[buf][wn + nt * 8 + g][k0 + t4 + 4]);
            }
#pragma unroll
            for (int mt = 0; mt < 4; mt++) {
                uint32_t a0 = __float_as_uint(As[buf][wm + mt * 16 + g][k0 + t4]);
                uint32_t a1 = __float_as_uint(As[buf][wm + mt * 16 + g + 8][k0 + t4]);
                uint32_t a2 = __float_as_uint(As[buf][wm + mt * 16 + g][k0 + t4 + 4]);
                uint32_t a3 = __float_as_uint(As[buf][wm + mt * 16 + g + 8][k0 + t4 + 4]);
#pragma unroll
                for (int nt = 0; nt < 4; nt++)
                    mma_tf32(acc[mt][nt], a0, a1, a2, a3, bf[nt][0], bf[nt][1]);
            }
        }
        __syncthreads();
    }

#pragma unroll
    for (int mt = 0; mt < 4; mt++) {
#pragma unroll
        for (int nt = 0; nt < 4; nt++) {
            int m = bm + wm + mt * 16 + g;
            int n = bn + wn + nt * 8 + t4 * 2;
            float2 v0 = make_float2(acc[mt][nt][0], acc[mt][nt][1]);
            float2 v1 = make_float2(acc[mt][nt][2], acc[mt][nt][3]);
            if (ACT == 1) {
                v0.x = v0.x / (1.f + __expf(-v0.x));
                v0.y = v0.y / (1.f + __expf(-v0.y));
                v1.x = v1.x / (1.f + __expf(-v1.x));
                v1.y = v1.y / (1.f + __expf(-v1.y));
            }
            *(float2*)&C[(size_t)m * N + n]       = v0;
            *(float2*)&C[(size_t)(m + 8) * N + n] = v1;
        }
    }
}

// ---------------------------------------------------------------------------
// lr/wd chunk means
// ---------------------------------------------------------------------------
__global__ __launch_bounds__(256, 2)
void lrwd_kernel(const float* __restrict__ x,
                 const float* __restrict__ Wlr,
                 const float* __restrict__ Wbeta)
{
    __shared__ float xs[64][65];
    __shared__ float ws[64][65];
    __shared__ float red2[64 * 16];

    const int bc = blockIdx.x;
    const size_t xb = (size_t)bc * 64 * 1024;
    const int t  = threadIdx.x;
    const int r0 = t >> 4;
    const int c0 = t & 15;

    float acc[4][4];
#pragma unroll
    for (int i = 0; i < 4; i++)
#pragma unroll
        for (int j = 0; j < 4; j++) acc[i][j] = 0.f;

    for (int k0 = 0; k0 < 1024; k0 += 64) {
        for (int i = t; i < 4096; i += 256) {
            int n = i >> 6, d = i & 63;
            xs[n][d] = x[xb + (size_t)n * 1024 + k0 + d];
            ws[n][d] = (n < 32) ? Wlr[n * 1024 + k0 + d]
                                : Wbeta[(n - 32) * 1024 + k0 + d];
        }
        __syncthreads();
#pragma unroll 4
        for (int k = 0; k < 64; k++) {
            float a[4], b[4];
#pragma unroll
            for (int ii = 0; ii < 4; ii++) a[ii] = xs[r0 + 16 * ii][k];
#pragma unroll
            for (int jj = 0; jj < 4; jj++) b[jj] = ws[c0 + 16 * jj][k];
#pragma unroll
            for (int ii = 0; ii < 4; ii++)
#pragma unroll
                for (int jj = 0; jj < 4; jj++) acc[ii][jj] += a[ii] * b[jj];
        }
        __syncthreads();
    }

#pragma unroll
    for (int jj = 0; jj < 4; jj++) {
        int j = c0 + 16 * jj;
        float scale = (j < 32) ? 0.001f : 0.9f;
        float p = 0.f;
#pragma unroll
        for (int ii = 0; ii < 4; ii++)
            p += scale / (1.f + __expf(-acc[ii][jj]));
        red2[j * 16 + r0] = p;
    }
    __syncthreads();
    if (t < 64) {
        float s = 0.f;
        for (int r = 0; r < 16; r++) s += red2[t * 16 + r];
        g_lrwd[bc * 64 + t] = s * (1.f / 64.f);
    }
}

// ---------------------------------------------------------------------------
// Cluster-2 persistent scan, 256 threads (round-7 layout: LDS-traffic
// optimal), tf32 fused into the o-store, P6 merged into P7.
// ---------------------------------------------------------------------------
#define P64 65
#define P32 33

#define OFF_WI   0                           // [32][65]
#define OFF_WO   (32 * P64)
#define OFF_Q    (2 * 32 * P64)              // [64][65]
#define OFF_K    (OFF_Q + 64 * P64)
#define OFF_V    (OFF_K + 64 * P64)
#define OFF_PQ   (OFF_V + 64 * P64)          // [64][33]
#define OFF_PK   (OFF_PQ + 64 * P32)
#define OFF_AM   (OFF_PK + 64 * P32)
#define OFF_OP   (OFF_AM + 64 * P32)         // [64][65]
#define OFF_SP   (OFF_OP + 64 * P64)
#define OFF_SS   (OFF_SP + 64)
#define OFF_RED  (OFF_SS + 64)               // [4][64]
#define OFF_CS   (OFF_RED + 256)
#define SCAN_SMEM_FLOATS (OFF_CS + 64)       // 27584 floats -> 110336 bytes

__global__ __launch_bounds__(256, 1) __cluster_dims__(2, 1, 1)
void scan_kernel(const float* __restrict__ Win0, const float* __restrict__ Wout0)
{
    extern __shared__ float sm[];
    float* Wi  = sm + OFF_WI;
    float* Wo_ = sm + OFF_WO;
    float* Q   = sm + OFF_Q;
    float* Kt  = sm + OFF_K;
    float* V   = sm + OFF_V;
    float* Pq  = sm + OFF_PQ;
    float* Pk  = sm + OFF_PK;
    float* Am  = sm + OFF_AM;
    float* op  = sm + OFF_OP;
    float* sp  = sm + OFF_SP;
    float* ss  = sm + OFF_SS;
    float* red = sm + OFF_RED;
    float* cs  = sm + OFF_CS;

    const int pair = blockIdx.x >> 1;
    const uint32_t rank = blockIdx.x & 1;
    const int b = pair >> 4;
    const int h = pair & 15;
    const int t = threadIdx.x;

    const int r8  = t >> 3, c8  = t & 7;    // 32x8 grid (logits, a)
    const int r16 = t >> 4, c16 = t & 15;   // 16x16 grid (o)
    const int rg  = t >> 5, cg  = t & 31;   // 8x32 grid (grads)
    const int task = t & 63, sg = t >> 6;   // softmax

    const uint32_t op_peer = mapa_u32((uint32_t)__cvta_generic_to_shared(op), rank ^ 1u);
    const uint32_t sp_peer = mapa_u32((uint32_t)__cvta_generic_to_shared(sp), rank ^ 1u);

    // init state halves
    for (int i = t; i < 2048; i += 256) {
        int Dl = i >> 6, d = i & 63;
        int Dg = (int)rank * 32 + Dl;
        Wi [Dl * P64 + d] = Win0 [Dg * 1024 + h * 64 + d];
        Wo_[Dl * P64 + d] = Wout0[Dg * 1024 + h * 64 + d];
    }
    __syncthreads();

    for (int c = 0; c < NCHUNK_; c++) {
        const size_t base = ((size_t)b * L_ + (size_t)c * 64) * 1024 + h * 64;
        const int lb = (b * 64 + c) * 64;
        const float li  = g_lrwd[lb + h];
        const float lo  = g_lrwd[lb + 16 + h];
        const float wdi = g_lrwd[lb + 32 + h];
        const float wdo = g_lrwd[lb + 48 + h];

        // ---- P1: load q,k,v tiles (float4 LDG)
        for (int i = t; i < 1024; i += 256) {
            int n = i >> 4, d4 = (i & 15) * 4;
            size_t gidx = base + (size_t)n * 1024 + d4;
            float4 a = *(const float4*)&g_q[gidx];
            float4 e = *(const float4*)&g_k[gidx];
            float4 f = *(const float4*)&g_v[gidx];
            Q [n * P64 + d4] = a.x; Q [n * P64 + d4 + 1] = a.y; Q [n * P64 + d4 + 2] = a.z; Q [n * P64 + d4 + 3] = a.w;
            Kt[n * P64 + d4] = e.x; Kt[n * P64 + d4 + 1] = e.y; Kt[n * P64 + d4 + 2] = e.z; Kt[n * P64 + d4 + 3] = e.w;
            V [n * P64 + d4] = f.x; V [n * P64 + d4 + 1] = f.y; V [n * P64 + d4 + 2] = f.z; V [n * P64 + d4 + 3] = f.w;
        }
        __syncthreads();

        // ---- P2: fused q/k logits vs Wi (M=128, N=32, K=64)
        {
            float aq[2][4], ak[2][4];
#pragma unroll
            for (int i = 0; i < 2; i++)
#pragma unroll
                for (int j = 0; j < 4; j++) { aq[i][j] = 0.f; ak[i][j] = 0.f; }
#pragma unroll 4
            for (int k = 0; k < 64; k++) {
                float q0 = Q [r8 * P64 + k],        q1 = Q [(r8 + 32) * P64 + k];
                float k0 = Kt[r8 * P64 + k],        k1 = Kt[(r8 + 32) * P64 + k];
                float bw[4];
#pragma unroll
                for (int j = 0; j < 4; j++) bw[j] = Wi[(c8 + 8 * j) * P64 + k];
#pragma unroll
                for (int j = 0; j < 4; j++) {
                    aq[0][j] += q0 * bw[j];
                    aq[1][j] += q1 * bw[j];
                    ak[0][j] += k0 * bw[j];
                    ak[1][j] += k1 * bw[j];
                }
            }
#pragma unroll
            for (int j = 0; j < 4; j++) {
                Pq[r8 * P32 + c8 + 8 * j]        = aq[0][j];
                Pq[(r8 + 32) * P32 + c8 + 8 * j] = aq[1][j];
                Pk[r8 * P32 + c8 + 8 * j]        = ak[0][j];
                Pk[(r8 + 32) * P32 + c8 + 8 * j] = ak[1][j];
            }
        }
        __syncthreads();

        // ---- P3: merged softmax over n for both Pq and Pk (per column D)
        {
            float* Pp = (task < 32) ? Pq : Pk;
            const int D = task & 31;
            float m = -1e30f;
#pragma unroll
            for (int n = sg * 16; n < sg * 16 + 16; n++) m = fmaxf(m, Pp[n * P32 + D]);
            red[sg * 64 + task] = m;
            __syncthreads();
            if (t < 64)
                cs[t] = fmaxf(fmaxf(red[t], red[64 + t]), fmaxf(red[128 + t], red[192 + t]));
            __syncthreads();
            float mm = cs[task], s = 0.f;
#pragma unroll
            for (int n = sg * 16; n < sg * 16 + 16; n++) {
                float e = __expf(Pp[n * P32 + D] - mm);
                Pp[n * P32 + D] = e;
                s += e;
            }
            red[sg * 64 + task] = s;
            __syncthreads();
            if (t < 64) cs[t] = 1.f / (red[t] + red[64 + t] + red[128 + t] + red[192 + t]);
            __syncthreads();
            float inv = cs[task];
#pragma unroll
            for (int n = sg * 16; n < sg * 16 + 16; n++) Pp[n * P32 + D] *= inv;
        }
        __syncthreads();

        // ---- P4: op (partial o) and a, one phase
        {
            float acc[4][4];
#pragma unroll
            for (int i = 0; i < 4; i++)
#pragma unroll
                for (int j = 0; j < 4; j++) acc[i][j] = 0.f;
#pragma unroll 4
            for (int k = 0; k < 32; k++) {
                float a[4], bb[4];
#pragma unroll
                for (int i = 0; i < 4; i++) a[i]  = Pq[(r16 + 16 * i) * P32 + k];
#pragma unroll
                for (int j = 0; j < 4; j++) bb[j] = Wo_[k * P64 + c16 + 16 * j];
#pragma unroll
                for (int i = 0; i < 4; i++)
#pragma unroll
                    for (int j = 0; j < 4; j++) acc[i][j] += a[i] * bb[j];
            }
#pragma unroll
            for (int i = 0; i < 4; i++)
#pragma unroll
                for (int j = 0; j < 4; j++)
                    op[(r16 + 16 * i) * P64 + c16 + 16 * j] = acc[i][j];

            float av[2][4];
#pragma unroll
            for (int i = 0; i < 2; i++)
#pragma unroll
                for (int j = 0; j < 4; j++) av[i][j] = 0.f;
#pragma unroll 4
            for (int k = 0; k < 64; k++) {
                float v0 = V[r8 * P64 + k], v1 = V[(r8 + 32) * P64 + k];
                float bw[4];
#pragma unroll
                for (int j = 0; j < 4; j++) bw[j] = Wo_[(c8 + 8 * j) * P64 + k];
#pragma unroll
                for (int j = 0; j < 4; j++) {
                    av[0][j] += v0 * bw[j];
                    av[1][j] += v1 * bw[j];
                }
            }
#pragma unroll
            for (int j = 0; j < 4; j++) {
                Am[r8 * P32 + c8 + 8 * j]        = av[0][j];
                Am[(r8 + 32) * P32 + c8 + 8 * j] = av[1][j];
            }
        }
        __syncthreads();
        CLUSTER_SYNC();

        // ---- P5: o = op_self + op_peer (tf32 fused into store); sp
        for (int i = t; i < 2048; i += 256) {
            int n = (int)rank * 32 + (i >> 6), d = i & 63;
            float v2 = op[n * P64 + d] + ld_dsmem(op_peer + (uint32_t)(n * P64 + d) * 4u);
            g_o[base + (size_t)n * 1024 + d] = cvt_tf32f(v2);
        }
        if (t < 64) {
            float s = 0.f;
#pragma unroll 8
            for (int Dl = 0; Dl < 32; Dl++) s += Pk[t * P32 + Dl] * Am[t * P32 + Dl];
            sp[t] = s;
        }
        __syncthreads();
        CLUSTER_SYNC();

        // ---- P6+P7: total s, then grads (g_z inline) + state update
        if (t < 64) ss[t] = sp[t] + ld_dsmem(sp_peer + (uint32_t)t * 4u);
        __syncthreads();
        {
            float gin[4][2], gout[4][2];
#pragma unroll
            for (int i = 0; i < 4; i++) { gin[i][0] = gin[i][1] = 0.f; gout[i][0] = gout[i][1] = 0.f; }
#pragma unroll 4
            for (int n = 0; n < 64; n++) {
                float ssn = ss[n];
                float pk[4], am[4];
#pragma unroll
                for (int i = 0; i < 4; i++) {
                    pk[i] = Pk[n * P32 + rg + 8 * i];
                    am[i] = Am[n * P32 + rg + 8 * i];
                }
                float kk0 = Kt[n * P64 + cg], kk1 = Kt[n * P64 + cg + 32];
                float vv0 = V [n * P64 + cg], vv1 = V [n * P64 + cg + 32];
#pragma unroll
                for (int i = 0; i < 4; i++) {
                    float gz = -pk[i] * (am[i] - ssn);
                    gin[i][0]  += gz * kk0;
                    gin[i][1]  += gz * kk1;
                    gout[i][0] += pk[i] * vv0;
                    gout[i][1] += pk[i] * vv1;
                }
            }
#pragma unroll
            for (int i = 0; i < 4; i++) {
#pragma unroll
                for (int j = 0; j < 2; j++) {
                    int idx = (rg + 8 * i) * P64 + cg + 32 * j;
                    Wi [idx] = wdi * Wi [idx] - li * gin[i][j];
                    Wo_[idx] = wdo * Wo_[idx] + lo * gout[i][j];
                }
            }
        }
        __syncthreads();
    }
    CLUSTER_SYNC();   // keep smem alive for peer's in-flight DSMEM reads
}

// ---------------------------------------------------------------------------
// Launch
// ---------------------------------------------------------------------------
extern "C" void kernel_launch(void* const* d_in, const int* in_sizes, int n_in,
                              void* d_out, int out_size)
{
    (void)in_sizes; (void)n_in; (void)out_size;
    const float* x     = (const float*)d_in[0];
    const float* Wq    = (const float*)d_in[1];
    const float* Wk    = (const float*)d_in[2];
    const float* Wv    = (const float*)d_in[3];
    const float* Wlr   = (const float*)d_in[4];
    const float* Wbeta = (const float*)d_in[5];
    const float* Wo    = (const float*)d_in[6];
    const float* Win0  = (const float*)d_in[7];
    const float* Wout0 = (const float*)d_in[8];
    float* out = (float*)d_out;

    float *q, *k, *v, *om, *xt, *wt;
    cudaGetSymbolAddress((void**)&q,  g_q);
    cudaGetSymbolAddress((void**)&k,  g_k);
    cudaGetSymbolAddress((void**)&v,  g_v);
    cudaGetSymbolAddress((void**)&om, g_o);
    cudaGetSymbolAddress((void**)&xt, g_xt);
    cudaGetSymbolAddress((void**)&wt, g_wt);

    cudaFuncSetAttribute(gemm_tf32p<0>, cudaFuncAttributeMaxDynamicSharedMemorySize, GEMM_SMEM_BYTES);
    cudaFuncSetAttribute(gemm_tf32p<1>, cudaFuncAttributeMaxDynamicSharedMemorySize, GEMM_SMEM_BYTES);
    cudaFuncSetAttribute(scan_kernel,   cudaFuncAttributeMaxDynamicSharedMemorySize,
                         SCAN_SMEM_FLOATS * (int)sizeof(float));

    const int NX4 = (M_ * 1024) / 4;
    const int NW4 = (1024 * 1024) / 4;
    cvt_kernel<<<(NX4 + 255) / 256, 256>>>(x,  xt,            NX4);
    cvt_kernel<<<(NW4 + 255) / 256, 256>>>(Wq, wt + 0u * 1024u * 1024u, NW4);
    cvt_kernel<<<(NW4 + 255) / 256, 256>>>(Wk, wt + 1u * 1024u * 1024u, NW4);
    cvt_kernel<<<(NW4 + 255) / 256, 256>>>(Wv, wt + 2u * 1024u * 1024u, NW4);
    cvt_kernel<<<(NW4 + 255) / 256, 256>>>(Wo, wt + 3u * 1024u * 1024u, NW4);

    dim3 grid(1024 / 128, M_ / 128);
    gemm_tf32p<1><<<grid, 256, GEMM_SMEM_BYTES>>>(xt, wt + 0u * 1024u * 1024u, q, M_, 1024, 1024);
    gemm_tf32p<1><<<grid, 256, GEMM_SMEM_BYTES>>>(xt, wt + 1u * 1024u * 1024u, k, M_, 1024, 1024);
    gemm_tf32p<0><<<grid, 256, GEMM_SMEM_BYTES>>>(xt, wt + 2u * 1024u * 1024u, v, M_, 1024, 1024);
    lrwd_kernel<<<B_ * NCHUNK_, 256>>>(x, Wlr, Wbeta);

    const int smem_bytes = SCAN_SMEM_FLOATS * (int)sizeof(float);
    scan_kernel<<<128, 256, smem_bytes>>>(Win0, Wout0);

    // g_o already holds tf32 bits — final GEMM reads it directly
    gemm_tf32p<0><<<grid, 256, GEMM_SMEM_BYTES>>>(om, wt + 3u * 1024u * 1024u, out, M_, 1024, 1024);
}

// round 11
// speedup vs baseline: 1.2786x; 1.2077x over previous
#include <cuda_runtime.h>
#include <cstdint>

// Problem constants
#define B_ 4
#define L_ 4096
#define DIM_ 1024
#define H_ 16
#define NCHUNK_ 64
#define CHUNK_ 64
#define M_ (B_ * L_)          // 16384

// ---------------------------------------------------------------------------
// Device scratch (allocation-free contract: __device__ globals)
// ---------------------------------------------------------------------------
__device__ float g_q[(size_t)B_ * L_ * 1024];
__device__ float g_k[(size_t)B_ * L_ * 1024];
__device__ float g_v[(size_t)B_ * L_ * 1024];
__device__ float g_o[(size_t)B_ * L_ * 1024];   // scan writes tf32 bits directly
__device__ float g_xt[(size_t)B_ * L_ * 1024];  // tf32(x)
__device__ float g_wt[4u * 1024u * 1024u];      // tf32(Wq,Wk,Wv,Wo)
__device__ float g_lrwd[B_ * NCHUNK_ * 64];

// ---------------------------------------------------------------------------
// PTX helpers
// ---------------------------------------------------------------------------
__device__ __forceinline__ float cvt_tf32f(float f) {
    uint32_t u;
    asm("cvt.rna.tf32.f32 %0, %1;" : "=r"(u) : "f"(f));
    return __uint_as_float(u);
}
__device__ __forceinline__ uint32_t f2t(float f) {
    uint32_t u;
    asm("cvt.rna.tf32.f32 %0, %1;" : "=r"(u) : "f"(f));
    return u;
}

__device__ __forceinline__ void cp16(void* smem, const void* gmem) {
    uint32_t s = (uint32_t)__cvta_generic_to_shared(smem);
    asm volatile("cp.async.cg.shared.global [%0], [%1], 16;" :: "r"(s), "l"(gmem));
}
__device__ __forceinline__ void cp_commit() {
    asm volatile("cp.async.commit_group;");
}
template <int N>
__device__ __forceinline__ void cp_wait() {
    asm volatile("cp.async.wait_group %0;" :: "n"(N));
}

__device__ __forceinline__ void mma_tf32(float c[4],
                                         uint32_t a0, uint32_t a1, uint32_t a2, uint32_t a3,
                                         uint32_t b0, uint32_t b1) {
    asm volatile(
        "mma.sync.aligned.m16n8k8.row.col.f32.tf32.tf32.f32 "
        "{%0,%1,%2,%3}, {%4,%5,%6,%7}, {%8,%9}, {%0,%1,%2,%3};"
        : "+f"(c[0]), "+f"(c[1]), "+f"(c[2]), "+f"(c[3])
        : "r"(a0), "r"(a1), "r"(a2), "r"(a3), "r"(b0), "r"(b1));
}

__device__ __forceinline__ uint32_t mapa_u32(uint32_t addr, uint32_t rank) {
    uint32_t r;
    asm("mapa.shared::cluster.u32 %0, %1, %2;" : "=r"(r) : "r"(addr), "r"(rank));
    return r;
}
__device__ __forceinline__ float ld_dsmem(uint32_t addr) {
    float v;
    asm volatile("ld.shared::cluster.f32 %0, [%1];" : "=f"(v) : "r"(addr));
    return v;
}
#define CLUSTER_SYNC() do { \
    asm volatile("barrier.cluster.arrive.aligned;" ::: "memory"); \
    asm volatile("barrier.cluster.wait.aligned;" ::: "memory"); } while (0)

// ---------------------------------------------------------------------------
// tf32 pre-convert
// ---------------------------------------------------------------------------
__global__ __launch_bounds__(256)
void cvt_kernel(const float* __restrict__ src, float* __restrict__ dst, int n4)
{
    int i = blockIdx.x * 256 + threadIdx.x;
    if (i < n4) {
        float4 v = ((const float4*)src)[i];
        v.x = cvt_tf32f(v.x); v.y = cvt_tf32f(v.y);
        v.z = cvt_tf32f(v.z); v.w = cvt_tf32f(v.w);
        ((float4*)dst)[i] = v;
    }
}

// ---------------------------------------------------------------------------
// TF32 tensor-core GEMM (NT), pre-converted inputs, 3-stage cp.async.
// ---------------------------------------------------------------------------
#define GEMM_SMEM_BYTES (3 * 2 * 128 * 20 * 4)

template <int ACT>
__global__ __launch_bounds__(256)
void gemm_tf32p(const float* __restrict__ A, const float* __restrict__ W,
                float* __restrict__ C, int M, int N, int K)
{
    extern __shared__ __align__(16) float gsm[];
    float (*As)[128][20] = (float (*)[128][20])gsm;
    float (*Bs)[128][20] = (float (*)[128][20])(gsm + 3 * 128 * 20);

    const int t    = threadIdx.x;
    const int bm   = blockIdx.y * 128;
    const int bn   = blockIdx.x * 128;
    const int w    = t >> 5;
    const int lane = t & 31;
    const int wm   = (w >> 2) * 64;
    const int wn   = (w & 3) * 32;
    const int g    = lane >> 2;
    const int t4   = lane & 3;

    float acc[4][4][4];
#pragma unroll
    for (int mt = 0; mt < 4; mt++)
#pragma unroll
        for (int nt = 0; nt < 4; nt++)
#pragma unroll
            for (int c = 0; c < 4; c++) acc[mt][nt][c] = 0.f;

    const int KT = K >> 4;

    auto load_stage = [&](int kb, int buf) {
        const int k0 = kb * 16;
#pragma unroll
        for (int s = 0; s < 2; s++) {
            int j   = t + s * 256;
            int row = j >> 2;
            int c4  = (j & 3) * 4;
            cp16(&As[buf][row][c4], A + (size_t)(bm + row) * K + k0 + c4);
            cp16(&Bs[buf][row][c4], W + (size_t)(bn + row) * K + k0 + c4);
        }
    };

    load_stage(0, 0); cp_commit();
    load_stage(1, 1); cp_commit();

    for (int kb = 0; kb < KT; kb++) {
        cp_wait<1>();
        __syncthreads();
        if (kb + 2 < KT) { load_stage(kb + 2, (kb + 2) % 3); cp_commit(); }
        else             { cp_commit(); }
        const int buf = kb % 3;

#pragma unroll
        for (int ks = 0; ks < 2; ks++) {
            const int k0 = ks * 8;
            uint32_t bf[4][2];
#pragma unroll
            for (int nt = 0; nt < 4; nt++) {
                bf[nt][0] = __float_as_uint(Bs[buf][wn + nt * 8 + g][k0 + t4]);
                bf[nt][1] = __float_as_uint(Bs[buf][wn + nt * 8 + g][k0 + t4 + 4]);
            }
#pragma unroll
            for (int mt = 0; mt < 4; mt++) {
                uint32_t a0 = __float_as_uint(As[buf][wm + mt * 16 + g][k0 + t4]);
                uint32_t a1 = __float_as_uint(As[buf][wm + mt * 16 + g + 8][k0 + t4]);
                uint32_t a2 = __float_as_uint(As[buf][wm + mt * 16 + g][k0 + t4 + 4]);
                uint32_t a3 = __float_as_uint(As[buf][wm + mt * 16 + g + 8][k0 + t4 + 4]);
#pragma unroll
                for (int nt = 0; nt < 4; nt++)
                    mma_tf32(acc[mt][nt], a0, a1, a2, a3, bf[nt][0], bf[nt][1]);
            }
        }
        __syncthreads();
    }

#pragma unroll
    for (int mt = 0; mt < 4; mt++) {
#pragma unroll
        for (int nt = 0; nt < 4; nt++) {
            int m = bm + wm + mt * 16 + g;
            int n = bn + wn + nt * 8 + t4 * 2;
            float2 v0 = make_float2(acc[mt][nt][0], acc[mt][nt][1]);
            float2 v1 = make_float2(acc[mt][nt][2], acc[mt][nt][3]);
            if (ACT == 1) {
                v0.x = v0.x / (1.f + __expf(-v0.x));
                v0.y = v0.y / (1.f + __expf(-v0.y));
                v1.x = v1.x / (1.f + __expf(-v1.x));
                v1.y = v1.y / (1.f + __expf(-v1.y));
            }
            *(float2*)&C[(size_t)m * N + n]       = v0;
            *(float2*)&C[(size_t)(m + 8) * N + n] = v1;
        }
    }
}

// ---------------------------------------------------------------------------
// lr/wd chunk means
// ---------------------------------------------------------------------------
__global__ __launch_bounds__(256, 2)
void lrwd_kernel(const float* __restrict__ x,
                 const float* __restrict__ Wlr,
                 const float* __restrict__ Wbeta)
{
    __shared__ float xs[64][65];
    __shared__ float ws[64][65];
    __shared__ float red2[64 * 16];

    const int bc = blockIdx.x;
    const size_t xb = (size_t)bc * 64 * 1024;
    const int t  = threadIdx.x;
    const int r0 = t >> 4;
    const int c0 = t & 15;

    float acc[4][4];
#pragma unroll
    for (int i = 0; i < 4; i++)
#pragma unroll
        for (int j = 0; j < 4; j++) acc[i][j] = 0.f;

    for (int k0 = 0; k0 < 1024; k0 += 64) {
        for (int i = t; i < 4096; i += 256) {
            int n = i >> 6, d = i & 63;
            xs[n][d] = x[xb + (size_t)n * 1024 + k0 + d];
            ws[n][d] = (n < 32) ? Wlr[n * 1024 + k0 + d]
                                : Wbeta[(n - 32) * 1024 + k0 + d];
        }
        __syncthreads();
#pragma unroll 4
        for (int k = 0; k < 64; k++) {
            float a[4], b[4];
#pragma unroll
            for (int ii = 0; ii < 4; ii++) a[ii] = xs[r0 + 16 * ii][k];
#pragma unroll
            for (int jj = 0; jj < 4; jj++) b[jj] = ws[c0 + 16 * jj][k];
#pragma unroll
            for (int ii = 0; ii < 4; ii++)
#pragma unroll
                for (int jj = 0; jj < 4; jj++) acc[ii][jj] += a[ii] * b[jj];
        }
        __syncthreads();
    }

#pragma unroll
    for (int jj = 0; jj < 4; jj++) {
        int j = c0 + 16 * jj;
        float scale = (j < 32) ? 0.001f : 0.9f;
        float p = 0.f;
#pragma unroll
        for (int ii = 0; ii < 4; ii++)
            p += scale / (1.f + __expf(-acc[ii][jj]));
        red2[j * 16 + r0] = p;
    }
    __syncthreads();
    if (t < 64) {
        float s = 0.f;
        for (int r = 0; r < 16; r++) s += red2[t * 16 + r];
        g_lrwd[bc * 64 + t] = s * (1.f / 64.f);
    }
}

// ---------------------------------------------------------------------------
// Cluster-2 persistent scan with mma.sync gemmlets (P2, P4b, P7).
// Pitches 68/36 (== 4 mod 32): fragment loads conflict-free.
// op (output path) stays fp32 FFMA for precision.
// ---------------------------------------------------------------------------
#define P64 68
#define P32 36

#define OFF_WI   0                           // [32][68]
#define OFF_WO   (32 * P64)                  // 2176
#define OFF_Q    (2 * 32 * P64)              // 4352  [64][68]
#define OFF_K    (OFF_Q + 64 * P64)          // 8704
#define OFF_V    (OFF_K + 64 * P64)          // 13056
#define OFF_PQ   (OFF_V + 64 * P64)          // 17408 [64][36]
#define OFF_PK   (OFF_PQ + 64 * P32)         // 19712
#define OFF_AM   (OFF_PK + 64 * P32)         // 22016
#define OFF_OP   (OFF_AM + 64 * P32)         // 24320 [64][68]
#define OFF_SP   (OFF_OP + 64 * P64)         // 28672
#define OFF_SS   (OFF_SP + 64)               // 28736
#define OFF_RED  (OFF_SS + 64)               // 28800 [4][64]
#define OFF_CS   (OFF_RED + 256)             // 29056
#define SCAN_SMEM_FLOATS (OFF_CS + 64)       // 29120 -> 116480 bytes

__global__ __launch_bounds__(256, 1) __cluster_dims__(2, 1, 1)
void scan_kernel(const float* __restrict__ Win0, const float* __restrict__ Wout0)
{
    extern __shared__ float sm[];
    float* Wi  = sm + OFF_WI;
    float* Wo_ = sm + OFF_WO;
    float* Q   = sm + OFF_Q;
    float* Kt  = sm + OFF_K;
    float* V   = sm + OFF_V;
    float* Pq  = sm + OFF_PQ;
    float* Pk  = sm + OFF_PK;
    float* Am  = sm + OFF_AM;
    float* op  = sm + OFF_OP;
    float* sp  = sm + OFF_SP;
    float* ss  = sm + OFF_SS;
    float* red = sm + OFF_RED;
    float* cs  = sm + OFF_CS;

    const int pair = blockIdx.x >> 1;
    const uint32_t rank = blockIdx.x & 1;
    const int b = pair >> 4;
    const int h = pair & 15;
    const int t = threadIdx.x;

    const int w    = t >> 5;
    const int lane = t & 31;
    const int g    = lane >> 2;     // 0..7
    const int t4   = lane & 3;      // 0..3
    const int r16  = t >> 4, c16 = t & 15;   // 16x16 grid (op FFMA)
    const int task = t & 63, sg = t >> 6;    // softmax

    const uint32_t op_peer = mapa_u32((uint32_t)__cvta_generic_to_shared(op), rank ^ 1u);
    const uint32_t sp_peer = mapa_u32((uint32_t)__cvta_generic_to_shared(sp), rank ^ 1u);

    // init state halves (pitch 68)
    for (int i = t; i < 2048; i += 256) {
        int Dl = i >> 6, d = i & 63;
        int Dg = (int)rank * 32 + Dl;
        Wi [Dl * P64 + d] = Win0 [Dg * 1024 + h * 64 + d];
        Wo_[Dl * P64 + d] = Wout0[Dg * 1024 + h * 64 + d];
    }
    __syncthreads();

    for (int c = 0; c < NCHUNK_; c++) {
        const size_t base = ((size_t)b * L_ + (size_t)c * 64) * 1024 + h * 64;
        const int lb = (b * 64 + c) * 64;
        const float li  = g_lrwd[lb + h];
        const float lo  = g_lrwd[lb + 16 + h];
        const float wdi = g_lrwd[lb + 32 + h];
        const float wdo = g_lrwd[lb + 48 + h];

        // ---- P1: load q,k,v tiles (float4 LDG -> float4 STS, pitch 68)
        for (int i = t; i < 1024; i += 256) {
            int n = i >> 4, d4 = (i & 15) * 4;
            size_t gidx = base + (size_t)n * 1024 + d4;
            *(float4*)&Q [n * P64 + d4] = *(const float4*)&g_q[gidx];
            *(float4*)&Kt[n * P64 + d4] = *(const float4*)&g_k[gidx];
            *(float4*)&V [n * P64 + d4] = *(const float4*)&g_v[gidx];
        }
        __syncthreads();

        // ---- P2 (mma): logits. warps 0-3: Pq = Q@Wi^T, warps 4-7: Pk = K@Wi^T
        {
            const float* src = (w < 4) ? Q  : Kt;
            float*       dst = (w < 4) ? Pq : Pk;
            const int m0 = 16 * (w & 3);
            float C_[4][4];
#pragma unroll
            for (int j = 0; j < 4; j++)
#pragma unroll
                for (int x2 = 0; x2 < 4; x2++) C_[j][x2] = 0.f;
#pragma unroll
            for (int kk = 0; kk < 8; kk++) {
                const int k0 = kk * 8;
                uint32_t a0 = f2t(src[(m0 + g)     * P64 + k0 + t4]);
                uint32_t a1 = f2t(src[(m0 + g + 8) * P64 + k0 + t4]);
                uint32_t a2 = f2t(src[(m0 + g)     * P64 + k0 + t4 + 4]);
                uint32_t a3 = f2t(src[(m0 + g + 8) * P64 + k0 + t4 + 4]);
#pragma unroll
                for (int j = 0; j < 4; j++) {
                    uint32_t b0 = f2t(Wi[(8 * j + g) * P64 + k0 + t4]);
                    uint32_t b1 = f2t(Wi[(8 * j + g) * P64 + k0 + t4 + 4]);
                    mma_tf32(C_[j], a0, a1, a2, a3, b0, b1);
                }
            }
#pragma unroll
            for (int j = 0; j < 4; j++) {
                dst[(m0 + g)     * P32 + 8 * j + 2 * t4]     = C_[j][0];
                dst[(m0 + g)     * P32 + 8 * j + 2 * t4 + 1] = C_[j][1];
                dst[(m0 + g + 8) * P32 + 8 * j + 2 * t4]     = C_[j][2];
                dst[(m0 + g + 8) * P32 + 8 * j + 2 * t4 + 1] = C_[j][3];
            }
        }
        __syncthreads();

        // ---- P3: merged softmax over n for both Pq and Pk (per column D)
        {
            float* Pp = (task < 32) ? Pq : Pk;
            const int D = task & 31;
            float m = -1e30f;
#pragma unroll
            for (int n = sg * 16; n < sg * 16 + 16; n++) m = fmaxf(m, Pp[n * P32 + D]);
            red[sg * 64 + task] = m;
            __syncthreads();
            if (t < 64)
                cs[t] = fmaxf(fmaxf(red[t], red[64 + t]), fmaxf(red[128 + t], red[192 + t]));
            __syncthreads();
            float mm = cs[task], s = 0.f;
#pragma unroll
            for (int n = sg * 16; n < sg * 16 + 16; n++) {
                float e = __expf(Pp[n * P32 + D] - mm);
                Pp[n * P32 + D] = e;
                s += e;
            }
            red[sg * 64 + task] = s;
            __syncthreads();
            if (t < 64) cs[t] = 1.f / (red[t] + red[64 + t] + red[128 + t] + red[192 + t]);
            __syncthreads();
            float inv = cs[task];
#pragma unroll
            for (int n = sg * 16; n < sg * 16 + 16; n++) Pp[n * P32 + D] *= inv;
        }
        __syncthreads();

        // ---- P4a (FFMA, fp32 — output path): op[n][d] = sum_Dl Pq[n][Dl]*Wo_[Dl][d]
        {
            float acc[4][4];
#pragma unroll
            for (int i = 0; i < 4; i++)
#pragma unroll
                for (int j = 0; j < 4; j++) acc[i][j] = 0.f;
#pragma unroll 4
            for (int k = 0; k < 32; k++) {
                float a[4], bb[4];
#pragma unroll
                for (int i = 0; i < 4; i++) a[i]  = Pq[(r16 + 16 * i) * P32 + k];
#pragma unroll
                for (int j = 0; j < 4; j++) bb[j] = Wo_[k * P64 + c16 + 16 * j];
#pragma unroll
                for (int i = 0; i < 4; i++)
#pragma unroll
                    for (int j = 0; j < 4; j++) acc[i][j] += a[i] * bb[j];
            }
#pragma unroll
            for (int i = 0; i < 4; i++)
#pragma unroll
                for (int j = 0; j < 4; j++)
                    op[(r16 + 16 * i) * P64 + c16 + 16 * j] = acc[i][j];
        }

        // ---- P4b (mma): Am[n][Dl] = sum_d V[n][d]*Wo_[Dl][d]
        {
            const int m0 = 16 * (w & 3);
            const int nb = (w >> 2) * 16;
            float Ca[2][4];
#pragma unroll
            for (int j = 0; j < 2; j++)
#pragma unroll
                for (int x2 = 0; x2 < 4; x2++) Ca[j][x2] = 0.f;
#pragma unroll
            for (int kk = 0; kk < 8; kk++) {
                const int k0 = kk * 8;
                uint32_t a0 = f2t(V[(m0 + g)     * P64 + k0 + t4]);
                uint32_t a1 = f2t(V[(m0 + g + 8) * P64 + k0 + t4]);
                uint32_t a2 = f2t(V[(m0 + g)     * P64 + k0 + t4 + 4]);
                uint32_t a3 = f2t(V[(m0 + g + 8) * P64 + k0 + t4 + 4]);
#pragma unroll
                for (int j = 0; j < 2; j++) {
                    const int Dl = nb + 8 * j + g;
                    uint32_t b0 = f2t(Wo_[Dl * P64 + k0 + t4]);
                    uint32_t b1 = f2t(Wo_[Dl * P64 + k0 + t4 + 4]);
                    mma_tf32(Ca[j], a0, a1, a2, a3, b0, b1);
                }
            }
#pragma unroll
            for (int j = 0; j < 2; j++) {
                Am[(m0 + g)     * P32 + nb + 8 * j + 2 * t4]     = Ca[j][0];
                Am[(m0 + g)     * P32 + nb + 8 * j + 2 * t4 + 1] = Ca[j][1];
                Am[(m0 + g + 8) * P32 + nb + 8 * j + 2 * t4]     = Ca[j][2];
                Am[(m0 + g + 8) * P32 + nb + 8 * j + 2 * t4 + 1] = Ca[j][3];
            }
        }
        __syncthreads();
        CLUSTER_SYNC();

        // ---- P5: o = op_self + op_peer (tf32 fused into store); sp
        for (int i = t; i < 2048; i += 256) {
            int n = (int)rank * 32 + (i >> 6), d = i & 63;
            float v2 = op[n * P64 + d] + ld_dsmem(op_peer + (uint32_t)(n * P64 + d) * 4u);
            g_o[base + (size_t)n * 1024 + d] = cvt_tf32f(v2);
        }
        if (t < 64) {
            float s = 0.f;
#pragma unroll 8
            for (int Dl = 0; Dl < 32; Dl++) s += Pk[t * P32 + Dl] * Am[t * P32 + Dl];
            sp[t] = s;
        }
        __syncthreads();
        CLUSTER_SYNC();

        // ---- P6: total s
        if (t < 64) ss[t] = sp[t] + ld_dsmem(sp_peer + (uint32_t)t * 4u);
        __syncthreads();

        // ---- P7 (mma): grads + state update.
        // gin[Dl][d] = sum_n gz[n][Dl]*Kt[n][d], gout[Dl][d] = sum_n Pk[n][Dl]*V[n][d]
        // A transposed (gz/Pk read [k=tok][m=Dl]); B transposed (Kt/V read [k=tok][n=d]).
        {
            const int m0 = 16 * (w & 1);
            const int nb = (w >> 1) * 16;
            float Cgi[2][4], Cgo[2][4];
#pragma unroll
            for (int j = 0; j < 2; j++)
#pragma unroll
                for (int x2 = 0; x2 < 4; x2++) { Cgi[j][x2] = 0.f; Cgo[j][x2] = 0.f; }
#pragma unroll
            for (int kk = 0; kk < 8; kk++) {
                const int ka = kk * 8 + t4;
                const int kb2 = ka + 4;
                float ssa = ss[ka], ssb = ss[kb2];
                float pk0 = Pk[ka  * P32 + m0 + g],     am0 = Am[ka  * P32 + m0 + g];
                float pk1 = Pk[ka  * P32 + m0 + g + 8], am1 = Am[ka  * P32 + m0 + g + 8];
                float pk2 = Pk[kb2 * P32 + m0 + g],     am2 = Am[kb2 * P32 + m0 + g];
                float pk3 = Pk[kb2 * P32 + m0 + g + 8], am3 = Am[kb2 * P32 + m0 + g + 8];
                uint32_t gz0 = f2t(-pk0 * (am0 - ssa));
                uint32_t gz1 = f2t(-pk1 * (am1 - ssa));
                uint32_t gz2 = f2t(-pk2 * (am2 - ssb));
                uint32_t gz3 = f2t(-pk3 * (am3 - ssb));
                uint32_t p0 = f2t(pk0), p1 = f2t(pk1), p2 = f2t(pk2), p3 = f2t(pk3);
#pragma unroll
                for (int j = 0; j < 2; j++) {
                    const int dcol = nb + 8 * j + g;
                    uint32_t bk0 = f2t(Kt[ka  * P64 + dcol]);
                    uint32_t bk1 = f2t(Kt[kb2 * P64 + dcol]);
                    uint32_t bv0 = f2t(V [ka  * P64 + dcol]);
                    uint32_t bv1 = f2t(V [kb2 * P64 + dcol]);
                    mma_tf32(Cgi[j], gz0, gz1, gz2, gz3, bk0, bk1);
                    mma_tf32(Cgo[j], p0,  p1,  p2,  p3,  bv0, bv1);
                }
            }
#pragma unroll
            for (int j = 0; j < 2; j++) {
                const int col = nb + 8 * j + 2 * t4;
                const int i0 = (m0 + g)     * P64 + col;
                const int i1 = (m0 + g + 8) * P64 + col;
                Wi [i0]     = wdi * Wi [i0]     - li * Cgi[j][0];
                Wi [i0 + 1] = wdi * Wi [i0 + 1] - li * Cgi[j][1];
                Wi [i1]     = wdi * Wi [i1]     - li * Cgi[j][2];
                Wi [i1 + 1] = wdi * Wi [i1 + 1] - li * Cgi[j][3];
                Wo_[i0]     = wdo * Wo_[i0]     + lo * Cgo[j][0];
                Wo_[i0 + 1] = wdo * Wo_[i0 + 1] + lo * Cgo[j][1];
                Wo_[i1]     = wdo * Wo_[i1]     + lo * Cgo[j][2];
                Wo_[i1 + 1] = wdo * Wo_[i1 + 1] + lo * Cgo[j][3];
            }
        }
        __syncthreads();
    }
    CLUSTER_SYNC();   // keep smem alive for peer's in-flight DSMEM reads
}

// ---------------------------------------------------------------------------
// Launch
// ---------------------------------------------------------------------------
extern "C" void kernel_launch(void* const* d_in, const int* in_sizes, int n_in,
                              void* d_out, int out_size)
{
    (void)in_sizes; (void)n_in; (void)out_size;
    const float* x     = (const float*)d_in[0];
    const float* Wq    = (const float*)d_in[1];
    const float* Wk    = (const float*)d_in[2];
    const float* Wv    = (const float*)d_in[3];
    const float* Wlr   = (const float*)d_in[4];
    const float* Wbeta = (const float*)d_in[5];
    const float* Wo    = (const float*)d_in[6];
    const float* Win0  = (const float*)d_in[7];
    const float* Wout0 = (const float*)d_in[8];
    float* out = (float*)d_out;

    float *q, *k, *v, *om, *xt, *wt;
    cudaGetSymbolAddress((void**)&q,  g_q);
    cudaGetSymbolAddress((void**)&k,  g_k);
    cudaGetSymbolAddress((void**)&v,  g_v);
    cudaGetSymbolAddress((void**)&om, g_o);
    cudaGetSymbolAddress((void**)&xt, g_xt);
    cudaGetSymbolAddress((void**)&wt, g_wt);

    cudaFuncSetAttribute(gemm_tf32p<0>, cudaFuncAttributeMaxDynamicSharedMemorySize, GEMM_SMEM_BYTES);
    cudaFuncSetAttribute(gemm_tf32p<1>, cudaFuncAttributeMaxDynamicSharedMemorySize, GEMM_SMEM_BYTES);
    cudaFuncSetAttribute(scan_kernel,   cudaFuncAttributeMaxDynamicSharedMemorySize,
                         SCAN_SMEM_FLOATS * (int)sizeof(float));

    const int NX4 = (M_ * 1024) / 4;
    const int NW4 = (1024 * 1024) / 4;
    cvt_kernel<<<(NX4 + 255) / 256, 256>>>(x,  xt,            NX4);
    cvt_kernel<<<(NW4 + 255) / 256, 256>>>(Wq, wt + 0u * 1024u * 1024u, NW4);
    cvt_kernel<<<(NW4 + 255) / 256, 256>>>(Wk, wt + 1u * 1024u * 1024u, NW4);
    cvt_kernel<<<(NW4 + 255) / 256, 256>>>(Wv, wt + 2u * 1024u * 1024u, NW4);
    cvt_kernel<<<(NW4 + 255) / 256, 256>>>(Wo, wt + 3u * 1024u * 1024u, NW4);

    dim3 grid(1024 / 128, M_ / 128);
    gemm_tf32p<1><<<grid, 256, GEMM_SMEM_BYTES>>>(xt, wt + 0u * 1024u * 1024u, q, M_, 1024, 1024);
    gemm_tf32p<1><<<grid, 256, GEMM_SMEM_BYTES>>>(xt, wt + 1u * 1024u * 1024u, k, M_, 1024, 1024);
    gemm_tf32p<0><<<grid, 256, GEMM_SMEM_BYTES>>>(xt, wt + 2u * 1024u * 1024u, v, M_, 1024, 1024);
    lrwd_kernel<<<B_ * NCHUNK_, 256>>>(x, Wlr, Wbeta);

    const int smem_bytes = SCAN_SMEM_FLOATS * (int)sizeof(float);
    scan_kernel<<<128, 256, smem_bytes>>>(Win0, Wout0);

    // g_o already holds tf32 bits — final GEMM reads it directly
    gemm_tf32p<0><<<grid, 256, GEMM_SMEM_BYTES>>>(om, wt + 3u * 1024u * 1024u, out, M_, 1024, 1024);
}

// round 12
// speedup vs baseline: 1.3325x; 1.0422x over previous
#include <cuda_runtime.h>
#include <cstdint>

// Problem constants
#define B_ 4
#define L_ 4096
#define DIM_ 1024
#define H_ 16
#define NCHUNK_ 64
#define CHUNK_ 64
#define M_ (B_ * L_)          // 16384

// ---------------------------------------------------------------------------
// Device scratch (allocation-free contract: __device__ globals)
// ---------------------------------------------------------------------------
__device__ float g_q[(size_t)B_ * L_ * 1024];
__device__ float g_k[(size_t)B_ * L_ * 1024];
__device__ float g_v[(size_t)B_ * L_ * 1024];
__device__ float g_o[(size_t)B_ * L_ * 1024];   // scan writes tf32 bits directly
__device__ float g_xt[(size_t)B_ * L_ * 1024];  // tf32(x), produced by lrwd_kernel
__device__ float g_wt[4u * 1024u * 1024u];      // tf32(Wq,Wk,Wv,Wo)
__device__ float g_lrwd[B_ * NCHUNK_ * 64];

// ---------------------------------------------------------------------------
// PTX helpers
// ---------------------------------------------------------------------------
__device__ __forceinline__ float cvt_tf32f(float f) {
    uint32_t u;
    asm("cvt.rna.tf32.f32 %0, %1;" : "=r"(u) : "f"(f));
    return __uint_as_float(u);
}
__device__ __forceinline__ uint32_t f2t(float f) {
    uint32_t u;
    asm("cvt.rna.tf32.f32 %0, %1;" : "=r"(u) : "f"(f));
    return u;
}

__device__ __forceinline__ void cp16(void* smem, const void* gmem) {
    uint32_t s = (uint32_t)__cvta_generic_to_shared(smem);
    asm volatile("cp.async.cg.shared.global [%0], [%1], 16;" :: "r"(s), "l"(gmem));
}
__device__ __forceinline__ void cp_commit() {
    asm volatile("cp.async.commit_group;");
}
template <int N>
__device__ __forceinline__ void cp_wait() {
    asm volatile("cp.async.wait_group %0;" :: "n"(N));
}

__device__ __forceinline__ void mma_tf32(float c[4],
                                         uint32_t a0, uint32_t a1, uint32_t a2, uint32_t a3,
                                         uint32_t b0, uint32_t b1) {
    asm volatile(
        "mma.sync.aligned.m16n8k8.row.col.f32.tf32.tf32.f32 "
        "{%0,%1,%2,%3}, {%4,%5,%6,%7}, {%8,%9}, {%0,%1,%2,%3};"
        : "+f"(c[0]), "+f"(c[1]), "+f"(c[2]), "+f"(c[3])
        : "r"(a0), "r"(a1), "r"(a2), "r"(a3), "r"(b0), "r"(b1));
}

__device__ __forceinline__ uint32_t mapa_u32(uint32_t addr, uint32_t rank) {
    uint32_t r;
    asm("mapa.shared::cluster.u32 %0, %1, %2;" : "=r"(r) : "r"(addr), "r"(rank));
    return r;
}
__device__ __forceinline__ float ld_dsmem(uint32_t addr) {
    float v;
    asm volatile("ld.shared::cluster.f32 %0, [%1];" : "=f"(v) : "r"(addr));
    return v;
}
#define CLUSTER_SYNC() do { \
    asm volatile("barrier.cluster.arrive.aligned;" ::: "memory"); \
    asm volatile("barrier.cluster.wait.aligned;" ::: "memory"); } while (0)

// ---------------------------------------------------------------------------
// tf32 pre-convert (weights only now)
// ---------------------------------------------------------------------------
__global__ __launch_bounds__(256)
void cvt_kernel(const float* __restrict__ src, float* __restrict__ dst, int n4)
{
    int i = blockIdx.x * 256 + threadIdx.x;
    if (i < n4) {
        float4 v = ((const float4*)src)[i];
        v.x = cvt_tf32f(v.x); v.y = cvt_tf32f(v.y);
        v.z = cvt_tf32f(v.z); v.w = cvt_tf32f(v.w);
        ((float4*)dst)[i] = v;
    }
}

// ---------------------------------------------------------------------------
// TF32 tensor-core GEMM (NT), pre-converted inputs, 3-stage cp.async.
// ---------------------------------------------------------------------------
#define GEMM_SMEM_BYTES (3 * 2 * 128 * 20 * 4)

template <int ACT>
__global__ __launch_bounds__(256)
void gemm_tf32p(const float* __restrict__ A, const float* __restrict__ W,
                float* __restrict__ C, int M, int N, int K)
{
    extern __shared__ __align__(16) float gsm[];
    float (*As)[128][20] = (float (*)[128][20])gsm;
    float (*Bs)[128][20] = (float (*)[128][20])(gsm + 3 * 128 * 20);

    const int t    = threadIdx.x;
    const int bm   = blockIdx.y * 128;
    const int bn   = blockIdx.x * 128;
    const int w    = t >> 5;
    const int lane = t & 31;
    const int wm   = (w >> 2) * 64;
    const int wn   = (w & 3) * 32;
    const int g    = lane >> 2;
    const int t4   = lane & 3;

    float acc[4][4][4];
#pragma unroll
    for (int mt = 0; mt < 4; mt++)
#pragma unroll
        for (int nt = 0; nt < 4; nt++)
#pragma unroll
            for (int c = 0; c < 4; c++) acc[mt][nt][c] = 0.f;

    const int KT = K >> 4;

    auto load_stage = [&](int kb, int buf) {
        const int k0 = kb * 16;
#pragma unroll
        for (int s = 0; s < 2; s++) {
            int j   = t + s * 256;
            int row = j >> 2;
            int c4  = (j & 3) * 4;
            cp16(&As[buf][row][c4], A + (size_t)(bm + row) * K + k0 + c4);
            cp16(&Bs[buf][row][c4], W + (size_t)(bn + row) * K + k0 + c4);
        }
    };

    load_stage(0, 0); cp_commit();
    load_stage(1, 1); cp_commit();

    for (int kb = 0; kb < KT; kb++) {
        cp_wait<1>();
        __syncthreads();
        if (kb + 2 < KT) { load_stage(kb + 2, (kb + 2) % 3); cp_commit(); }
        else             { cp_commit(); }
        const int buf = kb % 3;

#pragma unroll
        for (int ks = 0; ks < 2; ks++) {
            const int k0 = ks * 8;
            uint32_t bf[4][2];
#pragma unroll
            for (int nt = 0; nt < 4; nt++) {
                bf[nt][0] = __float_as_uint(Bs[buf][wn + nt * 8 + g][k0 + t4]);
                bf[nt][1] = __float_as_uint(Bs[buf][wn + nt * 8 + g][k0 + t4 + 4]);
            }
#pragma unroll
            for (int mt = 0; mt < 4; mt++) {
                uint32_t a0 = __float_as_uint(As[buf][wm + mt * 16 + g][k0 + t4]);
                uint32_t a1 = __float_as_uint(As[buf][wm + mt * 16 + g + 8][k0 + t4]);
                uint32_t a2 = __float_as_uint(As[buf][wm + mt * 16 + g][k0 + t4 + 4]);
                uint32_t a3 = __float_as_uint(As[buf][wm + mt * 16 + g + 8][k0 + t4 + 4]);
#pragma unroll
                for (int nt = 0; nt < 4; nt++)
                    mma_tf32(acc[mt][nt], a0, a1, a2, a3, bf[nt][0], bf[nt][1]);
            }
        }
        __syncthreads();
    }

#pragma unroll
    for (int mt = 0; mt < 4; mt++) {
#pragma unroll
        for (int nt = 0; nt < 4; nt++) {
            int m = bm + wm + mt * 16 + g;
            int n = bn + wn + nt * 8 + t4 * 2;
            float2 v0 = make_float2(acc[mt][nt][0], acc[mt][nt][1]);
            float2 v1 = make_float2(acc[mt][nt][2], acc[mt][nt][3]);
            if (ACT == 1) {
                v0.x = v0.x / (1.f + __expf(-v0.x));
                v0.y = v0.y / (1.f + __expf(-v0.y));
                v1.x = v1.x / (1.f + __expf(-v1.x));
                v1.y = v1.y / (1.f + __expf(-v1.y));
            }
            *(float2*)&C[(size_t)m * N + n]       = v0;
            *(float2*)&C[(size_t)(m + 8) * N + n] = v1;
        }
    }
}

// ---------------------------------------------------------------------------
// lr/wd chunk means + fused x -> tf32 conversion (writes g_xt as it streams x)
// ---------------------------------------------------------------------------
__global__ __launch_bounds__(256, 2)
void lrwd_kernel(const float* __restrict__ x,
                 const float* __restrict__ Wlr,
                 const float* __restrict__ Wbeta,
                 float* __restrict__ xt)
{
    __shared__ float xs[64][65];
    __shared__ float ws[64][65];
    __shared__ float red2[64 * 16];

    const int bc = blockIdx.x;
    const size_t xb = (size_t)bc * 64 * 1024;
    const int t  = threadIdx.x;
    const int r0 = t >> 4;
    const int c0 = t & 15;

    float acc[4][4];
#pragma unroll
    for (int i = 0; i < 4; i++)
#pragma unroll
        for (int j = 0; j < 4; j++) acc[i][j] = 0.f;

    for (int k0 = 0; k0 < 1024; k0 += 64) {
        for (int i = t; i < 4096; i += 256) {
            int n = i >> 6, d = i & 63;
            size_t gi = xb + (size_t)n * 1024 + k0 + d;
            float xv = x[gi];
            xs[n][d] = xv;
            xt[gi]   = cvt_tf32f(xv);          // fused tf32 conversion
            ws[n][d] = (n < 32) ? Wlr[n * 1024 + k0 + d]
                                : Wbeta[(n - 32) * 1024 + k0 + d];
        }
        __syncthreads();
#pragma unroll 4
        for (int k = 0; k < 64; k++) {
            float a[4], b[4];
#pragma unroll
            for (int ii = 0; ii < 4; ii++) a[ii] = xs[r0 + 16 * ii][k];
#pragma unroll
            for (int jj = 0; jj < 4; jj++) b[jj] = ws[c0 + 16 * jj][k];
#pragma unroll
            for (int ii = 0; ii < 4; ii++)
#pragma unroll
                for (int jj = 0; jj < 4; jj++) acc[ii][jj] += a[ii] * b[jj];
        }
        __syncthreads();
    }

#pragma unroll
    for (int jj = 0; jj < 4; jj++) {
        int j = c0 + 16 * jj;
        float scale = (j < 32) ? 0.001f : 0.9f;
        float p = 0.f;
#pragma unroll
        for (int ii = 0; ii < 4; ii++)
            p += scale / (1.f + __expf(-acc[ii][jj]));
        red2[j * 16 + r0] = p;
    }
    __syncthreads();
    if (t < 64) {
        float s = 0.f;
        for (int r = 0; r < 16; r++) s += red2[t * 16 + r];
        g_lrwd[bc * 64 + t] = s * (1.f / 64.f);
    }
}

// ---------------------------------------------------------------------------
// Cluster-2 persistent scan, all four gemmlets on mma.sync.
// Pitches 68/36 (== 4 mod 32): A-fragment loads conflict-free.
// ---------------------------------------------------------------------------
#define P64 68
#define P32 36

#define OFF_WI   0                           // [32][68]
#define OFF_WO   (32 * P64)                  // 2176
#define OFF_Q    (2 * 32 * P64)              // 4352  [64][68]
#define OFF_K    (OFF_Q + 64 * P64)          // 8704
#define OFF_V    (OFF_K + 64 * P64)          // 13056
#define OFF_PQ   (OFF_V + 64 * P64)          // 17408 [64][36]
#define OFF_PK   (OFF_PQ + 64 * P32)         // 19712
#define OFF_AM   (OFF_PK + 64 * P32)         // 22016
#define OFF_OP   (OFF_AM + 64 * P32)         // 24320 [64][68]
#define OFF_SP   (OFF_OP + 64 * P64)         // 28672
#define OFF_SS   (OFF_SP + 64)               // 28736
#define OFF_RED  (OFF_SS + 64)               // 28800 [4][64]
#define OFF_CS   (OFF_RED + 256)             // 29056
#define SCAN_SMEM_FLOATS (OFF_CS + 64)       // 29120 -> 116480 bytes

__global__ __launch_bounds__(256, 1) __cluster_dims__(2, 1, 1)
void scan_kernel(const float* __restrict__ Win0, const float* __restrict__ Wout0)
{
    extern __shared__ float sm[];
    float* Wi  = sm + OFF_WI;
    float* Wo_ = sm + OFF_WO;
    float* Q   = sm + OFF_Q;
    float* Kt  = sm + OFF_K;
    float* V   = sm + OFF_V;
    float* Pq  = sm + OFF_PQ;
    float* Pk  = sm + OFF_PK;
    float* Am  = sm + OFF_AM;
    float* op  = sm + OFF_OP;
    float* sp  = sm + OFF_SP;
    float* ss  = sm + OFF_SS;
    float* red = sm + OFF_RED;
    float* cs  = sm + OFF_CS;

    const int pair = blockIdx.x >> 1;
    const uint32_t rank = blockIdx.x & 1;
    const int b = pair >> 4;
    const int h = pair & 15;
    const int t = threadIdx.x;

    const int w    = t >> 5;
    const int lane = t & 31;
    const int g    = lane >> 2;     // 0..7
    const int t4   = lane & 3;      // 0..3
    const int task = t & 63, sg = t >> 6;    // softmax

    const uint32_t op_peer = mapa_u32((uint32_t)__cvta_generic_to_shared(op), rank ^ 1u);
    const uint32_t sp_peer = mapa_u32((uint32_t)__cvta_generic_to_shared(sp), rank ^ 1u);

    // init state halves (pitch 68)
    for (int i = t; i < 2048; i += 256) {
        int Dl = i >> 6, d = i & 63;
        int Dg = (int)rank * 32 + Dl;
        Wi [Dl * P64 + d] = Win0 [Dg * 1024 + h * 64 + d];
        Wo_[Dl * P64 + d] = Wout0[Dg * 1024 + h * 64 + d];
    }
    __syncthreads();

    for (int c = 0; c < NCHUNK_; c++) {
        const size_t base = ((size_t)b * L_ + (size_t)c * 64) * 1024 + h * 64;
        const int lb = (b * 64 + c) * 64;
        const float li  = g_lrwd[lb + h];
        const float lo  = g_lrwd[lb + 16 + h];
        const float wdi = g_lrwd[lb + 32 + h];
        const float wdo = g_lrwd[lb + 48 + h];

        // ---- P1: load q,k,v tiles (float4 LDG -> float4 STS, pitch 68)
        for (int i = t; i < 1024; i += 256) {
            int n = i >> 4, d4 = (i & 15) * 4;
            size_t gidx = base + (size_t)n * 1024 + d4;
            *(float4*)&Q [n * P64 + d4] = *(const float4*)&g_q[gidx];
            *(float4*)&Kt[n * P64 + d4] = *(const float4*)&g_k[gidx];
            *(float4*)&V [n * P64 + d4] = *(const float4*)&g_v[gidx];
        }
        __syncthreads();

        // ---- P2 (mma): logits. warps 0-3: Pq = Q@Wi^T, warps 4-7: Pk = K@Wi^T
        {
            const float* src = (w < 4) ? Q  : Kt;
            float*       dst = (w < 4) ? Pq : Pk;
            const int m0 = 16 * (w & 3);
            float C_[4][4];
#pragma unroll
            for (int j = 0; j < 4; j++)
#pragma unroll
                for (int x2 = 0; x2 < 4; x2++) C_[j][x2] = 0.f;
#pragma unroll
            for (int kk = 0; kk < 8; kk++) {
                const int k0 = kk * 8;
                uint32_t a0 = f2t(src[(m0 + g)     * P64 + k0 + t4]);
                uint32_t a1 = f2t(src[(m0 + g + 8) * P64 + k0 + t4]);
                uint32_t a2 = f2t(src[(m0 + g)     * P64 + k0 + t4 + 4]);
                uint32_t a3 = f2t(src[(m0 + g + 8) * P64 + k0 + t4 + 4]);
#pragma unroll
                for (int j = 0; j < 4; j++) {
                    uint32_t b0 = f2t(Wi[(8 * j + g) * P64 + k0 + t4]);
                    uint32_t b1 = f2t(Wi[(8 * j + g) * P64 + k0 + t4 + 4]);
                    mma_tf32(C_[j], a0, a1, a2, a3, b0, b1);
                }
            }
#pragma unroll
            for (int j = 0; j < 4; j++) {
                dst[(m0 + g)     * P32 + 8 * j + 2 * t4]     = C_[j][0];
                dst[(m0 + g)     * P32 + 8 * j + 2 * t4 + 1] = C_[j][1];
                dst[(m0 + g + 8) * P32 + 8 * j + 2 * t4]     = C_[j][2];
                dst[(m0 + g + 8) * P32 + 8 * j + 2 * t4 + 1] = C_[j][3];
            }
        }
        __syncthreads();

        // ---- P3: merged softmax over n for both Pq and Pk (per column D)
        {
            float* Pp = (task < 32) ? Pq : Pk;
            const int D = task & 31;
            float m = -1e30f;
#pragma unroll
            for (int n = sg * 16; n < sg * 16 + 16; n++) m = fmaxf(m, Pp[n * P32 + D]);
            red[sg * 64 + task] = m;
            __syncthreads();
            if (t < 64)
                cs[t] = fmaxf(fmaxf(red[t], red[64 + t]), fmaxf(red[128 + t], red[192 + t]));
            __syncthreads();
            float mm = cs[task], s = 0.f;
#pragma unroll
            for (int n = sg * 16; n < sg * 16 + 16; n++) {
                float e = __expf(Pp[n * P32 + D] - mm);
                Pp[n * P32 + D] = e;
                s += e;
            }
            red[sg * 64 + task] = s;
            __syncthreads();
            if (t < 64) cs[t] = 1.f / (red[t] + red[64 + t] + red[128 + t] + red[192 + t]);
            __syncthreads();
            float inv = cs[task];
#pragma unroll
            for (int n = sg * 16; n < sg * 16 + 16; n++) Pp[n * P32 + D] *= inv;
        }
        __syncthreads();

        // ---- P4a (mma): op[n][d] = sum_Dl Pq[n][Dl] * Wo_[Dl][d]
        // M=64(n) x N=64(d) x K=32(Dl). m0 = 16*(w&3), d-half nb = 32*(w>>2).
        {
            const int m0 = 16 * (w & 3);
            const int nb = 32 * (w >> 2);
            float Co[4][4];
#pragma unroll
            for (int j = 0; j < 4; j++)
#pragma unroll
                for (int x2 = 0; x2 < 4; x2++) Co[j][x2] = 0.f;
#pragma unroll
            for (int kk = 0; kk < 4; kk++) {
                const int k0 = kk * 8;
                uint32_t a0 = f2t(Pq[(m0 + g)     * P32 + k0 + t4]);
                uint32_t a1 = f2t(Pq[(m0 + g + 8) * P32 + k0 + t4]);
                uint32_t a2 = f2t(Pq[(m0 + g)     * P32 + k0 + t4 + 4]);
                uint32_t a3 = f2t(Pq[(m0 + g + 8) * P32 + k0 + t4 + 4]);
#pragma unroll
                for (int j = 0; j < 4; j++) {
                    const int dcol = nb + 8 * j + g;
                    uint32_t b0 = f2t(Wo_[(k0 + t4)     * P64 + dcol]);
                    uint32_t b1 = f2t(Wo_[(k0 + t4 + 4) * P64 + dcol]);
                    mma_tf32(Co[j], a0, a1, a2, a3, b0, b1);
                }
            }
#pragma unroll
            for (int j = 0; j < 4; j++) {
                const int col = nb + 8 * j + 2 * t4;
                op[(m0 + g)     * P64 + col]     = Co[j][0];
                op[(m0 + g)     * P64 + col + 1] = Co[j][1];
                op[(m0 + g + 8) * P64 + col]     = Co[j][2];
                op[(m0 + g + 8) * P64 + col + 1] = Co[j][3];
            }
        }

        // ---- P4b (mma): Am[n][Dl] = sum_d V[n][d]*Wo_[Dl][d]
        {
            const int m0 = 16 * (w & 3);
            const int nb = (w >> 2) * 16;
            float Ca[2][4];
#pragma unroll
            for (int j = 0; j < 2; j++)
#pragma unroll
                for (int x2 = 0; x2 < 4; x2++) Ca[j][x2] = 0.f;
#pragma unroll
            for (int kk = 0; kk < 8; kk++) {
                const int k0 = kk * 8;
                uint32_t a0 = f2t(V[(m0 + g)     * P64 + k0 + t4]);
                uint32_t a1 = f2t(V[(m0 + g + 8) * P64 + k0 + t4]);
                uint32_t a2 = f2t(V[(m0 + g)     * P64 + k0 + t4 + 4]);
                uint32_t a3 = f2t(V[(m0 + g + 8) * P64 + k0 + t4 + 4]);
#pragma unroll
                for (int j = 0; j < 2; j++) {
                    const int Dl = nb + 8 * j + g;
                    uint32_t b0 = f2t(Wo_[Dl * P64 + k0 + t4]);
                    uint32_t b1 = f2t(Wo_[Dl * P64 + k0 + t4 + 4]);
                    mma_tf32(Ca[j], a0, a1, a2, a3, b0, b1);
                }
            }
#pragma unroll
            for (int j = 0; j < 2; j++) {
                Am[(m0 + g)     * P32 + nb + 8 * j + 2 * t4]     = Ca[j][0];
                Am[(m0 + g)     * P32 + nb + 8 * j + 2 * t4 + 1] = Ca[j][1];
                Am[(m0 + g + 8) * P32 + nb + 8 * j + 2 * t4]     = Ca[j][2];
                Am[(m0 + g + 8) * P32 + nb + 8 * j + 2 * t4 + 1] = Ca[j][3];
            }
        }
        __syncthreads();
        CLUSTER_SYNC();

        // ---- P5: o = op_self + op_peer (tf32 fused into store); sp
        for (int i = t; i < 2048; i += 256) {
            int n = (int)rank * 32 + (i >> 6), d = i & 63;
            float v2 = op[n * P64 + d] + ld_dsmem(op_peer + (uint32_t)(n * P64 + d) * 4u);
            g_o[base + (size_t)n * 1024 + d] = cvt_tf32f(v2);
        }
        if (t < 64) {
            float s = 0.f;
#pragma unroll 8
            for (int Dl = 0; Dl < 32; Dl++) s += Pk[t * P32 + Dl] * Am[t * P32 + Dl];
            sp[t] = s;
        }
        __syncthreads();
        CLUSTER_SYNC();

        // ---- P6: total s
        if (t < 64) ss[t] = sp[t] + ld_dsmem(sp_peer + (uint32_t)t * 4u);
        __syncthreads();

        // ---- P7 (mma): grads + state update (A,B both transposed reads)
        {
            const int m0 = 16 * (w & 1);
            const int nb = (w >> 1) * 16;
            float Cgi[2][4], Cgo[2][4];
#pragma unroll
            for (int j = 0; j < 2; j++)
#pragma unroll
                for (int x2 = 0; x2 < 4; x2++) { Cgi[j][x2] = 0.f; Cgo[j][x2] = 0.f; }
#pragma unroll
            for (int kk = 0; kk < 8; kk++) {
                const int ka = kk * 8 + t4;
                const int kb2 = ka + 4;
                float ssa = ss[ka], ssb = ss[kb2];
                float pk0 = Pk[ka  * P32 + m0 + g],     am0 = Am[ka  * P32 + m0 + g];
                float pk1 = Pk[ka  * P32 + m0 + g + 8], am1 = Am[ka  * P32 + m0 + g + 8];
                float pk2 = Pk[kb2 * P32 + m0 + g],     am2 = Am[kb2 * P32 + m0 + g];
                float pk3 = Pk[kb2 * P32 + m0 + g + 8], am3 = Am[kb2 * P32 + m0 + g + 8];
                uint32_t gz0 = f2t(-pk0 * (am0 - ssa));
                uint32_t gz1 = f2t(-pk1 * (am1 - ssa));
                uint32_t gz2 = f2t(-pk2 * (am2 - ssb));
                uint32_t gz3 = f2t(-pk3 * (am3 - ssb));
                uint32_t p0 = f2t(pk0), p1 = f2t(pk1), p2 = f2t(pk2), p3 = f2t(pk3);
#pragma unroll
                for (int j = 0; j < 2; j++) {
                    const int dcol = nb + 8 * j + g;
                    uint32_t bk0 = f2t(Kt[ka  * P64 + dcol]);
                    uint32_t bk1 = f2t(Kt[kb2 * P64 + dcol]);
                    uint32_t bv0 = f2t(V [ka  * P64 + dcol]);
                    uint32_t bv1 = f2t(V [kb2 * P64 + dcol]);
                    mma_tf32(Cgi[j], gz0, gz1, gz2, gz3, bk0, bk1);
                    mma_tf32(Cgo[j], p0,  p1,  p2,  p3,  bv0, bv1);
                }
            }
#pragma unroll
            for (int j = 0; j < 2; j++) {
                const int col = nb + 8 * j + 2 * t4;
                const int i0 = (m0 + g)     * P64 + col;
                const int i1 = (m0 + g + 8) * P64 + col;
                Wi [i0]     = wdi * Wi [i0]     - li * Cgi[j][0];
                Wi [i0 + 1] = wdi * Wi [i0 + 1] - li * Cgi[j][1];
                Wi [i1]     = wdi * Wi [i1]     - li * Cgi[j][2];
                Wi [i1 + 1] = wdi * Wi [i1 + 1] - li * Cgi[j][3];
                Wo_[i0]     = wdo * Wo_[i0]     + lo * Cgo[j][0];
                Wo_[i0 + 1] = wdo * Wo_[i0 + 1] + lo * Cgo[j][1];
                Wo_[i1]     = wdo * Wo_[i1]     + lo * Cgo[j][2];
                Wo_[i1 + 1] = wdo * Wo_[i1 + 1] + lo * Cgo[j][3];
            }
        }
        __syncthreads();
    }
    CLUSTER_SYNC();   // keep smem alive for peer's in-flight DSMEM reads
}

// ---------------------------------------------------------------------------
// Launch
// ---------------------------------------------------------------------------
extern "C" void kernel_launch(void* const* d_in, const int* in_sizes, int n_in,
                              void* d_out, int out_size)
{
    (void)in_sizes; (void)n_in; (void)out_size;
    const float* x     = (const float*)d_in[0];
    const float* Wq    = (const float*)d_in[1];
    const float* Wk    = (const float*)d_in[2];
    const float* Wv    = (const float*)d_in[3];
    const float* Wlr   = (const float*)d_in[4];
    const float* Wbeta = (const float*)d_in[5];
    const float* Wo    = (const float*)d_in[6];
    const float* Win0  = (const float*)d_in[7];
    const float* Wout0 = (const float*)d_in[8];
    float* out = (float*)d_out;

    float *q, *k, *v, *om, *xt, *wt;
    cudaGetSymbolAddress((void**)&q,  g_q);
    cudaGetSymbolAddress((void**)&k,  g_k);
    cudaGetSymbolAddress((void**)&v,  g_v);
    cudaGetSymbolAddress((void**)&om, g_o);
    cudaGetSymbolAddress((void**)&xt, g_xt);
    cudaGetSymbolAddress((void**)&wt, g_wt);

    cudaFuncSetAttribute(gemm_tf32p<0>, cudaFuncAttributeMaxDynamicSharedMemorySize, GEMM_SMEM_BYTES);
    cudaFuncSetAttribute(gemm_tf32p<1>, cudaFuncAttributeMaxDynamicSharedMemorySize, GEMM_SMEM_BYTES);
    cudaFuncSetAttribute(scan_kernel,   cudaFuncAttributeMaxDynamicSharedMemorySize,
                         SCAN_SMEM_FLOATS * (int)sizeof(float));

    const int NW4 = (1024 * 1024) / 4;
    // lrwd first: streams x once, emits tf32(x) into g_xt as a side product
    lrwd_kernel<<<B_ * NCHUNK_, 256>>>(x, Wlr, Wbeta, xt);
    cvt_kernel<<<(NW4 + 255) / 256, 256>>>(Wq, wt + 0u * 1024u * 1024u, NW4);
    cvt_kernel<<<(NW4 + 255) / 256, 256>>>(Wk, wt + 1u * 1024u * 1024u, NW4);
    cvt_kernel<<<(NW4 + 255) / 256, 256>>>(Wv, wt + 2u * 1024u * 1024u, NW4);
    cvt_kernel<<<(NW4 + 255) / 256, 256>>>(Wo, wt + 3u * 1024u * 1024u, NW4);

    dim3 grid(1024 / 128, M_ / 128);
    gemm_tf32p<1><<<grid, 256, GEMM_SMEM_BYTES>>>(xt, wt + 0u * 1024u * 1024u, q, M_, 1024, 1024);
    gemm_tf32p<1><<<grid, 256, GEMM_SMEM_BYTES>>>(xt, wt + 1u * 1024u * 1024u, k, M_, 1024, 1024);
    gemm_tf32p<0><<<grid, 256, GEMM_SMEM_BYTES>>>(xt, wt + 2u * 1024u * 1024u, v, M_, 1024, 1024);

    const int smem_bytes = SCAN_SMEM_FLOATS * (int)sizeof(float);
    scan_kernel<<<128, 256, smem_bytes>>>(Win0, Wout0);

    // g_o already holds tf32 bits — final GEMM reads it directly
    gemm_tf32p<0><<<grid, 256, GEMM_SMEM_BYTES>>>(om, wt + 3u * 1024u * 1024u, out, M_, 1024, 1024);
}

// round 14
// speedup vs baseline: 1.4497x; 1.0879x over previous
#include <cuda_runtime.h>
#include <cstdint>

// Problem constants
#define B_ 4
#define L_ 4096
#define DIM_ 1024
#define H_ 16
#define NCHUNK_ 64
#define CHUNK_ 64
#define M_ (B_ * L_)          // 16384

// ---------------------------------------------------------------------------
// Device scratch (allocation-free contract: __device__ globals)
// ---------------------------------------------------------------------------
__device__ float g_q[(size_t)B_ * L_ * 1024];   // tf32 bits (projection epilogue cvt)
__device__ float g_k[(size_t)B_ * L_ * 1024];   // tf32 bits
__device__ float g_v[(size_t)B_ * L_ * 1024];   // tf32 bits
__device__ float g_o[(size_t)B_ * L_ * 1024];   // tf32 bits (scan P5 cvt)
__device__ float g_xt[(size_t)B_ * L_ * 1024];  // tf32(x), produced by lrwd_kernel
__device__ float g_wt[4u * 1024u * 1024u];      // tf32(Wq,Wk,Wv,Wo)
__device__ float g_lrwd[B_ * NCHUNK_ * 64];

// ---------------------------------------------------------------------------
// PTX helpers
// ---------------------------------------------------------------------------
__device__ __forceinline__ float cvt_tf32f(float f) {
    uint32_t u;
    asm("cvt.rna.tf32.f32 %0, %1;" : "=r"(u) : "f"(f));
    return __uint_as_float(u);
}
__device__ __forceinline__ uint32_t f2t(float f) {
    uint32_t u;
    asm("cvt.rna.tf32.f32 %0, %1;" : "=r"(u) : "f"(f));
    return u;
}

__device__ __forceinline__ void cp16(void* smem, const void* gmem) {
    uint32_t s = (uint32_t)__cvta_generic_to_shared(smem);
    asm volatile("cp.async.cg.shared.global [%0], [%1], 16;" :: "r"(s), "l"(gmem));
}
__device__ __forceinline__ void cp_commit() {
    asm volatile("cp.async.commit_group;");
}
template <int N>
__device__ __forceinline__ void cp_wait() {
    asm volatile("cp.async.wait_group %0;" :: "n"(N));
}

__device__ __forceinline__ void mma_tf32(float c[4],
                                         uint32_t a0, uint32_t a1, uint32_t a2, uint32_t a3,
                                         uint32_t b0, uint32_t b1) {
    asm volatile(
        "mma.sync.aligned.m16n8k8.row.col.f32.tf32.tf32.f32 "
        "{%0,%1,%2,%3}, {%4,%5,%6,%7}, {%8,%9}, {%0,%1,%2,%3};"
        : "+f"(c[0]), "+f"(c[1]), "+f"(c[2]), "+f"(c[3])
        : "r"(a0), "r"(a1), "r"(a2), "r"(a3), "r"(b0), "r"(b1));
}

__device__ __forceinline__ uint32_t mapa_u32(uint32_t addr, uint32_t rank) {
    uint32_t r;
    asm("mapa.shared::cluster.u32 %0, %1, %2;" : "=r"(r) : "r"(addr), "r"(rank));
    return r;
}
__device__ __forceinline__ float ld_dsmem(uint32_t addr) {
    float v;
    asm volatile("ld.shared::cluster.f32 %0, [%1];" : "=f"(v) : "r"(addr));
    return v;
}
#define CLUSTER_SYNC() do { \
    asm volatile("barrier.cluster.arrive.aligned;" ::: "memory"); \
    asm volatile("barrier.cluster.wait.aligned;" ::: "memory"); } while (0)

// ---------------------------------------------------------------------------
// tf32 pre-convert (weights only)
// ---------------------------------------------------------------------------
__global__ __launch_bounds__(256)
void cvt_kernel(const float* __restrict__ src, float* __restrict__ dst, int n4)
{
    int i = blockIdx.x * 256 + threadIdx.x;
    if (i < n4) {
        float4 v = ((const float4*)src)[i];
        v.x = cvt_tf32f(v.x); v.y = cvt_tf32f(v.y);
        v.z = cvt_tf32f(v.z); v.w = cvt_tf32f(v.w);
        ((float4*)dst)[i] = v;
    }
}

// ---------------------------------------------------------------------------
// TF32 tensor-core GEMM (NT), pre-converted inputs, 3-stage cp.async.
// CVT=1: store tf32 bit patterns (for scan-consumed q/k/v).
// ---------------------------------------------------------------------------
#define GEMM_SMEM_BYTES (3 * 2 * 128 * 20 * 4)

template <int ACT, int CVT>
__global__ __launch_bounds__(256)
void gemm_tf32p(const float* __restrict__ A, const float* __restrict__ W,
                float* __restrict__ C, int M, int N, int K)
{
    extern __shared__ __align__(16) float gsm[];
    float (*As)[128][20] = (float (*)[128][20])gsm;
    float (*Bs)[128][20] = (float (*)[128][20])(gsm + 3 * 128 * 20);

    const int t    = threadIdx.x;
    const int bm   = blockIdx.y * 128;
    const int bn   = blockIdx.x * 128;
    const int w    = t >> 5;
    const int lane = t & 31;
    const int wm   = (w >> 2) * 64;
    const int wn   = (w & 3) * 32;
    const int g    = lane >> 2;
    const int t4   = lane & 3;

    float acc[4][4][4];
#pragma unroll
    for (int mt = 0; mt < 4; mt++)
#pragma unroll
        for (int nt = 0; nt < 4; nt++)
#pragma unroll
            for (int c = 0; c < 4; c++) acc[mt][nt][c] = 0.f;

    const int KT = K >> 4;

    auto load_stage = [&](int kb, int buf) {
        const int k0 = kb * 16;
#pragma unroll
        for (int s = 0; s < 2; s++) {
            int j   = t + s * 256;
            int row = j >> 2;
            int c4  = (j & 3) * 4;
            cp16(&As[buf][row][c4], A + (size_t)(bm + row) * K + k0 + c4);
            cp16(&Bs[buf][row][c4], W + (size_t)(bn + row) * K + k0 + c4);
        }
    };

    load_stage(0, 0); cp_commit();
    load_stage(1, 1); cp_commit();

    for (int kb = 0; kb < KT; kb++) {
        cp_wait<1>();
        __syncthreads();
        if (kb + 2 < KT) { load_stage(kb + 2, (kb + 2) % 3); cp_commit(); }
        else             { cp_commit(); }
        const int buf = kb % 3;

#pragma unroll
        for (int ks = 0; ks < 2; ks++) {
            const int k0 = ks * 8;
            uint32_t bf[4][2];
#pragma unroll
            for (int nt = 0; nt < 4; nt++) {
                bf[nt][0] = __float_as_uint(Bs[buf][wn + nt * 8 + g][k0 + t4]);
                bf[nt][1] = __float_as_uint(Bs[buf][wn + nt * 8 + g][k0 + t4 + 4]);
            }
#pragma unroll
            for (int mt = 0; mt < 4; mt++) {
                uint32_t a0 = __float_as_uint(As[buf][wm + mt * 16 + g][k0 + t4]);
                uint32_t a1 = __float_as_uint(As[buf][wm + mt * 16 + g + 8][k0 + t4]);
                uint32_t a2 = __float_as_uint(As[buf][wm + mt * 16 + g][k0 + t4 + 4]);
                uint32_t a3 = __float_as_uint(As[buf][wm + mt * 16 + g + 8][k0 + t4 + 4]);
#pragma unroll
                for (int nt = 0; nt < 4; nt++)
                    mma_tf32(acc[mt][nt], a0, a1, a2, a3, bf[nt][0], bf[nt][1]);
            }
        }
        __syncthreads();
    }

#pragma unroll
    for (int mt = 0; mt < 4; mt++) {
#pragma unroll
        for (int nt = 0; nt < 4; nt++) {
            int m = bm + wm + mt * 16 + g;
            int n = bn + wn + nt * 8 + t4 * 2;
            float2 v0 = make_float2(acc[mt][nt][0], acc[mt][nt][1]);
            float2 v1 = make_float2(acc[mt][nt][2], acc[mt][nt][3]);
            if (ACT == 1) {
                v0.x = v0.x / (1.f + __expf(-v0.x));
                v0.y = v0.y / (1.f + __expf(-v0.y));
                v1.x = v1.x / (1.f + __expf(-v1.x));
                v1.y = v1.y / (1.f + __expf(-v1.y));
            }
            if (CVT == 1) {
                v0.x = cvt_tf32f(v0.x); v0.y = cvt_tf32f(v0.y);
                v1.x = cvt_tf32f(v1.x); v1.y = cvt_tf32f(v1.y);
            }
            *(float2*)&C[(size_t)m * N + n]       = v0;
            *(float2*)&C[(size_t)(m + 8) * N + n] = v1;
        }
    }
}

// ---------------------------------------------------------------------------
// lr/wd chunk means + fused x -> tf32 conversion
// ---------------------------------------------------------------------------
__global__ __launch_bounds__(256, 2)
void lrwd_kernel(const float* __restrict__ x,
                 const float* __restrict__ Wlr,
                 const float* __restrict__ Wbeta,
                 float* __restrict__ xt)
{
    __shared__ float xs[64][65];
    __shared__ float ws[64][65];
    __shared__ float red2[64 * 16];

    const int bc = blockIdx.x;
    const size_t xb = (size_t)bc * 64 * 1024;
    const int t  = threadIdx.x;
    const int r0 = t >> 4;
    const int c0 = t & 15;

    float acc[4][4];
#pragma unroll
    for (int i = 0; i < 4; i++)
#pragma unroll
        for (int j = 0; j < 4; j++) acc[i][j] = 0.f;

    for (int k0 = 0; k0 < 1024; k0 += 64) {
        for (int i = t; i < 4096; i += 256) {
            int n = i >> 6, d = i & 63;
            size_t gi = xb + (size_t)n * 1024 + k0 + d;
            float xv = x[gi];
            xs[n][d] = xv;
            xt[gi]   = cvt_tf32f(xv);
            ws[n][d] = (n < 32) ? Wlr[n * 1024 + k0 + d]
                                : Wbeta[(n - 32) * 1024 + k0 + d];
        }
        __syncthreads();
#pragma unroll 4
        for (int k = 0; k < 64; k++) {
            float a[4], b[4];
#pragma unroll
            for (int ii = 0; ii < 4; ii++) a[ii] = xs[r0 + 16 * ii][k];
#pragma unroll
            for (int jj = 0; jj < 4; jj++) b[jj] = ws[c0 + 16 * jj][k];
#pragma unroll
            for (int ii = 0; ii < 4; ii++)
#pragma unroll
                for (int jj = 0; jj < 4; jj++) acc[ii][jj] += a[ii] * b[jj];
        }
        __syncthreads();
    }

#pragma unroll
    for (int jj = 0; jj < 4; jj++) {
        int j = c0 + 16 * jj;
        float scale = (j < 32) ? 0.001f : 0.9f;
        float p = 0.f;
#pragma unroll
        for (int ii = 0; ii < 4; ii++)
            p += scale / (1.f + __expf(-acc[ii][jj]));
        red2[j * 16 + r0] = p;
    }
    __syncthreads();
    if (t < 64) {
        float s = 0.f;
        for (int r = 0; r < 16; r++) s += red2[t * 16 + r];
        g_lrwd[bc * 64 + t] = s * (1.f / 64.f);
    }
}

// ---------------------------------------------------------------------------
// Cluster-2 persistent scan: all-mma gemmlets, double-buffered cp.async
// q/k/v prefetch (tiles hold tf32 bits), pitches 68/36.
// ---------------------------------------------------------------------------
#define P64 68
#define P32 36

#define OFF_WI   0                           // [32][68]
#define OFF_WO   (32 * P64)                  // 2176
#define OFF_T    (2 * 32 * P64)              // 4352: tiles [2 bufs][3 tiles][64][68]
#define TILE_SZ  (64 * P64)                  // 4352
#define OFF_PQ   (OFF_T + 6 * TILE_SZ)       // 30464 [64][36]
#define OFF_PK   (OFF_PQ + 64 * P32)         // 32768
#define OFF_AM   (OFF_PK + 64 * P32)         // 35072
#define OFF_OP   (OFF_AM + 64 * P32)         // 37376 [64][68]
#define OFF_SP   (OFF_OP + TILE_SZ)          // 41728
#define OFF_SS   (OFF_SP + 64)               // 41792
#define OFF_RED  (OFF_SS + 64)               // 41856 [4][64]
#define OFF_CS   (OFF_RED + 256)             // 42112
#define SCAN_SMEM_FLOATS (OFF_CS + 64)       // 42176 -> 168704 bytes

__global__ __launch_bounds__(256, 1) __cluster_dims__(2, 1, 1)
void scan_kernel(const float* __restrict__ Win0, const float* __restrict__ Wout0)
{
    extern __shared__ float sm[];
    float* Wi  = sm + OFF_WI;
    float* Wo_ = sm + OFF_WO;
    float* Pq  = sm + OFF_PQ;
    float* Pk  = sm + OFF_PK;
    float* Am  = sm + OFF_AM;
    float* op  = sm + OFF_OP;
    float* sp  = sm + OFF_SP;
    float* ss  = sm + OFF_SS;
    float* red = sm + OFF_RED;
    float* cs  = sm + OFF_CS;

    const int pair = blockIdx.x >> 1;
    const uint32_t rank = blockIdx.x & 1;
    const int b = pair >> 4;
    const int h = pair & 15;
    const int t = threadIdx.x;

    const int w    = t >> 5;
    const int lane = t & 31;
    const int g    = lane >> 2;
    const int t4   = lane & 3;
    const int task = t & 63, sg = t >> 6;

    const uint32_t op_peer = mapa_u32((uint32_t)__cvta_generic_to_shared(op), rank ^ 1u);
    const uint32_t sp_peer = mapa_u32((uint32_t)__cvta_generic_to_shared(sp), rank ^ 1u);

    // init state halves (pitch 68)
    for (int i = t; i < 2048; i += 256) {
        int Dl = i >> 6, d = i & 63;
        int Dg = (int)rank * 32 + Dl;
        Wi [Dl * P64 + d] = Win0 [Dg * 1024 + h * 64 + d];
        Wo_[Dl * P64 + d] = Wout0[Dg * 1024 + h * 64 + d];
    }

    // prefetch q/k/v for a chunk into tile buffer `buf`
    auto prefetch = [&](int c, int buf) {
        const size_t base = ((size_t)b * L_ + (size_t)c * 64) * 1024 + h * 64;
        float* Qb = sm + OFF_T + (buf * 3 + 0) * TILE_SZ;
        float* Kb = sm + OFF_T + (buf * 3 + 1) * TILE_SZ;
        float* Vb = sm + OFF_T + (buf * 3 + 2) * TILE_SZ;
        for (int i = t; i < 1024; i += 256) {
            int n = i >> 4, d4 = (i & 15) * 4;
            size_t gidx = base + (size_t)n * 1024 + d4;
            cp16(&Qb[n * P64 + d4], &g_q[gidx]);
            cp16(&Kb[n * P64 + d4], &g_k[gidx]);
            cp16(&Vb[n * P64 + d4], &g_v[gidx]);
        }
    };

    prefetch(0, 0); cp_commit();
    __syncthreads();   // also covers Wi/Wo_ init

    for (int c = 0; c < NCHUNK_; c++) {
        const int buf = c & 1;
        const float* Q  = sm + OFF_T + (buf * 3 + 0) * TILE_SZ;
        const float* Kt = sm + OFF_T + (buf * 3 + 1) * TILE_SZ;
        const float* V  = sm + OFF_T + (buf * 3 + 2) * TILE_SZ;

        const size_t base = ((size_t)b * L_ + (size_t)c * 64) * 1024 + h * 64;
        const int lb = (b * 64 + c) * 64;
        const float li  = g_lrwd[lb + h];
        const float lo  = g_lrwd[lb + 16 + h];
        const float wdi = g_lrwd[lb + 32 + h];
        const float wdo = g_lrwd[lb + 48 + h];

        // ---- P1: wait prefetch of this chunk; issue prefetch of next
        cp_wait<0>();
        __syncthreads();
        if (c + 1 < NCHUNK_) { prefetch(c + 1, buf ^ 1); cp_commit(); }

        // ---- P2 (mma): logits. warps 0-3: Pq = Q@Wi^T, warps 4-7: Pk = K@Wi^T
        {
            const float* src = (w < 4) ? Q  : Kt;
            float*       dst = (w < 4) ? Pq : Pk;
            const int m0 = 16 * (w & 3);
            float C_[4][4];
#pragma unroll
            for (int j = 0; j < 4; j++)
#pragma unroll
                for (int x2 = 0; x2 < 4; x2++) C_[j][x2] = 0.f;
#pragma unroll
            for (int kk = 0; kk < 8; kk++) {
                const int k0 = kk * 8;
                uint32_t a0 = __float_as_uint(src[(m0 + g)     * P64 + k0 + t4]);
                uint32_t a1 = __float_as_uint(src[(m0 + g + 8) * P64 + k0 + t4]);
                uint32_t a2 = __float_as_uint(src[(m0 + g)     * P64 + k0 + t4 + 4]);
                uint32_t a3 = __float_as_uint(src[(m0 + g + 8) * P64 + k0 + t4 + 4]);
#pragma unroll
                for (int j = 0; j < 4; j++) {
                    uint32_t b0 = f2t(Wi[(8 * j + g) * P64 + k0 + t4]);
                    uint32_t b1 = f2t(Wi[(8 * j + g) * P64 + k0 + t4 + 4]);
                    mma_tf32(C_[j], a0, a1, a2, a3, b0, b1);
                }
            }
#pragma unroll
            for (int j = 0; j < 4; j++) {
                dst[(m0 + g)     * P32 + 8 * j + 2 * t4]     = C_[j][0];
                dst[(m0 + g)     * P32 + 8 * j + 2 * t4 + 1] = C_[j][1];
                dst[(m0 + g + 8) * P32 + 8 * j + 2 * t4]     = C_[j][2];
                dst[(m0 + g + 8) * P32 + 8 * j + 2 * t4 + 1] = C_[j][3];
            }
        }
        __syncthreads();

        // ---- P3: merged softmax over n for both Pq and Pk (per column D)
        {
            float* Pp = (task < 32) ? Pq : Pk;
            const int D = task & 31;
            float m = -1e30f;
#pragma unroll
            for (int n = sg * 16; n < sg * 16 + 16; n++) m = fmaxf(m, Pp[n * P32 + D]);
            red[sg * 64 + task] = m;
            __syncthreads();
            if (t < 64)
                cs[t] = fmaxf(fmaxf(red[t], red[64 + t]), fmaxf(red[128 + t], red[192 + t]));
            __syncthreads();
            float mm = cs[task], s = 0.f;
#pragma unroll
            for (int n = sg * 16; n < sg * 16 + 16; n++) {
                float e = __expf(Pp[n * P32 + D] - mm);
                Pp[n * P32 + D] = e;
                s += e;
            }
            red[sg * 64 + task] = s;
            __syncthreads();
            if (t < 64) cs[t] = 1.f / (red[t] + red[64 + t] + red[128 + t] + red[192 + t]);
            __syncthreads();
            float inv = cs[task];
#pragma unroll
            for (int n = sg * 16; n < sg * 16 + 16; n++) Pp[n * P32 + D] *= inv;
        }
        __syncthreads();

        // ---- P4a (mma): op[n][d] = sum_Dl Pq[n][Dl] * Wo_[Dl][d]
        {
            const int m0 = 16 * (w & 3);
            const int nb = 32 * (w >> 2);
            float Co[4][4];
#pragma unroll
            for (int j = 0; j < 4; j++)
#pragma unroll
                for (int x2 = 0; x2 < 4; x2++) Co[j][x2] = 0.f;
#pragma unroll
            for (int kk = 0; kk < 4; kk++) {
                const int k0 = kk * 8;
                uint32_t a0 = f2t(Pq[(m0 + g)     * P32 + k0 + t4]);
                uint32_t a1 = f2t(Pq[(m0 + g + 8) * P32 + k0 + t4]);
                uint32_t a2 = f2t(Pq[(m0 + g)     * P32 + k0 + t4 + 4]);
                uint32_t a3 = f2t(Pq[(m0 + g + 8) * P32 + k0 + t4 + 4]);
#pragma unroll
                for (int j = 0; j < 4; j++) {
                    const int dcol = nb + 8 * j + g;
                    uint32_t b0 = f2t(Wo_[(k0 + t4)     * P64 + dcol]);
                    uint32_t b1 = f2t(Wo_[(k0 + t4 + 4) * P64 + dcol]);
                    mma_tf32(Co[j], a0, a1, a2, a3, b0, b1);
                }
            }
#pragma unroll
            for (int j = 0; j < 4; j++) {
                const int col = nb + 8 * j + 2 * t4;
                op[(m0 + g)     * P64 + col]     = Co[j][0];
                op[(m0 + g)     * P64 + col + 1] = Co[j][1];
                op[(m0 + g + 8) * P64 + col]     = Co[j][2];
                op[(m0 + g + 8) * P64 + col + 1] = Co[j][3];
            }
        }

        // ---- P4b (mma): Am[n][Dl] = sum_d V[n][d]*Wo_[Dl][d]
        {
            const int m0 = 16 * (w & 3);
            const int nb = (w >> 2) * 16;
            float Ca[2][4];
#pragma unroll
            for (int j = 0; j < 2; j++)
#pragma unroll
                for (int x2 = 0; x2 < 4; x2++) Ca[j][x2] = 0.f;
#pragma unroll
            for (int kk = 0; kk < 8; kk++) {
                const int k0 = kk * 8;
                uint32_t a0 = __float_as_uint(V[(m0 + g)     * P64 + k0 + t4]);
                uint32_t a1 = __float_as_uint(V[(m0 + g + 8) * P64 + k0 + t4]);
                uint32_t a2 = __float_as_uint(V[(m0 + g)     * P64 + k0 + t4 + 4]);
                uint32_t a3 = __float_as_uint(V[(m0 + g + 8) * P64 + k0 + t4 + 4]);
#pragma unroll
                for (int j = 0; j < 2; j++) {
                    const int Dl = nb + 8 * j + g;
                    uint32_t b0 = f2t(Wo_[Dl * P64 + k0 + t4]);
                    uint32_t b1 = f2t(Wo_[Dl * P64 + k0 + t4 + 4]);
                    mma_tf32(Ca[j], a0, a1, a2, a3, b0, b1);
                }
            }
#pragma unroll
            for (int j = 0; j < 2; j++) {
                Am[(m0 + g)     * P32 + nb + 8 * j + 2 * t4]     = Ca[j][0];
                Am[(m0 + g)     * P32 + nb + 8 * j + 2 * t4 + 1] = Ca[j][1];
                Am[(m0 + g + 8) * P32 + nb + 8 * j + 2 * t4]     = Ca[j][2];
                Am[(m0 + g + 8) * P32 + nb + 8 * j + 2 * t4 + 1] = Ca[j][3];
            }
        }
        __syncthreads();
        CLUSTER_SYNC();

        // ---- P5: o = op_self + op_peer (tf32 fused into store); sp
        for (int i = t; i < 2048; i += 256) {
            int n = (int)rank * 32 + (i >> 6), d = i & 63;
            float v2 = op[n * P64 + d] + ld_dsmem(op_peer + (uint32_t)(n * P64 + d) * 4u);
            g_o[base + (size_t)n * 1024 + d] = cvt_tf32f(v2);
        }
        if (t < 64) {
            float s = 0.f;
#pragma unroll 8
            for (int Dl = 0; Dl < 32; Dl++) s += Pk[t * P32 + Dl] * Am[t * P32 + Dl];
            sp[t] = s;
        }
        __syncthreads();
        CLUSTER_SYNC();

        // ---- P6: total s
        if (t < 64) ss[t] = sp[t] + ld_dsmem(sp_peer + (uint32_t)t * 4u);
        __syncthreads();

        // ---- P7 (mma): grads + state update (A,B both transposed reads)
        {
            const int m0 = 16 * (w & 1);
            const int nb = (w >> 1) * 16;
            float Cgi[2][4], Cgo[2][4];
#pragma unroll
            for (int j = 0; j < 2; j++)
#pragma unroll
                for (int x2 = 0; x2 < 4; x2++) { Cgi[j][x2] = 0.f; Cgo[j][x2] = 0.f; }
#pragma unroll
            for (int kk = 0; kk < 8; kk++) {
                const int ka = kk * 8 + t4;
                const int kb2 = ka + 4;
                float ssa = ss[ka], ssb = ss[kb2];
                float pk0 = Pk[ka  * P32 + m0 + g],     am0 = Am[ka  * P32 + m0 + g];
                float pk1 = Pk[ka  * P32 + m0 + g + 8], am1 = Am[ka  * P32 + m0 + g + 8];
                float pk2 = Pk[kb2 * P32 + m0 + g],     am2 = Am[kb2 * P32 + m0 + g];
                float pk3 = Pk[kb2 * P32 + m0 + g + 8], am3 = Am[kb2 * P32 + m0 + g + 8];
                uint32_t gz0 = f2t(-pk0 * (am0 - ssa));
                uint32_t gz1 = f2t(-pk1 * (am1 - ssa));
                uint32_t gz2 = f2t(-pk2 * (am2 - ssb));
                uint32_t gz3 = f2t(-pk3 * (am3 - ssb));
                uint32_t p0 = f2t(pk0), p1 = f2t(pk1), p2 = f2t(pk2), p3 = f2t(pk3);
#pragma unroll
                for (int j = 0; j < 2; j++) {
                    const int dcol = nb + 8 * j + g;
                    uint32_t bk0 = __float_as_uint(Kt[ka  * P64 + dcol]);
                    uint32_t bk1 = __float_as_uint(Kt[kb2 * P64 + dcol]);
                    uint32_t bv0 = __float_as_uint(V [ka  * P64 + dcol]);
                    uint32_t bv1 = __float_as_uint(V [kb2 * P64 + dcol]);
                    mma_tf32(Cgi[j], gz0, gz1, gz2, gz3, bk0, bk1);
                    mma_tf32(Cgo[j], p0,  p1,  p2,  p3,  bv0, bv1);
                }
            }
#pragma unroll
            for (int j = 0; j < 2; j++) {
                const int col = nb + 8 * j + 2 * t4;
                const int i0 = (m0 + g)     * P64 + col;
                const int i1 = (m0 + g + 8) * P64 + col;
                Wi [i0]     = wdi * Wi [i0]     - li * Cgi[j][0];
                Wi [i0 + 1] = wdi * Wi [i0 + 1] - li * Cgi[j][1];
                Wi [i1]     = wdi * Wi [i1]     - li * Cgi[j][2];
                Wi [i1 + 1] = wdi * Wi [i1 + 1] - li * Cgi[j][3];
                Wo_[i0]     = wdo * Wo_[i0]     + lo * Cgo[j][0];
                Wo_[i0 + 1] = wdo * Wo_[i0 + 1] + lo * Cgo[j][1];
                Wo_[i1]     = wdo * Wo_[i1]     + lo * Cgo[j][2];
                Wo_[i1 + 1] = wdo * Wo_[i1 + 1] + lo * Cgo[j][3];
            }
        }
        __syncthreads();
    }
    CLUSTER_SYNC();   // keep smem alive for peer's in-flight DSMEM reads
}

// ---------------------------------------------------------------------------
// Launch
// ---------------------------------------------------------------------------
extern "C" void kernel_launch(void* const* d_in, const int* in_sizes, int n_in,
                              void* d_out, int out_size)
{
    (void)in_sizes; (void)n_in; (void)out_size;
    const float* x     = (const float*)d_in[0];
    const float* Wq    = (const float*)d_in[1];
    const float* Wk    = (const float*)d_in[2];
    const float* Wv    = (const float*)d_in[3];
    const float* Wlr   = (const float*)d_in[4];
    const float* Wbeta = (const float*)d_in[5];
    const float* Wo    = (const float*)d_in[6];
    const float* Win0  = (const float*)d_in[7];
    const float* Wout0 = (const float*)d_in[8];
    float* out = (float*)d_out;

    float *q, *k, *v, *om, *xt, *wt;
    cudaGetSymbolAddress((void**)&q,  g_q);
    cudaGetSymbolAddress((void**)&k,  g_k);
    cudaGetSymbolAddress((void**)&v,  g_v);
    cudaGetSymbolAddress((void**)&om, g_o);
    cudaGetSymbolAddress((void**)&xt, g_xt);
    cudaGetSymbolAddress((void**)&wt, g_wt);

    cudaFuncSetAttribute(gemm_tf32p<0, 0>, cudaFuncAttributeMaxDynamicSharedMemorySize, GEMM_SMEM_BYTES);
    cudaFuncSetAttribute(gemm_tf32p<0, 1>, cudaFuncAttributeMaxDynamicSharedMemorySize, GEMM_SMEM_BYTES);
    cudaFuncSetAttribute(gemm_tf32p<1, 1>, cudaFuncAttributeMaxDynamicSharedMemorySize, GEMM_SMEM_BYTES);
    cudaFuncSetAttribute(scan_kernel,      cudaFuncAttributeMaxDynamicSharedMemorySize,
                         SCAN_SMEM_FLOATS * (int)sizeof(float));

    const int NW4 = (1024 * 1024) / 4;
    // lrwd first: streams x once, emits tf32(x) into g_xt as a side product
    lrwd_kernel<<<B_ * NCHUNK_, 256>>>(x, Wlr, Wbeta, xt);
    cvt_kernel<<<(NW4 + 255) / 256, 256>>>(Wq, wt + 0u * 1024u * 1024u, NW4);
    cvt_kernel<<<(NW4 + 255) / 256, 256>>>(Wk, wt + 1u * 1024u * 1024u, NW4);
    cvt_kernel<<<(NW4 + 255) / 256, 256>>>(Wv, wt + 2u * 1024u * 1024u, NW4);
    cvt_kernel<<<(NW4 + 255) / 256, 256>>>(Wo, wt + 3u * 1024u * 1024u, NW4);

    dim3 grid(1024 / 128, M_ / 128);
    gemm_tf32p<1, 1><<<grid, 256, GEMM_SMEM_BYTES>>>(xt, wt + 0u * 1024u * 1024u, q, M_, 1024, 1024);
    gemm_tf32p<1, 1><<<grid, 256, GEMM_SMEM_BYTES>>>(xt, wt + 1u * 1024u * 1024u, k, M_, 1024, 1024);
    gemm_tf32p<0, 1><<<grid, 256, GEMM_SMEM_BYTES>>>(xt, wt + 2u * 1024u * 1024u, v, M_, 1024, 1024);

    const int smem_bytes = SCAN_SMEM_FLOATS * (int)sizeof(float);
    scan_kernel<<<128, 256, smem_bytes>>>(Win0, Wout0);

    // g_o holds tf32 bits — final GEMM reads it directly, stores plain fp32
    gemm_tf32p<0, 0><<<grid, 256, GEMM_SMEM_BYTES>>>(om, wt + 3u * 1024u * 1024u, out, M_, 1024, 1024);
}

// round 15
// speedup vs baseline: 1.5013x; 1.0356x over previous
#include <cuda_runtime.h>
#include <cstdint>

// Problem constants
#define B_ 4
#define L_ 4096
#define DIM_ 1024
#define H_ 16
#define NCHUNK_ 64
#define CHUNK_ 64
#define M_ (B_ * L_)          // 16384

// ---------------------------------------------------------------------------
// Device scratch (allocation-free contract: __device__ globals)
// ---------------------------------------------------------------------------
__device__ float g_q[(size_t)B_ * L_ * 1024];   // tf32 bits (projection epilogue cvt)
__device__ float g_k[(size_t)B_ * L_ * 1024];   // tf32 bits
__device__ float g_v[(size_t)B_ * L_ * 1024];   // tf32 bits
__device__ float g_o[(size_t)B_ * L_ * 1024];   // tf32 bits (scan P5 cvt)
__device__ float g_xt[(size_t)B_ * L_ * 1024];  // tf32(x), produced by lrwd_kernel
__device__ float g_wt[4u * 1024u * 1024u];      // tf32(Wq,Wk,Wv,Wo)
__device__ float g_lrwd[B_ * NCHUNK_ * 64];

// ---------------------------------------------------------------------------
// PTX helpers
// ---------------------------------------------------------------------------
__device__ __forceinline__ float cvt_tf32f(float f) {
    uint32_t u;
    asm("cvt.rna.tf32.f32 %0, %1;" : "=r"(u) : "f"(f));
    return __uint_as_float(u);
}
__device__ __forceinline__ uint32_t f2t(float f) {
    uint32_t u;
    asm("cvt.rna.tf32.f32 %0, %1;" : "=r"(u) : "f"(f));
    return u;
}

__device__ __forceinline__ void cp16(void* smem, const void* gmem) {
    uint32_t s = (uint32_t)__cvta_generic_to_shared(smem);
    asm volatile("cp.async.cg.shared.global [%0], [%1], 16;" :: "r"(s), "l"(gmem));
}
__device__ __forceinline__ void cp_commit() {
    asm volatile("cp.async.commit_group;");
}
template <int N>
__device__ __forceinline__ void cp_wait() {
    asm volatile("cp.async.wait_group %0;" :: "n"(N));
}

__device__ __forceinline__ void mma_tf32(float c[4],
                                         uint32_t a0, uint32_t a1, uint32_t a2, uint32_t a3,
                                         uint32_t b0, uint32_t b1) {
    asm volatile(
        "mma.sync.aligned.m16n8k8.row.col.f32.tf32.tf32.f32 "
        "{%0,%1,%2,%3}, {%4,%5,%6,%7}, {%8,%9}, {%0,%1,%2,%3};"
        : "+f"(c[0]), "+f"(c[1]), "+f"(c[2]), "+f"(c[3])
        : "r"(a0), "r"(a1), "r"(a2), "r"(a3), "r"(b0), "r"(b1));
}

__device__ __forceinline__ uint32_t mapa_u32(uint32_t addr, uint32_t rank) {
    uint32_t r;
    asm("mapa.shared::cluster.u32 %0, %1, %2;" : "=r"(r) : "r"(addr), "r"(rank));
    return r;
}
__device__ __forceinline__ float ld_dsmem(uint32_t addr) {
    float v;
    asm volatile("ld.shared::cluster.f32 %0, [%1];" : "=f"(v) : "r"(addr));
    return v;
}
#define CLUSTER_SYNC() do { \
    asm volatile("barrier.cluster.arrive.aligned;" ::: "memory"); \
    asm volatile("barrier.cluster.wait.aligned;" ::: "memory"); } while (0)

// ---------------------------------------------------------------------------
// tf32 pre-convert (weights only)
// ---------------------------------------------------------------------------
__global__ __launch_bounds__(256)
void cvt_kernel(const float* __restrict__ src, float* __restrict__ dst, int n4)
{
    int i = blockIdx.x * 256 + threadIdx.x;
    if (i < n4) {
        float4 v = ((const float4*)src)[i];
        v.x = cvt_tf32f(v.x); v.y = cvt_tf32f(v.y);
        v.z = cvt_tf32f(v.z); v.w = cvt_tf32f(v.w);
        ((float4*)dst)[i] = v;
    }
}

// ---------------------------------------------------------------------------
// TF32 tensor-core GEMM (NT), pre-converted inputs, 3-stage cp.async.
// CVT=1: store tf32 bit patterns (for scan-consumed q/k/v).
// Single barrier per k-iteration (bottom sync proven redundant: next write
// to buf kb%3 is issued only after iteration kb+1's top sync).
// ---------------------------------------------------------------------------
#define GEMM_SMEM_BYTES (3 * 2 * 128 * 20 * 4)

template <int ACT, int CVT>
__global__ __launch_bounds__(256)
void gemm_tf32p(const float* __restrict__ A, const float* __restrict__ W,
                float* __restrict__ C, int M, int N, int K)
{
    extern __shared__ __align__(16) float gsm[];
    float (*As)[128][20] = (float (*)[128][20])gsm;
    float (*Bs)[128][20] = (float (*)[128][20])(gsm + 3 * 128 * 20);

    const int t    = threadIdx.x;
    const int bm   = blockIdx.y * 128;
    const int bn   = blockIdx.x * 128;
    const int w    = t >> 5;
    const int lane = t & 31;
    const int wm   = (w >> 2) * 64;
    const int wn   = (w & 3) * 32;
    const int g    = lane >> 2;
    const int t4   = lane & 3;

    float acc[4][4][4];
#pragma unroll
    for (int mt = 0; mt < 4; mt++)
#pragma unroll
        for (int nt = 0; nt < 4; nt++)
#pragma unroll
            for (int c = 0; c < 4; c++) acc[mt][nt][c] = 0.f;

    const int KT = K >> 4;

    auto load_stage = [&](int kb, int buf) {
        const int k0 = kb * 16;
#pragma unroll
        for (int s = 0; s < 2; s++) {
            int j   = t + s * 256;
            int row = j >> 2;
            int c4  = (j & 3) * 4;
            cp16(&As[buf][row][c4], A + (size_t)(bm + row) * K + k0 + c4);
            cp16(&Bs[buf][row][c4], W + (size_t)(bn + row) * K + k0 + c4);
        }
    };

    load_stage(0, 0); cp_commit();
    load_stage(1, 1); cp_commit();

    for (int kb = 0; kb < KT; kb++) {
        cp_wait<1>();
        __syncthreads();
        if (kb + 2 < KT) { load_stage(kb + 2, (kb + 2) % 3); cp_commit(); }
        else             { cp_commit(); }   // empty group keeps wait<1> semantics
        const int buf = kb % 3;

#pragma unroll
        for (int ks = 0; ks < 2; ks++) {
            const int k0 = ks * 8;
            uint32_t bf[4][2];
#pragma unroll
            for (int nt = 0; nt < 4; nt++) {
                bf[nt][0] = __float_as_uint(Bs[buf][wn + nt * 8 + g][k0 + t4]);
                bf[nt][1] = __float_as_uint(Bs[buf][wn + nt * 8 + g][k0 + t4 + 4]);
            }
#pragma unroll
            for (int mt = 0; mt < 4; mt++) {
                uint32_t a0 = __float_as_uint(As[buf][wm + mt * 16 + g][k0 + t4]);
                uint32_t a1 = __float_as_uint(As[buf][wm + mt * 16 + g + 8][k0 + t4]);
                uint32_t a2 = __float_as_uint(As[buf][wm + mt * 16 + g][k0 + t4 + 4]);
                uint32_t a3 = __float_as_uint(As[buf][wm + mt * 16 + g + 8][k0 + t4 + 4]);
#pragma unroll
                for (int nt = 0; nt < 4; nt++)
                    mma_tf32(acc[mt][nt], a0, a1, a2, a3, bf[nt][0], bf[nt][1]);
            }
        }
        // no bottom __syncthreads: buffer kb%3 is next written at iter kb+1,
        // strictly after that iteration's top __syncthreads.
    }

#pragma unroll
    for (int mt = 0; mt < 4; mt++) {
#pragma unroll
        for (int nt = 0; nt < 4; nt++) {
            int m = bm + wm + mt * 16 + g;
            int n = bn + wn + nt * 8 + t4 * 2;
            float2 v0 = make_float2(acc[mt][nt][0], acc[mt][nt][1]);
            float2 v1 = make_float2(acc[mt][nt][2], acc[mt][nt][3]);
            if (ACT == 1) {
                v0.x = v0.x / (1.f + __expf(-v0.x));
                v0.y = v0.y / (1.f + __expf(-v0.y));
                v1.x = v1.x / (1.f + __expf(-v1.x));
                v1.y = v1.y / (1.f + __expf(-v1.y));
            }
            if (CVT == 1) {
                v0.x = cvt_tf32f(v0.x); v0.y = cvt_tf32f(v0.y);
                v1.x = cvt_tf32f(v1.x); v1.y = cvt_tf32f(v1.y);
            }
            *(float2*)&C[(size_t)m * N + n]       = v0;
            *(float2*)&C[(size_t)(m + 8) * N + n] = v1;
        }
    }
}

// ---------------------------------------------------------------------------
// lr/wd chunk means + fused x -> tf32 conversion
// ---------------------------------------------------------------------------
__global__ __launch_bounds__(256, 2)
void lrwd_kernel(const float* __restrict__ x,
                 const float* __restrict__ Wlr,
                 const float* __restrict__ Wbeta,
                 float* __restrict__ xt)
{
    __shared__ float xs[64][65];
    __shared__ float ws[64][65];
    __shared__ float red2[64 * 16];

    const int bc = blockIdx.x;
    const size_t xb = (size_t)bc * 64 * 1024;
    const int t  = threadIdx.x;
    const int r0 = t >> 4;
    const int c0 = t & 15;

    float acc[4][4];
#pragma unroll
    for (int i = 0; i < 4; i++)
#pragma unroll
        for (int j = 0; j < 4; j++) acc[i][j] = 0.f;

    for (int k0 = 0; k0 < 1024; k0 += 64) {
        for (int i = t; i < 4096; i += 256) {
            int n = i >> 6, d = i & 63;
            size_t gi = xb + (size_t)n * 1024 + k0 + d;
            float xv = x[gi];
            xs[n][d] = xv;
            xt[gi]   = cvt_tf32f(xv);
            ws[n][d] = (n < 32) ? Wlr[n * 1024 + k0 + d]
                                : Wbeta[(n - 32) * 1024 + k0 + d];
        }
        __syncthreads();
#pragma unroll 4
        for (int k = 0; k < 64; k++) {
            float a[4], b[4];
#pragma unroll
            for (int ii = 0; ii < 4; ii++) a[ii] = xs[r0 + 16 * ii][k];
#pragma unroll
            for (int jj = 0; jj < 4; jj++) b[jj] = ws[c0 + 16 * jj][k];
#pragma unroll
            for (int ii = 0; ii < 4; ii++)
#pragma unroll
                for (int jj = 0; jj < 4; jj++) acc[ii][jj] += a[ii] * b[jj];
        }
        __syncthreads();
    }

#pragma unroll
    for (int jj = 0; jj < 4; jj++) {
        int j = c0 + 16 * jj;
        float scale = (j < 32) ? 0.001f : 0.9f;
        float p = 0.f;
#pragma unroll
        for (int ii = 0; ii < 4; ii++)
            p += scale / (1.f + __expf(-acc[ii][jj]));
        red2[j * 16 + r0] = p;
    }
    __syncthreads();
    if (t < 64) {
        float s = 0.f;
        for (int r = 0; r < 16; r++) s += red2[t * 16 + r];
        g_lrwd[bc * 64 + t] = s * (1.f / 64.f);
    }
}

// ---------------------------------------------------------------------------
// Cluster-2 persistent scan: all-mma gemmlets, cp.async double-buffered
// q/k/v prefetch, no-max softmax, ONE cluster sync per chunk with
// parity-double-buffered op/sp exchange buffers.
// ---------------------------------------------------------------------------
#define P64 68
#define P32 36

#define OFF_WI   0                           // [32][68]
#define OFF_WO   (32 * P64)                  // 2176
#define OFF_T    (2 * 32 * P64)              // 4352: tiles [2 bufs][3 tiles][64][68]
#define TILE_SZ  (64 * P64)                  // 4352
#define OFF_PQ   (OFF_T + 6 * TILE_SZ)       // 30464 [64][36]
#define OFF_PK   (OFF_PQ + 64 * P32)         // 32768
#define OFF_AM   (OFF_PK + 64 * P32)         // 35072
#define OFF_OP   (OFF_AM + 64 * P32)         // 37376 [2][64][68] parity buffers
#define OFF_SP   (OFF_OP + 2 * TILE_SZ)      // 46080 [2][64]
#define OFF_SS   (OFF_SP + 128)              // 46208
#define OFF_RED  (OFF_SS + 64)               // 46272 [4][64]
#define OFF_CS   (OFF_RED + 256)             // 46528
#define SCAN_SMEM_FLOATS (OFF_CS + 64)       // 46592 -> 186368 bytes

__global__ __launch_bounds__(256, 1) __cluster_dims__(2, 1, 1)
void scan_kernel(const float* __restrict__ Win0, const float* __restrict__ Wout0)
{
    extern __shared__ float sm[];
    float* Wi  = sm + OFF_WI;
    float* Wo_ = sm + OFF_WO;
    float* Pq  = sm + OFF_PQ;
    float* Pk  = sm + OFF_PK;
    float* Am  = sm + OFF_AM;
    float* ss  = sm + OFF_SS;
    float* red = sm + OFF_RED;
    float* cs  = sm + OFF_CS;

    const int pair = blockIdx.x >> 1;
    const uint32_t rank = blockIdx.x & 1;
    const int b = pair >> 4;
    const int h = pair & 15;
    const int t = threadIdx.x;

    const int w    = t >> 5;
    const int lane = t & 31;
    const int g    = lane >> 2;
    const int t4   = lane & 3;
    const int task = t & 63, sg = t >> 6;

    const uint32_t op_peer0 = mapa_u32((uint32_t)__cvta_generic_to_shared(sm + OFF_OP), rank ^ 1u);
    const uint32_t sp_peer0 = mapa_u32((uint32_t)__cvta_generic_to_shared(sm + OFF_SP), rank ^ 1u);

    // init state halves (pitch 68)
    for (int i = t; i < 2048; i += 256) {
        int Dl = i >> 6, d = i & 63;
        int Dg = (int)rank * 32 + Dl;
        Wi [Dl * P64 + d] = Win0 [Dg * 1024 + h * 64 + d];
        Wo_[Dl * P64 + d] = Wout0[Dg * 1024 + h * 64 + d];
    }

    // prefetch q/k/v for a chunk into tile buffer `buf`
    auto prefetch = [&](int c, int buf) {
        const size_t base = ((size_t)b * L_ + (size_t)c * 64) * 1024 + h * 64;
        float* Qb = sm + OFF_T + (buf * 3 + 0) * TILE_SZ;
        float* Kb = sm + OFF_T + (buf * 3 + 1) * TILE_SZ;
        float* Vb = sm + OFF_T + (buf * 3 + 2) * TILE_SZ;
        for (int i = t; i < 1024; i += 256) {
            int n = i >> 4, d4 = (i & 15) * 4;
            size_t gidx = base + (size_t)n * 1024 + d4;
            cp16(&Qb[n * P64 + d4], &g_q[gidx]);
            cp16(&Kb[n * P64 + d4], &g_k[gidx]);
            cp16(&Vb[n * P64 + d4], &g_v[gidx]);
        }
    };

    prefetch(0, 0); cp_commit();
    __syncthreads();   // also covers Wi/Wo_ init

    for (int c = 0; c < NCHUNK_; c++) {
        const int buf = c & 1;
        const float* Q  = sm + OFF_T + (buf * 3 + 0) * TILE_SZ;
        const float* Kt = sm + OFF_T + (buf * 3 + 1) * TILE_SZ;
        const float* V  = sm + OFF_T + (buf * 3 + 2) * TILE_SZ;
        float* op = sm + OFF_OP + buf * TILE_SZ;       // parity exchange buffer
        float* sp = sm + OFF_SP + buf * 64;
        const uint32_t op_peer = op_peer0 + (uint32_t)(buf * TILE_SZ) * 4u;
        const uint32_t sp_peer = sp_peer0 + (uint32_t)(buf * 64) * 4u;

        const size_t base = ((size_t)b * L_ + (size_t)c * 64) * 1024 + h * 64;
        const int lb = (b * 64 + c) * 64;
        const float li  = g_lrwd[lb + h];
        const float lo  = g_lrwd[lb + 16 + h];
        const float wdi = g_lrwd[lb + 32 + h];
        const float wdo = g_lrwd[lb + 48 + h];

        // ---- P1: wait prefetch of this chunk; issue prefetch of next
        cp_wait<0>();
        __syncthreads();
        if (c + 1 < NCHUNK_) { prefetch(c + 1, buf ^ 1); cp_commit(); }

        // ---- P2 (mma): logits. warps 0-3: Pq = Q@Wi^T, warps 4-7: Pk = K@Wi^T
        {
            const float* src = (w < 4) ? Q  : Kt;
            float*       dst = (w < 4) ? Pq : Pk;
            const int m0 = 16 * (w & 3);
            float C_[4][4];
#pragma unroll
            for (int j = 0; j < 4; j++)
#pragma unroll
                for (int x2 = 0; x2 < 4; x2++) C_[j][x2] = 0.f;
#pragma unroll
            for (int kk = 0; kk < 8; kk++) {
                const int k0 = kk * 8;
                uint32_t a0 = __float_as_uint(src[(m0 + g)     * P64 + k0 + t4]);
                uint32_t a1 = __float_as_uint(src[(m0 + g + 8) * P64 + k0 + t4]);
                uint32_t a2 = __float_as_uint(src[(m0 + g)     * P64 + k0 + t4 + 4]);
                uint32_t a3 = __float_as_uint(src[(m0 + g + 8) * P64 + k0 + t4 + 4]);
#pragma unroll
                for (int j = 0; j < 4; j++) {
                    uint32_t b0 = f2t(Wi[(8 * j + g) * P64 + k0 + t4]);
                    uint32_t b1 = f2t(Wi[(8 * j + g) * P64 + k0 + t4 + 4]);
                    mma_tf32(C_[j], a0, a1, a2, a3, b0, b1);
                }
            }
#pragma unroll
            for (int j = 0; j < 4; j++) {
                dst[(m0 + g)     * P32 + 8 * j + 2 * t4]     = C_[j][0];
                dst[(m0 + g)     * P32 + 8 * j + 2 * t4 + 1] = C_[j][1];
                dst[(m0 + g + 8) * P32 + 8 * j + 2 * t4]     = C_[j][2];
                dst[(m0 + g + 8) * P32 + 8 * j + 2 * t4 + 1] = C_[j][3];
            }
        }
        __syncthreads();

        // ---- P3: softmax without max-subtraction (logits bounded |.|<~6)
        {
            float* Pp = (task < 32) ? Pq : Pk;
            const int D = task & 31;
            float s = 0.f;
#pragma unroll
            for (int n = sg * 16; n < sg * 16 + 16; n++) {
                float e = __expf(Pp[n * P32 + D]);
                Pp[n * P32 + D] = e;
                s += e;
            }
            red[sg * 64 + task] = s;
            __syncthreads();
            if (t < 64) cs[t] = 1.f / (red[t] + red[64 + t] + red[128 + t] + red[192 + t]);
            __syncthreads();
            float inv = cs[task];
#pragma unroll
            for (int n = sg * 16; n < sg * 16 + 16; n++) Pp[n * P32 + D] *= inv;
        }
        __syncthreads();

        // ---- P4a (mma): op[n][d] = sum_Dl Pq[n][Dl] * Wo_[Dl][d]
        {
            const int m0 = 16 * (w & 3);
            const int nb = 32 * (w >> 2);
            float Co[4][4];
#pragma unroll
            for (int j = 0; j < 4; j++)
#pragma unroll
                for (int x2 = 0; x2 < 4; x2++) Co[j][x2] = 0.f;
#pragma unroll
            for (int kk = 0; kk < 4; kk++) {
                const int k0 = kk * 8;
                uint32_t a0 = f2t(Pq[(m0 + g)     * P32 + k0 + t4]);
                uint32_t a1 = f2t(Pq[(m0 + g + 8) * P32 + k0 + t4]);
                uint32_t a2 = f2t(Pq[(m0 + g)     * P32 + k0 + t4 + 4]);
                uint32_t a3 = f2t(Pq[(m0 + g + 8) * P32 + k0 + t4 + 4]);
#pragma unroll
                for (int j = 0; j < 4; j++) {
                    const int dcol = nb + 8 * j + g;
                    uint32_t b0 = f2t(Wo_[(k0 + t4)     * P64 + dcol]);
                    uint32_t b1 = f2t(Wo_[(k0 + t4 + 4) * P64 + dcol]);
                    mma_tf32(Co[j], a0, a1, a2, a3, b0, b1);
                }
            }
#pragma unroll
            for (int j = 0; j < 4; j++) {
                const int col = nb + 8 * j + 2 * t4;
                op[(m0 + g)     * P64 + col]     = Co[j][0];
                op[(m0 + g)     * P64 + col + 1] = Co[j][1];
                op[(m0 + g + 8) * P64 + col]     = Co[j][2];
                op[(m0 + g + 8) * P64 + col + 1] = Co[j][3];
            }
        }

        // ---- P4b (mma): Am[n][Dl] = sum_d V[n][d]*Wo_[Dl][d]
        {
            const int m0 = 16 * (w & 3);
            const int nb = (w >> 2) * 16;
            float Ca[2][4];
#pragma unroll
            for (int j = 0; j < 2; j++)
#pragma unroll
                for (int x2 = 0; x2 < 4; x2++) Ca[j][x2] = 0.f;
#pragma unroll
            for (int kk = 0; kk < 8; kk++) {
                const int k0 = kk * 8;
                uint32_t a0 = __float_as_uint(V[(m0 + g)     * P64 + k0 + t4]);
                uint32_t a1 = __float_as_uint(V[(m0 + g + 8) * P64 + k0 + t4]);
                uint32_t a2 = __float_as_uint(V[(m0 + g)     * P64 + k0 + t4 + 4]);
                uint32_t a3 = __float_as_uint(V[(m0 + g + 8) * P64 + k0 + t4 + 4]);
#pragma unroll
                for (int j = 0; j < 2; j++) {
                    const int Dl = nb + 8 * j + g;
                    uint32_t b0 = f2t(Wo_[Dl * P64 + k0 + t4]);
                    uint32_t b1 = f2t(Wo_[Dl * P64 + k0 + t4 + 4]);
                    mma_tf32(Ca[j], a0, a1, a2, a3, b0, b1);
                }
            }
#pragma unroll
            for (int j = 0; j < 2; j++) {
                Am[(m0 + g)     * P32 + nb + 8 * j + 2 * t4]     = Ca[j][0];
                Am[(m0 + g)     * P32 + nb + 8 * j + 2 * t4 + 1] = Ca[j][1];
                Am[(m0 + g + 8) * P32 + nb + 8 * j + 2 * t4]     = Ca[j][2];
                Am[(m0 + g + 8) * P32 + nb + 8 * j + 2 * t4 + 1] = Ca[j][3];
            }
        }
        __syncthreads();

        // ---- sp (partial s over this D-half), then ONE cluster sync
        if (t < 64) {
            float s = 0.f;
#pragma unroll 8
            for (int Dl = 0; Dl < 32; Dl++) s += Pk[t * P32 + Dl] * Am[t * P32 + Dl];
            sp[t] = s;
        }
        CLUSTER_SYNC();

        // ---- P5: o = op_self + op_peer (tf32 fused); ss = sp + sp_peer
        for (int i = t; i < 2048; i += 256) {
            int n = (int)rank * 32 + (i >> 6), d = i & 63;
            float v2 = op[n * P64 + d] + ld_dsmem(op_peer + (uint32_t)(n * P64 + d) * 4u);
            g_o[base + (size_t)n * 1024 + d] = cvt_tf32f(v2);
        }
        if (t < 64) ss[t] = sp[t] + ld_dsmem(sp_peer + (uint32_t)t * 4u);
        __syncthreads();

        // ---- P7 (mma): grads + state update (A,B both transposed reads)
        {
            const int m0 = 16 * (w & 1);
            const int nb = (w >> 1) * 16;
            float Cgi[2][4], Cgo[2][4];
#pragma unroll
            for (int j = 0; j < 2; j++)
#pragma unroll
                for (int x2 = 0; x2 < 4; x2++) { Cgi[j][x2] = 0.f; Cgo[j][x2] = 0.f; }
#pragma unroll
            for (int kk = 0; kk < 8; kk++) {
                const int ka = kk * 8 + t4;
                const int kb2 = ka + 4;
                float ssa = ss[ka], ssb = ss[kb2];
                float pk0 = Pk[ka  * P32 + m0 + g],     am0 = Am[ka  * P32 + m0 + g];
                float pk1 = Pk[ka  * P32 + m0 + g + 8], am1 = Am[ka  * P32 + m0 + g + 8];
                float pk2 = Pk[kb2 * P32 + m0 + g],     am2 = Am[kb2 * P32 + m0 + g];
                float pk3 = Pk[kb2 * P32 + m0 + g + 8], am3 = Am[kb2 * P32 + m0 + g + 8];
                uint32_t gz0 = f2t(-pk0 * (am0 - ssa));
                uint32_t gz1 = f2t(-pk1 * (am1 - ssa));
                uint32_t gz2 = f2t(-pk2 * (am2 - ssb));
                uint32_t gz3 = f2t(-pk3 * (am3 - ssb));
                uint32_t p0 = f2t(pk0), p1 = f2t(pk1), p2 = f2t(pk2), p3 = f2t(pk3);
#pragma unroll
                for (int j = 0; j < 2; j++) {
                    const int dcol = nb + 8 * j + g;
                    uint32_t bk0 = __float_as_uint(Kt[ka  * P64 + dcol]);
                    uint32_t bk1 = __float_as_uint(Kt[kb2 * P64 + dcol]);
                    uint32_t bv0 = __float_as_uint(V [ka  * P64 + dcol]);
                    uint32_t bv1 = __float_as_uint(V [kb2 * P64 + dcol]);
                    mma_tf32(Cgi[j], gz0, gz1, gz2, gz3, bk0, bk1);
                    mma_tf32(Cgo[j], p0,  p1,  p2,  p3,  bv0, bv1);
                }
            }
#pragma unroll
            for (int j = 0; j < 2; j++) {
                const int col = nb + 8 * j + 2 * t4;
                const int i0 = (m0 + g)     * P64 + col;
                const int i1 = (m0 + g + 8) * P64 + col;
                Wi [i0]     = wdi * Wi [i0]     - li * Cgi[j][0];
                Wi [i0 + 1] = wdi * Wi [i0 + 1] - li * Cgi[j][1];
                Wi [i1]     = wdi * Wi [i1]     - li * Cgi[j][2];
                Wi [i1 + 1] = wdi * Wi [i1 + 1] - li * Cgi[j][3];
                Wo_[i0]     = wdo * Wo_[i0]     + lo * Cgo[j][0];
                Wo_[i0 + 1] = wdo * Wo_[i0 + 1] + lo * Cgo[j][1];
                Wo_[i1]     = wdo * Wo_[i1]     + lo * Cgo[j][2];
                Wo_[i1 + 1] = wdo * Wo_[i1 + 1] + lo * Cgo[j][3];
            }
        }
        __syncthreads();
    }
    CLUSTER_SYNC();   // keep smem alive for peer's in-flight DSMEM reads
}

// ---------------------------------------------------------------------------
// Launch
// ---------------------------------------------------------------------------
extern "C" void kernel_launch(void* const* d_in, const int* in_sizes, int n_in,
                              void* d_out, int out_size)
{
    (void)in_sizes; (void)n_in; (void)out_size;
    const float* x     = (const float*)d_in[0];
    const float* Wq    = (const float*)d_in[1];
    const float* Wk    = (const float*)d_in[2];
    const float* Wv    = (const float*)d_in[3];
    const float* Wlr   = (const float*)d_in[4];
    const float* Wbeta = (const float*)d_in[5];
    const float* Wo    = (const float*)d_in[6];
    const float* Win0  = (const float*)d_in[7];
    const float* Wout0 = (const float*)d_in[8];
    float* out = (float*)d_out;

    float *q, *k, *v, *om, *xt, *wt;
    cudaGetSymbolAddress((void**)&q,  g_q);
    cudaGetSymbolAddress((void**)&k,  g_k);
    cudaGetSymbolAddress((void**)&v,  g_v);
    cudaGetSymbolAddress((void**)&om, g_o);
    cudaGetSymbolAddress((void**)&xt, g_xt);
    cudaGetSymbolAddress((void**)&wt, g_wt);

    cudaFuncSetAttribute(gemm_tf32p<0, 0>, cudaFuncAttributeMaxDynamicSharedMemorySize, GEMM_SMEM_BYTES);
    cudaFuncSetAttribute(gemm_tf32p<0, 1>, cudaFuncAttributeMaxDynamicSharedMemorySize, GEMM_SMEM_BYTES);
    cudaFuncSetAttribute(gemm_tf32p<1, 1>, cudaFuncAttributeMaxDynamicSharedMemorySize, GEMM_SMEM_BYTES);
    cudaFuncSetAttribute(scan_kernel,      cudaFuncAttributeMaxDynamicSharedMemorySize,
                         SCAN_SMEM_FLOATS * (int)sizeof(float));

    const int NW4 = (1024 * 1024) / 4;
    // lrwd first: streams x once, emits tf32(x) into g_xt as a side product
    lrwd_kernel<<<B_ * NCHUNK_, 256>>>(x, Wlr, Wbeta, xt);
    cvt_kernel<<<(NW4 + 255) / 256, 256>>>(Wq, wt + 0u * 1024u * 1024u, NW4);
    cvt_kernel<<<(NW4 + 255) / 256, 256>>>(Wk, wt + 1u * 1024u * 1024u, NW4);
    cvt_kernel<<<(NW4 + 255) / 256, 256>>>(Wv, wt + 2u * 1024u * 1024u, NW4);
    cvt_kernel<<<(NW4 + 255) / 256, 256>>>(Wo, wt + 3u * 1024u * 1024u, NW4);

    dim3 grid(1024 / 128, M_ / 128);
    gemm_tf32p<1, 1><<<grid, 256, GEMM_SMEM_BYTES>>>(xt, wt + 0u * 1024u * 1024u, q, M_, 1024, 1024);
    gemm_tf32p<1, 1><<<grid, 256, GEMM_SMEM_BYTES>>>(xt, wt + 1u * 1024u * 1024u, k, M_, 1024, 1024);
    gemm_tf32p<0, 1><<<grid, 256, GEMM_SMEM_BYTES>>>(xt, wt + 2u * 1024u * 1024u, v, M_, 1024, 1024);

    const int smem_bytes = SCAN_SMEM_FLOATS * (int)sizeof(float);
    scan_kernel<<<128, 256, smem_bytes>>>(Win0, Wout0);

    // g_o holds tf32 bits — final GEMM reads it directly, stores plain fp32
    gemm_tf32p<0, 0><<<grid, 256, GEMM_SMEM_BYTES>>>(om, wt + 3u * 1024u * 1024u, out, M_, 1024, 1024);
}

// round 16
// speedup vs baseline: 1.5218x; 1.0137x over previous
#include <cuda_runtime.h>
#include <cstdint>

// Problem constants
#define B_ 4
#define L_ 4096
#define DIM_ 1024
#define H_ 16
#define NCHUNK_ 64
#define CHUNK_ 64
#define M_ (B_ * L_)          // 16384

// ---------------------------------------------------------------------------
// Device scratch (allocation-free contract: __device__ globals)
// ---------------------------------------------------------------------------
__device__ float g_q[(size_t)B_ * L_ * 1024];   // tf32 bits
__device__ float g_k[(size_t)B_ * L_ * 1024];   // tf32 bits
__device__ float g_v[(size_t)B_ * L_ * 1024];   // tf32 bits
__device__ float g_o[(size_t)B_ * L_ * 1024];   // tf32 bits (scan P5 cvt)
__device__ float g_xt[(size_t)B_ * L_ * 1024];  // tf32(x), produced by lrwd_kernel
__device__ float g_wt[4u * 1024u * 1024u];      // tf32(Wq,Wk,Wv,Wo) contiguous
__device__ float g_lrwd[B_ * NCHUNK_ * 64];

// ---------------------------------------------------------------------------
// PTX helpers
// ---------------------------------------------------------------------------
__device__ __forceinline__ float cvt_tf32f(float f) {
    uint32_t u;
    asm("cvt.rna.tf32.f32 %0, %1;" : "=r"(u) : "f"(f));
    return __uint_as_float(u);
}
__device__ __forceinline__ uint32_t f2t(float f) {
    uint32_t u;
    asm("cvt.rna.tf32.f32 %0, %1;" : "=r"(u) : "f"(f));
    return u;
}

__device__ __forceinline__ void cp16(void* smem, const void* gmem) {
    uint32_t s = (uint32_t)__cvta_generic_to_shared(smem);
    asm volatile("cp.async.cg.shared.global [%0], [%1], 16;" :: "r"(s), "l"(gmem));
}
__device__ __forceinline__ void cp_commit() {
    asm volatile("cp.async.commit_group;");
}
template <int N>
__device__ __forceinline__ void cp_wait() {
    asm volatile("cp.async.wait_group %0;" :: "n"(N));
}

__device__ __forceinline__ void mma_tf32(float c[4],
                                         uint32_t a0, uint32_t a1, uint32_t a2, uint32_t a3,
                                         uint32_t b0, uint32_t b1) {
    asm volatile(
        "mma.sync.aligned.m16n8k8.row.col.f32.tf32.tf32.f32 "
        "{%0,%1,%2,%3}, {%4,%5,%6,%7}, {%8,%9}, {%0,%1,%2,%3};"
        : "+f"(c[0]), "+f"(c[1]), "+f"(c[2]), "+f"(c[3])
        : "r"(a0), "r"(a1), "r"(a2), "r"(a3), "r"(b0), "r"(b1));
}

__device__ __forceinline__ uint32_t mapa_u32(uint32_t addr, uint32_t rank) {
    uint32_t r;
    asm("mapa.shared::cluster.u32 %0, %1, %2;" : "=r"(r) : "r"(addr), "r"(rank));
    return r;
}
__device__ __forceinline__ float ld_dsmem(uint32_t addr) {
    float v;
    asm volatile("ld.shared::cluster.f32 %0, [%1];" : "=f"(v) : "r"(addr));
    return v;
}
#define CLUSTER_SYNC() do { \
    asm volatile("barrier.cluster.arrive.aligned;" ::: "memory"); \
    asm volatile("barrier.cluster.wait.aligned;" ::: "memory"); } while (0)

// ---------------------------------------------------------------------------
// tf32 pre-convert (weights only)
// ---------------------------------------------------------------------------
__global__ __launch_bounds__(256)
void cvt_kernel(const float* __restrict__ src, float* __restrict__ dst, int n4)
{
    int i = blockIdx.x * 256 + threadIdx.x;
    if (i < n4) {
        float4 v = ((const float4*)src)[i];
        v.x = cvt_tf32f(v.x); v.y = cvt_tf32f(v.y);
        v.z = cvt_tf32f(v.z); v.w = cvt_tf32f(v.w);
        ((float4*)dst)[i] = v;
    }
}

// ---------------------------------------------------------------------------
// GEMM core (shared by both GEMM kernels): 128x128 block, BK=16, 3-stage.
// ---------------------------------------------------------------------------
#define GEMM_SMEM_BYTES (3 * 2 * 128 * 20 * 4)

struct GemmCtx {
    float (*As)[128][20];
    float (*Bs)[128][20];
    int t, w, lane, wm, wn, g, t4;
};

__device__ __forceinline__ void gemm_main(const float* A, const float* W,
                                          int bm, int bn, int K,
                                          GemmCtx& cx, float acc[4][4][4])
{
#pragma unroll
    for (int mt = 0; mt < 4; mt++)
#pragma unroll
        for (int nt = 0; nt < 4; nt++)
#pragma unroll
            for (int c = 0; c < 4; c++) acc[mt][nt][c] = 0.f;

    const int KT = K >> 4;
    const int t = cx.t;

    auto load_stage = [&](int kb, int buf) {
        const int k0 = kb * 16;
#pragma unroll
        for (int s = 0; s < 2; s++) {
            int j   = t + s * 256;
            int row = j >> 2;
            int c4  = (j & 3) * 4;
            cp16(&cx.As[buf][row][c4], A + (size_t)(bm + row) * K + k0 + c4);
            cp16(&cx.Bs[buf][row][c4], W + (size_t)(bn + row) * K + k0 + c4);
        }
    };

    load_stage(0, 0); cp_commit();
    load_stage(1, 1); cp_commit();

    for (int kb = 0; kb < KT; kb++) {
        cp_wait<1>();
        __syncthreads();
        if (kb + 2 < KT) { load_stage(kb + 2, (kb + 2) % 3); cp_commit(); }
        else             { cp_commit(); }
        const int buf = kb % 3;

#pragma unroll
        for (int ks = 0; ks < 2; ks++) {
            const int k0 = ks * 8;
            uint32_t bf[4][2];
#pragma unroll
            for (int nt = 0; nt < 4; nt++) {
                bf[nt][0] = __float_as_uint(cx.Bs[buf][cx.wn + nt * 8 + cx.g][k0 + cx.t4]);
                bf[nt][1] = __float_as_uint(cx.Bs[buf][cx.wn + nt * 8 + cx.g][k0 + cx.t4 + 4]);
            }
#pragma unroll
            for (int mt = 0; mt < 4; mt++) {
                uint32_t a0 = __float_as_uint(cx.As[buf][cx.wm + mt * 16 + cx.g][k0 + cx.t4]);
                uint32_t a1 = __float_as_uint(cx.As[buf][cx.wm + mt * 16 + cx.g + 8][k0 + cx.t4]);
                uint32_t a2 = __float_as_uint(cx.As[buf][cx.wm + mt * 16 + cx.g][k0 + cx.t4 + 4]);
                uint32_t a3 = __float_as_uint(cx.As[buf][cx.wm + mt * 16 + cx.g + 8][k0 + cx.t4 + 4]);
#pragma unroll
                for (int nt = 0; nt < 4; nt++)
                    mma_tf32(acc[mt][nt], a0, a1, a2, a3, bf[nt][0], bf[nt][1]);
            }
        }
        // no bottom barrier: buf kb%3 next written after iter kb+1's top sync
    }
}

__device__ __forceinline__ void gemm_init_ctx(GemmCtx& cx, float* gsm)
{
    cx.As = (float (*)[128][20])gsm;
    cx.Bs = (float (*)[128][20])(gsm + 3 * 128 * 20);
    cx.t    = threadIdx.x;
    cx.w    = cx.t >> 5;
    cx.lane = cx.t & 31;
    cx.wm   = (cx.w >> 2) * 64;
    cx.wn   = (cx.w & 3) * 32;
    cx.g    = cx.lane >> 2;
    cx.t4   = cx.lane & 3;
}

// Fused Q/K/V projection: W = [Wq;Wk;Wv] (3072 rows). bn>>10 selects output.
__global__ __launch_bounds__(256, 2)
void gemm_qkv(const float* __restrict__ A, const float* __restrict__ W,
              float* __restrict__ Cq, float* __restrict__ Ck, float* __restrict__ Cv)
{
    extern __shared__ __align__(16) float gsm[];
    GemmCtx cx; gemm_init_ctx(cx, gsm);
    const int bm = blockIdx.y * 128;
    const int bn = blockIdx.x * 128;

    float acc[4][4][4];
    gemm_main(A, W, bm, bn, 1024, cx, acc);

    const int mat  = bn >> 10;
    const int bnl  = bn & 1023;
    float* Cd = (mat == 0) ? Cq : (mat == 1) ? Ck : Cv;
    const bool act = (mat < 2);

#pragma unroll
    for (int mt = 0; mt < 4; mt++) {
#pragma unroll
        for (int nt = 0; nt < 4; nt++) {
            int m = bm + cx.wm + mt * 16 + cx.g;
            int n = bnl + cx.wn + nt * 8 + cx.t4 * 2;
            float2 v0 = make_float2(acc[mt][nt][0], acc[mt][nt][1]);
            float2 v1 = make_float2(acc[mt][nt][2], acc[mt][nt][3]);
            if (act) {
                v0.x = v0.x / (1.f + __expf(-v0.x));
                v0.y = v0.y / (1.f + __expf(-v0.y));
                v1.x = v1.x / (1.f + __expf(-v1.x));
                v1.y = v1.y / (1.f + __expf(-v1.y));
            }
            v0.x = cvt_tf32f(v0.x); v0.y = cvt_tf32f(v0.y);
            v1.x = cvt_tf32f(v1.x); v1.y = cvt_tf32f(v1.y);
            *(float2*)&Cd[(size_t)m * 1024 + n]       = v0;
            *(float2*)&Cd[(size_t)(m + 8) * 1024 + n] = v1;
        }
    }
}

// Plain GEMM (final output projection): fp32 stores.
__global__ __launch_bounds__(256, 2)
void gemm_out(const float* __restrict__ A, const float* __restrict__ W,
              float* __restrict__ C)
{
    extern __shared__ __align__(16) float gsm[];
    GemmCtx cx; gemm_init_ctx(cx, gsm);
    const int bm = blockIdx.y * 128;
    const int bn = blockIdx.x * 128;

    float acc[4][4][4];
    gemm_main(A, W, bm, bn, 1024, cx, acc);

#pragma unroll
    for (int mt = 0; mt < 4; mt++) {
#pragma unroll
        for (int nt = 0; nt < 4; nt++) {
            int m = bm + cx.wm + mt * 16 + cx.g;
            int n = bn + cx.wn + nt * 8 + cx.t4 * 2;
            *(float2*)&C[(size_t)m * 1024 + n] =
                make_float2(acc[mt][nt][0], acc[mt][nt][1]);
            *(float2*)&C[(size_t)(m + 8) * 1024 + n] =
                make_float2(acc[mt][nt][2], acc[mt][nt][3]);
        }
    }
}

// ---------------------------------------------------------------------------
// lr/wd chunk means + fused x -> tf32 conversion
// ---------------------------------------------------------------------------
__global__ __launch_bounds__(256, 2)
void lrwd_kernel(const float* __restrict__ x,
                 const float* __restrict__ Wlr,
                 const float* __restrict__ Wbeta,
                 float* __restrict__ xt)
{
    __shared__ float xs[64][65];
    __shared__ float ws[64][65];
    __shared__ float red2[64 * 16];

    const int bc = blockIdx.x;
    const size_t xb = (size_t)bc * 64 * 1024;
    const int t  = threadIdx.x;
    const int r0 = t >> 4;
    const int c0 = t & 15;

    float acc[4][4];
#pragma unroll
    for (int i = 0; i < 4; i++)
#pragma unroll
        for (int j = 0; j < 4; j++) acc[i][j] = 0.f;

    for (int k0 = 0; k0 < 1024; k0 += 64) {
        for (int i = t; i < 4096; i += 256) {
            int n = i >> 6, d = i & 63;
            size_t gi = xb + (size_t)n * 1024 + k0 + d;
            float xv = x[gi];
            xs[n][d] = xv;
            xt[gi]   = cvt_tf32f(xv);
            ws[n][d] = (n < 32) ? Wlr[n * 1024 + k0 + d]
                                : Wbeta[(n - 32) * 1024 + k0 + d];
        }
        __syncthreads();
#pragma unroll 4
        for (int k = 0; k < 64; k++) {
            float a[4], b[4];
#pragma unroll
            for (int ii = 0; ii < 4; ii++) a[ii] = xs[r0 + 16 * ii][k];
#pragma unroll
            for (int jj = 0; jj < 4; jj++) b[jj] = ws[c0 + 16 * jj][k];
#pragma unroll
            for (int ii = 0; ii < 4; ii++)
#pragma unroll
                for (int jj = 0; jj < 4; jj++) acc[ii][jj] += a[ii] * b[jj];
        }
        __syncthreads();
    }

#pragma unroll
    for (int jj = 0; jj < 4; jj++) {
        int j = c0 + 16 * jj;
        float scale = (j < 32) ? 0.001f : 0.9f;
        float p = 0.f;
#pragma unroll
        for (int ii = 0; ii < 4; ii++)
            p += scale / (1.f + __expf(-acc[ii][jj]));
        red2[j * 16 + r0] = p;
    }
    __syncthreads();
    if (t < 64) {
        float s = 0.f;
        for (int r = 0; r < 16; r++) s += red2[t * 16 + r];
        g_lrwd[bc * 64 + t] = s * (1.f / 64.f);
    }
}

// ---------------------------------------------------------------------------
// Cluster-2 persistent scan: all-mma gemmlets, cp.async prefetch, exp fused
// into P2 epilogue, no-max softmax, one cluster sync per chunk (parity bufs).
// ---------------------------------------------------------------------------
#define P64 68
#define P32 36

#define OFF_WI   0
#define OFF_WO   (32 * P64)
#define OFF_T    (2 * 32 * P64)
#define TILE_SZ  (64 * P64)
#define OFF_PQ   (OFF_T + 6 * TILE_SZ)
#define OFF_PK   (OFF_PQ + 64 * P32)
#define OFF_AM   (OFF_PK + 64 * P32)
#define OFF_OP   (OFF_AM + 64 * P32)         // [2][64][68] parity buffers
#define OFF_SP   (OFF_OP + 2 * TILE_SZ)      // [2][64]
#define OFF_SS   (OFF_SP + 128)
#define OFF_RED  (OFF_SS + 64)               // [4][64]
#define OFF_CS   (OFF_RED + 256)
#define SCAN_SMEM_FLOATS (OFF_CS + 64)       // 46592 -> 186368 bytes

__global__ __launch_bounds__(256, 1) __cluster_dims__(2, 1, 1)
void scan_kernel(const float* __restrict__ Win0, const float* __restrict__ Wout0)
{
    extern __shared__ float sm[];
    float* Wi  = sm + OFF_WI;
    float* Wo_ = sm + OFF_WO;
    float* Pq  = sm + OFF_PQ;
    float* Pk  = sm + OFF_PK;
    float* Am  = sm + OFF_AM;
    float* ss  = sm + OFF_SS;
    float* red = sm + OFF_RED;
    float* cs  = sm + OFF_CS;

    const int pair = blockIdx.x >> 1;
    const uint32_t rank = blockIdx.x & 1;
    const int b = pair >> 4;
    const int h = pair & 15;
    const int t = threadIdx.x;

    const int w    = t >> 5;
    const int lane = t & 31;
    const int g    = lane >> 2;
    const int t4   = lane & 3;
    const int task = t & 63, sg = t >> 6;

    const uint32_t op_peer0 = mapa_u32((uint32_t)__cvta_generic_to_shared(sm + OFF_OP), rank ^ 1u);
    const uint32_t sp_peer0 = mapa_u32((uint32_t)__cvta_generic_to_shared(sm + OFF_SP), rank ^ 1u);

    for (int i = t; i < 2048; i += 256) {
        int Dl = i >> 6, d = i & 63;
        int Dg = (int)rank * 32 + Dl;
        Wi [Dl * P64 + d] = Win0 [Dg * 1024 + h * 64 + d];
        Wo_[Dl * P64 + d] = Wout0[Dg * 1024 + h * 64 + d];
    }

    auto prefetch = [&](int c, int buf) {
        const size_t base = ((size_t)b * L_ + (size_t)c * 64) * 1024 + h * 64;
        float* Qb = sm + OFF_T + (buf * 3 + 0) * TILE_SZ;
        float* Kb = sm + OFF_T + (buf * 3 + 1) * TILE_SZ;
        float* Vb = sm + OFF_T + (buf * 3 + 2) * TILE_SZ;
        for (int i = t; i < 1024; i += 256) {
            int n = i >> 4, d4 = (i & 15) * 4;
            size_t gidx = base + (size_t)n * 1024 + d4;
            cp16(&Qb[n * P64 + d4], &g_q[gidx]);
            cp16(&Kb[n * P64 + d4], &g_k[gidx]);
            cp16(&Vb[n * P64 + d4], &g_v[gidx]);
        }
    };

    prefetch(0, 0); cp_commit();
    __syncthreads();

    for (int c = 0; c < NCHUNK_; c++) {
        const int buf = c & 1;
        const float* Q  = sm + OFF_T + (buf * 3 + 0) * TILE_SZ;
        const float* Kt = sm + OFF_T + (buf * 3 + 1) * TILE_SZ;
        const float* V  = sm + OFF_T + (buf * 3 + 2) * TILE_SZ;
        float* op = sm + OFF_OP + buf * TILE_SZ;
        float* sp = sm + OFF_SP + buf * 64;
        const uint32_t op_peer = op_peer0 + (uint32_t)(buf * TILE_SZ) * 4u;
        const uint32_t sp_peer = sp_peer0 + (uint32_t)(buf * 64) * 4u;

        const size_t base = ((size_t)b * L_ + (size_t)c * 64) * 1024 + h * 64;
        const int lb = (b * 64 + c) * 64;
        const float li  = g_lrwd[lb + h];
        const float lo  = g_lrwd[lb + 16 + h];
        const float wdi = g_lrwd[lb + 32 + h];
        const float wdo = g_lrwd[lb + 48 + h];

        // ---- P1
        cp_wait<0>();
        __syncthreads();
        if (c + 1 < NCHUNK_) { prefetch(c + 1, buf ^ 1); cp_commit(); }

        // ---- P2 (mma): logits, exp fused into epilogue
        {
            const float* src = (w < 4) ? Q  : Kt;
            float*       dst = (w < 4) ? Pq : Pk;
            const int m0 = 16 * (w & 3);
            float C_[4][4];
#pragma unroll
            for (int j = 0; j < 4; j++)
#pragma unroll
                for (int x2 = 0; x2 < 4; x2++) C_[j][x2] = 0.f;
#pragma unroll
            for (int kk = 0; kk < 8; kk++) {
                const int k0 = kk * 8;
                uint32_t a0 = __float_as_uint(src[(m0 + g)     * P64 + k0 + t4]);
                uint32_t a1 = __float_as_uint(src[(m0 + g + 8) * P64 + k0 + t4]);
                uint32_t a2 = __float_as_uint(src[(m0 + g)     * P64 + k0 + t4 + 4]);
                uint32_t a3 = __float_as_uint(src[(m0 + g + 8) * P64 + k0 + t4 + 4]);
#pragma unroll
                for (int j = 0; j < 4; j++) {
                    uint32_t b0 = f2t(Wi[(8 * j + g) * P64 + k0 + t4]);
                    uint32_t b1 = f2t(Wi[(8 * j + g) * P64 + k0 + t4 + 4]);
                    mma_tf32(C_[j], a0, a1, a2, a3, b0, b1);
                }
            }
#pragma unroll
            for (int j = 0; j < 4; j++) {
                dst[(m0 + g)     * P32 + 8 * j + 2 * t4]     = __expf(C_[j][0]);
                dst[(m0 + g)     * P32 + 8 * j + 2 * t4 + 1] = __expf(C_[j][1]);
                dst[(m0 + g + 8) * P32 + 8 * j + 2 * t4]     = __expf(C_[j][2]);
                dst[(m0 + g + 8) * P32 + 8 * j + 2 * t4 + 1] = __expf(C_[j][3]);
            }
        }
        __syncthreads();

        // ---- P3: normalize (values already exp'ed)
        {
            float* Pp = (task < 32) ? Pq : Pk;
            const int D = task & 31;
            float s = 0.f;
#pragma unroll
            for (int n = sg * 16; n < sg * 16 + 16; n++) s += Pp[n * P32 + D];
            red[sg * 64 + task] = s;
            __syncthreads();
            if (t < 64) cs[t] = 1.f / (red[t] + red[64 + t] + red[128 + t] + red[192 + t]);
            __syncthreads();
            float inv = cs[task];
#pragma unroll
            for (int n = sg * 16; n < sg * 16 + 16; n++) Pp[n * P32 + D] *= inv;
        }
        __syncthreads();

        // ---- P4a (mma): op[n][d] = sum_Dl Pq[n][Dl] * Wo_[Dl][d]
        {
            const int m0 = 16 * (w & 3);
            const int nb = 32 * (w >> 2);
            float Co[4][4];
#pragma unroll
            for (int j = 0; j < 4; j++)
#pragma unroll
                for (int x2 = 0; x2 < 4; x2++) Co[j][x2] = 0.f;
#pragma unroll
            for (int kk = 0; kk < 4; kk++) {
                const int k0 = kk * 8;
                uint32_t a0 = f2t(Pq[(m0 + g)     * P32 + k0 + t4]);
                uint32_t a1 = f2t(Pq[(m0 + g + 8) * P32 + k0 + t4]);
                uint32_t a2 = f2t(Pq[(m0 + g)     * P32 + k0 + t4 + 4]);
                uint32_t a3 = f2t(Pq[(m0 + g + 8) * P32 + k0 + t4 + 4]);
#pragma unroll
                for (int j = 0; j < 4; j++) {
                    const int dcol = nb + 8 * j + g;
                    uint32_t b0 = f2t(Wo_[(k0 + t4)     * P64 + dcol]);
                    uint32_t b1 = f2t(Wo_[(k0 + t4 + 4) * P64 + dcol]);
                    mma_tf32(Co[j], a0, a1, a2, a3, b0, b1);
                }
            }
#pragma unroll
            for (int j = 0; j < 4; j++) {
                const int col = nb + 8 * j + 2 * t4;
                op[(m0 + g)     * P64 + col]     = Co[j][0];
                op[(m0 + g)     * P64 + col + 1] = Co[j][1];
                op[(m0 + g + 8) * P64 + col]     = Co[j][2];
                op[(m0 + g + 8) * P64 + col + 1] = Co[j][3];
            }
        }

        // ---- P4b (mma): Am[n][Dl] = sum_d V[n][d]*Wo_[Dl][d]
        {
            const int m0 = 16 * (w & 3);
            const int nb = (w >> 2) * 16;
            float Ca[2][4];
#pragma unroll
            for (int j = 0; j < 2; j++)
#pragma unroll
                for (int x2 = 0; x2 < 4; x2++) Ca[j][x2] = 0.f;
#pragma unroll
            for (int kk = 0; kk < 8; kk++) {
                const int k0 = kk * 8;
                uint32_t a0 = __float_as_uint(V[(m0 + g)     * P64 + k0 + t4]);
                uint32_t a1 = __float_as_uint(V[(m0 + g + 8) * P64 + k0 + t4]);
                uint32_t a2 = __float_as_uint(V[(m0 + g)     * P64 + k0 + t4 + 4]);
                uint32_t a3 = __float_as_uint(V[(m0 + g + 8) * P64 + k0 + t4 + 4]);
#pragma unroll
                for (int j = 0; j < 2; j++) {
                    const int Dl = nb + 8 * j + g;
                    uint32_t b0 = f2t(Wo_[Dl * P64 + k0 + t4]);
                    uint32_t b1 = f2t(Wo_[Dl * P64 + k0 + t4 + 4]);
                    mma_tf32(Ca[j], a0, a1, a2, a3, b0, b1);
                }
            }
#pragma unroll
            for (int j = 0; j < 2; j++) {
                Am[(m0 + g)     * P32 + nb + 8 * j + 2 * t4]     = Ca[j][0];
                Am[(m0 + g)     * P32 + nb + 8 * j + 2 * t4 + 1] = Ca[j][1];
                Am[(m0 + g + 8) * P32 + nb + 8 * j + 2 * t4]     = Ca[j][2];
                Am[(m0 + g + 8) * P32 + nb + 8 * j + 2 * t4 + 1] = Ca[j][3];
            }
        }
        __syncthreads();

        // ---- sp, then ONE cluster sync
        if (t < 64) {
            float s = 0.f;
#pragma unroll 8
            for (int Dl = 0; Dl < 32; Dl++) s += Pk[t * P32 + Dl] * Am[t * P32 + Dl];
            sp[t] = s;
        }
        CLUSTER_SYNC();

        // ---- P5: o exchange + ss
        for (int i = t; i < 2048; i += 256) {
            int n = (int)rank * 32 + (i >> 6), d = i & 63;
            float v2 = op[n * P64 + d] + ld_dsmem(op_peer + (uint32_t)(n * P64 + d) * 4u);
            g_o[base + (size_t)n * 1024 + d] = cvt_tf32f(v2);
        }
        if (t < 64) ss[t] = sp[t] + ld_dsmem(sp_peer + (uint32_t)t * 4u);
        __syncthreads();

        // ---- P7 (mma): grads + state update
        {
            const int m0 = 16 * (w & 1);
            const int nb = (w >> 1) * 16;
            float Cgi[2][4], Cgo[2][4];
#pragma unroll
            for (int j = 0; j < 2; j++)
#pragma unroll
                for (int x2 = 0; x2 < 4; x2++) { Cgi[j][x2] = 0.f; Cgo[j][x2] = 0.f; }
#pragma unroll
            for (int kk = 0; kk < 8; kk++) {
                const int ka = kk * 8 + t4;
                const int kb2 = ka + 4;
                float ssa = ss[ka], ssb = ss[kb2];
                float pk0 = Pk[ka  * P32 + m0 + g],     am0 = Am[ka  * P32 + m0 + g];
                float pk1 = Pk[ka  * P32 + m0 + g + 8], am1 = Am[ka  * P32 + m0 + g + 8];
                float pk2 = Pk[kb2 * P32 + m0 + g],     am2 = Am[kb2 * P32 + m0 + g];
                float pk3 = Pk[kb2 * P32 + m0 + g + 8], am3 = Am[kb2 * P32 + m0 + g + 8];
                uint32_t gz0 = f2t(-pk0 * (am0 - ssa));
                uint32_t gz1 = f2t(-pk1 * (am1 - ssa));
                uint32_t gz2 = f2t(-pk2 * (am2 - ssb));
                uint32_t gz3 = f2t(-pk3 * (am3 - ssb));
                uint32_t p0 = f2t(pk0), p1 = f2t(pk1), p2 = f2t(pk2), p3 = f2t(pk3);
#pragma unroll
                for (int j = 0; j < 2; j++) {
                    const int dcol = nb + 8 * j + g;
                    uint32_t bk0 = __float_as_uint(Kt[ka  * P64 + dcol]);
                    uint32_t bk1 = __float_as_uint(Kt[kb2 * P64 + dcol]);
                    uint32_t bv0 = __float_as_uint(V [ka  * P64 + dcol]);
                    uint32_t bv1 = __float_as_uint(V [kb2 * P64 + dcol]);
                    mma_tf32(Cgi[j], gz0, gz1, gz2, gz3, bk0, bk1);
                    mma_tf32(Cgo[j], p0,  p1,  p2,  p3,  bv0, bv1);
                }
            }
#pragma unroll
            for (int j = 0; j < 2; j++) {
                const int col = nb + 8 * j + 2 * t4;
                const int i0 = (m0 + g)     * P64 + col;
                const int i1 = (m0 + g + 8) * P64 + col;
                Wi [i0]     = wdi * Wi [i0]     - li * Cgi[j][0];
                Wi [i0 + 1] = wdi * Wi [i0 + 1] - li * Cgi[j][1];
                Wi [i1]     = wdi * Wi [i1]     - li * Cgi[j][2];
                Wi [i1 + 1] = wdi * Wi [i1 + 1] - li * Cgi[j][3];
                Wo_[i0]     = wdo * Wo_[i0]     + lo * Cgo[j][0];
                Wo_[i0 + 1] = wdo * Wo_[i0 + 1] + lo * Cgo[j][1];
                Wo_[i1]     = wdo * Wo_[i1]     + lo * Cgo[j][2];
                Wo_[i1 + 1] = wdo * Wo_[i1 + 1] + lo * Cgo[j][3];
            }
        }
        __syncthreads();
    }
    CLUSTER_SYNC();
}

// ---------------------------------------------------------------------------
// Launch
// ---------------------------------------------------------------------------
extern "C" void kernel_launch(void* const* d_in, const int* in_sizes, int n_in,
                              void* d_out, int out_size)
{
    (void)in_sizes; (void)n_in; (void)out_size;
    const float* x     = (const float*)d_in[0];
    const float* Wq    = (const float*)d_in[1];
    const float* Wk    = (const float*)d_in[2];
    const float* Wv    = (const float*)d_in[3];
    const float* Wlr   = (const float*)d_in[4];
    const float* Wbeta = (const float*)d_in[5];
    const float* Wo    = (const float*)d_in[6];
    const float* Win0  = (const float*)d_in[7];
    const float* Wout0 = (const float*)d_in[8];
    float* out = (float*)d_out;

    float *q, *k, *v, *om, *xt, *wt;
    cudaGetSymbolAddress((void**)&q,  g_q);
    cudaGetSymbolAddress((void**)&k,  g_k);
    cudaGetSymbolAddress((void**)&v,  g_v);
    cudaGetSymbolAddress((void**)&om, g_o);
    cudaGetSymbolAddress((void**)&xt, g_xt);
    cudaGetSymbolAddress((void**)&wt, g_wt);

    cudaFuncSetAttribute(gemm_qkv, cudaFuncAttributeMaxDynamicSharedMemorySize, GEMM_SMEM_BYTES);
    cudaFuncSetAttribute(gemm_out, cudaFuncAttributeMaxDynamicSharedMemorySize, GEMM_SMEM_BYTES);
    cudaFuncSetAttribute(scan_kernel, cudaFuncAttributeMaxDynamicSharedMemorySize,
                         SCAN_SMEM_FLOATS * (int)sizeof(float));

    const int NW4 = (1024 * 1024) / 4;
    lrwd_kernel<<<B_ * NCHUNK_, 256>>>(x, Wlr, Wbeta, xt);
    cvt_kernel<<<(NW4 + 255) / 256, 256>>>(Wq, wt + 0u * 1024u * 1024u, NW4);
    cvt_kernel<<<(NW4 + 255) / 256, 256>>>(Wk, wt + 1u * 1024u * 1024u, NW4);
    cvt_kernel<<<(NW4 + 255) / 256, 256>>>(Wv, wt + 2u * 1024u * 1024u, NW4);
    cvt_kernel<<<(NW4 + 255) / 256, 256>>>(Wo, wt + 3u * 1024u * 1024u, NW4);

    // fused q/k/v projection: N = 3072 over [Wq;Wk;Wv]
    dim3 grid_qkv(3072 / 128, M_ / 128);
    gemm_qkv<<<grid_qkv, 256, GEMM_SMEM_BYTES>>>(xt, wt, q, k, v);

    const int smem_bytes = SCAN_SMEM_FLOATS * (int)sizeof(float);
    scan_kernel<<<128, 256, smem_bytes>>>(Win0, Wout0);

    dim3 grid_o(1024 / 128, M_ / 128);
    gemm_out<<<grid_o, 256, GEMM_SMEM_BYTES>>>(om, wt + 3u * 1024u * 1024u, out);
}

// round 17
// speedup vs baseline: 1.5686x; 1.0307x over previous
#include <cuda_runtime.h>
#include <cstdint>

// Problem constants
#define B_ 4
#define L_ 4096
#define DIM_ 1024
#define H_ 16
#define NCHUNK_ 64
#define CHUNK_ 64
#define M_ (B_ * L_)          // 16384

// ---------------------------------------------------------------------------
// Device scratch (allocation-free contract: __device__ globals)
// ---------------------------------------------------------------------------
__device__ float g_q[(size_t)B_ * L_ * 1024];     // tf32 bits
__device__ float g_k[(size_t)B_ * L_ * 1024];     // tf32 bits
__device__ float g_v[(size_t)B_ * L_ * 1024];     // tf32 bits
__device__ float g_o[(size_t)B_ * L_ * 1024];     // tf32 bits (scan P5 cvt)
__device__ float g_xt[(size_t)B_ * L_ * 1024];    // tf32(x)
__device__ float g_wcat[3200u * 1024u];           // tf32 [Wq;Wk;Wv;Wlr;Wbeta;pad(zero)]
__device__ float g_wo[1024u * 1024u];             // tf32 Wo
__device__ float g_lrx[(size_t)M_ * 128];         // per-token sigmoid outputs
__device__ float g_lrwd[B_ * NCHUNK_ * 64];

// ---------------------------------------------------------------------------
// PTX helpers
// ---------------------------------------------------------------------------
__device__ __forceinline__ float cvt_tf32f(float f) {
    uint32_t u;
    asm("cvt.rna.tf32.f32 %0, %1;" : "=r"(u) : "f"(f));
    return __uint_as_float(u);
}
__device__ __forceinline__ uint32_t f2t(float f) {
    uint32_t u;
    asm("cvt.rna.tf32.f32 %0, %1;" : "=r"(u) : "f"(f));
    return u;
}

__device__ __forceinline__ void cp16(void* smem, const void* gmem) {
    uint32_t s = (uint32_t)__cvta_generic_to_shared(smem);
    asm volatile("cp.async.cg.shared.global [%0], [%1], 16;" :: "r"(s), "l"(gmem));
}
__device__ __forceinline__ void cp_commit() {
    asm volatile("cp.async.commit_group;");
}
template <int N>
__device__ __forceinline__ void cp_wait() {
    asm volatile("cp.async.wait_group %0;" :: "n"(N));
}

__device__ __forceinline__ void mma_tf32(float c[4],
                                         uint32_t a0, uint32_t a1, uint32_t a2, uint32_t a3,
                                         uint32_t b0, uint32_t b1) {
    asm volatile(
        "mma.sync.aligned.m16n8k8.row.col.f32.tf32.tf32.f32 "
        "{%0,%1,%2,%3}, {%4,%5,%6,%7}, {%8,%9}, {%0,%1,%2,%3};"
        : "+f"(c[0]), "+f"(c[1]), "+f"(c[2]), "+f"(c[3])
        : "r"(a0), "r"(a1), "r"(a2), "r"(a3), "r"(b0), "r"(b1));
}

__device__ __forceinline__ uint32_t mapa_u32(uint32_t addr, uint32_t rank) {
    uint32_t r;
    asm("mapa.shared::cluster.u32 %0, %1, %2;" : "=r"(r) : "r"(addr), "r"(rank));
    return r;
}
__device__ __forceinline__ float ld_dsmem(uint32_t addr) {
    float v;
    asm volatile("ld.shared::cluster.f32 %0, [%1];" : "=f"(v) : "r"(addr));
    return v;
}
#define CLUSTER_SYNC() do { \
    asm volatile("barrier.cluster.arrive.aligned;" ::: "memory"); \
    asm volatile("barrier.cluster.wait.aligned;" ::: "memory"); } while (0)

// ---------------------------------------------------------------------------
// tf32 pre-convert
// ---------------------------------------------------------------------------
__global__ __launch_bounds__(256)
void cvt_kernel(const float* __restrict__ src, float* __restrict__ dst, int n4)
{
    int i = blockIdx.x * 256 + threadIdx.x;
    if (i < n4) {
        float4 v = ((const float4*)src)[i];
        v.x = cvt_tf32f(v.x); v.y = cvt_tf32f(v.y);
        v.z = cvt_tf32f(v.z); v.w = cvt_tf32f(v.w);
        ((float4*)dst)[i] = v;
    }
}

// ---------------------------------------------------------------------------
// GEMM core: 128x128 block, BK=16, 3-stage cp.async.
// ---------------------------------------------------------------------------
#define GEMM_SMEM_BYTES (3 * 2 * 128 * 20 * 4)

struct GemmCtx {
    float (*As)[128][20];
    float (*Bs)[128][20];
    int t, w, lane, wm, wn, g, t4;
};

__device__ __forceinline__ void gemm_init_ctx(GemmCtx& cx, float* gsm)
{
    cx.As = (float (*)[128][20])gsm;
    cx.Bs = (float (*)[128][20])(gsm + 3 * 128 * 20);
    cx.t    = threadIdx.x;
    cx.w    = cx.t >> 5;
    cx.lane = cx.t & 31;
    cx.wm   = (cx.w >> 2) * 64;
    cx.wn   = (cx.w & 3) * 32;
    cx.g    = cx.lane >> 2;
    cx.t4   = cx.lane & 3;
}

__device__ __forceinline__ void gemm_main(const float* A, const float* W,
                                          int bm, int bn, int K,
                                          GemmCtx& cx, float acc[4][4][4])
{
#pragma unroll
    for (int mt = 0; mt < 4; mt++)
#pragma unroll
        for (int nt = 0; nt < 4; nt++)
#pragma unroll
            for (int c = 0; c < 4; c++) acc[mt][nt][c] = 0.f;

    const int KT = K >> 4;
    const int t = cx.t;

    auto load_stage = [&](int kb, int buf) {
        const int k0 = kb * 16;
#pragma unroll
        for (int s = 0; s < 2; s++) {
            int j   = t + s * 256;
            int row = j >> 2;
            int c4  = (j & 3) * 4;
            cp16(&cx.As[buf][row][c4], A + (size_t)(bm + row) * K + k0 + c4);
            cp16(&cx.Bs[buf][row][c4], W + (size_t)(bn + row) * K + k0 + c4);
        }
    };

    load_stage(0, 0); cp_commit();
    load_stage(1, 1); cp_commit();

    for (int kb = 0; kb < KT; kb++) {
        cp_wait<1>();
        __syncthreads();
        if (kb + 2 < KT) { load_stage(kb + 2, (kb + 2) % 3); cp_commit(); }
        else             { cp_commit(); }
        const int buf = kb % 3;

#pragma unroll
        for (int ks = 0; ks < 2; ks++) {
            const int k0 = ks * 8;
            uint32_t bf[4][2];
#pragma unroll
            for (int nt = 0; nt < 4; nt++) {
                bf[nt][0] = __float_as_uint(cx.Bs[buf][cx.wn + nt * 8 + cx.g][k0 + cx.t4]);
                bf[nt][1] = __float_as_uint(cx.Bs[buf][cx.wn + nt * 8 + cx.g][k0 + cx.t4 + 4]);
            }
#pragma unroll
            for (int mt = 0; mt < 4; mt++) {
                uint32_t a0 = __float_as_uint(cx.As[buf][cx.wm + mt * 16 + cx.g][k0 + cx.t4]);
                uint32_t a1 = __float_as_uint(cx.As[buf][cx.wm + mt * 16 + cx.g + 8][k0 + cx.t4]);
                uint32_t a2 = __float_as_uint(cx.As[buf][cx.wm + mt * 16 + cx.g][k0 + cx.t4 + 4]);
                uint32_t a3 = __float_as_uint(cx.As[buf][cx.wm + mt * 16 + cx.g + 8][k0 + cx.t4 + 4]);
#pragma unroll
                for (int nt = 0; nt < 4; nt++)
                    mma_tf32(acc[mt][nt], a0, a1, a2, a3, bf[nt][0], bf[nt][1]);
            }
        }
        // no bottom barrier: buf kb%3 next written after iter kb+1's top sync
    }
}

// Fused Q/K/V/lr/wd projection: W = [Wq;Wk;Wv;Wlr;Wbeta;pad] (3200 rows).
__global__ __launch_bounds__(256, 2)
void gemm_qkv(const float* __restrict__ A, const float* __restrict__ W,
              float* __restrict__ Cq, float* __restrict__ Ck,
              float* __restrict__ Cv, float* __restrict__ Clr)
{
    extern __shared__ __align__(16) float gsm[];
    GemmCtx cx; gemm_init_ctx(cx, gsm);
    const int bm = blockIdx.y * 128;
    const int bn = blockIdx.x * 128;

    float acc[4][4][4];
    gemm_main(A, W, bm, bn, 1024, cx, acc);

    const int mat = bn >> 10;       // 0:q 1:k 2:v 3:lr/wd
    const int bnl = bn & 1023;

    if (mat == 3) {
        // sigmoid per token, store to lrx (pitch 128); cols >=64 are pad garbage
#pragma unroll
        for (int mt = 0; mt < 4; mt++) {
#pragma unroll
            for (int nt = 0; nt < 4; nt++) {
                int m = bm + cx.wm + mt * 16 + cx.g;
                int n = bnl + cx.wn + nt * 8 + cx.t4 * 2;
                float2 v0 = make_float2(1.f / (1.f + __expf(-acc[mt][nt][0])),
                                        1.f / (1.f + __expf(-acc[mt][nt][1])));
                float2 v1 = make_float2(1.f / (1.f + __expf(-acc[mt][nt][2])),
                                        1.f / (1.f + __expf(-acc[mt][nt][3])));
                *(float2*)&Clr[(size_t)m * 128 + n]       = v0;
                *(float2*)&Clr[(size_t)(m + 8) * 128 + n] = v1;
            }
        }
        return;
    }

    float* Cd = (mat == 0) ? Cq : (mat == 1) ? Ck : Cv;
    const bool act = (mat < 2);

#pragma unroll
    for (int mt = 0; mt < 4; mt++) {
#pragma unroll
        for (int nt = 0; nt < 4; nt++) {
            int m = bm + cx.wm + mt * 16 + cx.g;
            int n = bnl + cx.wn + nt * 8 + cx.t4 * 2;
            float2 v0 = make_float2(acc[mt][nt][0], acc[mt][nt][1]);
            float2 v1 = make_float2(acc[mt][nt][2], acc[mt][nt][3]);
            if (act) {
                v0.x = v0.x / (1.f + __expf(-v0.x));
                v0.y = v0.y / (1.f + __expf(-v0.y));
                v1.x = v1.x / (1.f + __expf(-v1.x));
                v1.y = v1.y / (1.f + __expf(-v1.y));
            }
            v0.x = cvt_tf32f(v0.x); v0.y = cvt_tf32f(v0.y);
            v1.x = cvt_tf32f(v1.x); v1.y = cvt_tf32f(v1.y);
            *(float2*)&Cd[(size_t)m * 1024 + n]       = v0;
            *(float2*)&Cd[(size_t)(m + 8) * 1024 + n] = v1;
        }
    }
}

// Final output projection: fp32 stores.
__global__ __launch_bounds__(256, 2)
void gemm_out(const float* __restrict__ A, const float* __restrict__ W,
              float* __restrict__ C)
{
    extern __shared__ __align__(16) float gsm[];
    GemmCtx cx; gemm_init_ctx(cx, gsm);
    const int bm = blockIdx.y * 128;
    const int bn = blockIdx.x * 128;

    float acc[4][4][4];
    gemm_main(A, W, bm, bn, 1024, cx, acc);

#pragma unroll
    for (int mt = 0; mt < 4; mt++) {
#pragma unroll
        for (int nt = 0; nt < 4; nt++) {
            int m = bm + cx.wm + mt * 16 + cx.g;
            int n = bn + cx.wn + nt * 8 + cx.t4 * 2;
            *(float2*)&C[(size_t)m * 1024 + n] =
                make_float2(acc[mt][nt][0], acc[mt][nt][1]);
            *(float2*)&C[(size_t)(m + 8) * 1024 + n] =
                make_float2(acc[mt][nt][2], acc[mt][nt][3]);
        }
    }
}

// ---------------------------------------------------------------------------
// lr/wd chunk means from per-token sigmoid outputs (deterministic)
// ---------------------------------------------------------------------------
__global__ __launch_bounds__(64)
void lrwd_reduce(const float* __restrict__ lrx)
{
    const int bc = blockIdx.x;          // b*64 + chunk
    const int j  = threadIdx.x;         // 0..63
    const float* p = lrx + (size_t)bc * 64 * 128 + j;
    float s = 0.f;
#pragma unroll 8
    for (int n = 0; n < 64; n++) s += p[(size_t)n * 128];
    g_lrwd[bc * 64 + j] = s * (1.f / 64.f) * ((j < 32) ? 0.001f : 0.9f);
}

// ---------------------------------------------------------------------------
// Cluster-2 persistent scan: all-mma gemmlets with tf32-bit state shadows
// (Wi_t/Wo_t) and bit-stored Pq/Pk; cp.async prefetch; exp fused into P2;
// one cluster sync per chunk (parity exchange buffers).
// ---------------------------------------------------------------------------
#define P64 68
#define P32 36

#define OFF_WI   0                           // [32][68] fp32 master
#define OFF_WO   (32 * P64)
#define OFF_WIT  (2 * 32 * P64)              // [32][68] tf32-bit shadows
#define OFF_WOT  (OFF_WIT + 32 * P64)
#define OFF_T    (OFF_WOT + 32 * P64)        // tiles [2 bufs][3][64][68]
#define TILE_SZ  (64 * P64)
#define OFF_PQ   (OFF_T + 6 * TILE_SZ)       // [64][36] tf32 bits after P3
#define OFF_PK   (OFF_PQ + 64 * P32)
#define OFF_AM   (OFF_PK + 64 * P32)
#define OFF_OP   (OFF_AM + 64 * P32)         // [2][64][68] parity buffers
#define OFF_SP   (OFF_OP + 2 * TILE_SZ)      // [2][64]
#define OFF_SS   (OFF_SP + 128)
#define OFF_RED  (OFF_SS + 64)               // [4][64]
#define OFF_CS   (OFF_RED + 256)
#define SCAN_SMEM_FLOATS (OFF_CS + 64)       // 50944 -> 203776 bytes

__global__ __launch_bounds__(256, 1) __cluster_dims__(2, 1, 1)
void scan_kernel(const float* __restrict__ Win0, const float* __restrict__ Wout0)
{
    extern __shared__ float sm[];
    float* Wi  = sm + OFF_WI;
    float* Wo_ = sm + OFF_WO;
    float* Wit = sm + OFF_WIT;
    float* Wot = sm + OFF_WOT;
    float* Pq  = sm + OFF_PQ;
    float* Pk  = sm + OFF_PK;
    float* Am  = sm + OFF_AM;
    float* ss  = sm + OFF_SS;
    float* red = sm + OFF_RED;
    float* cs  = sm + OFF_CS;

    const int pair = blockIdx.x >> 1;
    const uint32_t rank = blockIdx.x & 1;
    const int b = pair >> 4;
    const int h = pair & 15;
    const int t = threadIdx.x;

    const int w    = t >> 5;
    const int lane = t & 31;
    const int g    = lane >> 2;
    const int t4   = lane & 3;
    const int task = t & 63, sg = t >> 6;

    const uint32_t op_peer0 = mapa_u32((uint32_t)__cvta_generic_to_shared(sm + OFF_OP), rank ^ 1u);
    const uint32_t sp_peer0 = mapa_u32((uint32_t)__cvta_generic_to_shared(sm + OFF_SP), rank ^ 1u);

    for (int i = t; i < 2048; i += 256) {
        int Dl = i >> 6, d = i & 63;
        int Dg = (int)rank * 32 + Dl;
        float wi = Win0 [Dg * 1024 + h * 64 + d];
        float wo = Wout0[Dg * 1024 + h * 64 + d];
        Wi [Dl * P64 + d] = wi;  Wit[Dl * P64 + d] = cvt_tf32f(wi);
        Wo_[Dl * P64 + d] = wo;  Wot[Dl * P64 + d] = cvt_tf32f(wo);
    }

    auto prefetch = [&](int c, int buf) {
        const size_t base = ((size_t)b * L_ + (size_t)c * 64) * 1024 + h * 64;
        float* Qb = sm + OFF_T + (buf * 3 + 0) * TILE_SZ;
        float* Kb = sm + OFF_T + (buf * 3 + 1) * TILE_SZ;
        float* Vb = sm + OFF_T + (buf * 3 + 2) * TILE_SZ;
        for (int i = t; i < 1024; i += 256) {
            int n = i >> 4, d4 = (i & 15) * 4;
            size_t gidx = base + (size_t)n * 1024 + d4;
            cp16(&Qb[n * P64 + d4], &g_q[gidx]);
            cp16(&Kb[n * P64 + d4], &g_k[gidx]);
            cp16(&Vb[n * P64 + d4], &g_v[gidx]);
        }
    };

    prefetch(0, 0); cp_commit();
    __syncthreads();

    for (int c = 0; c < NCHUNK_; c++) {
        const int buf = c & 1;
        const float* Q  = sm + OFF_T + (buf * 3 + 0) * TILE_SZ;
        const float* Kt = sm + OFF_T + (buf * 3 + 1) * TILE_SZ;
        const float* V  = sm + OFF_T + (buf * 3 + 2) * TILE_SZ;
        float* op = sm + OFF_OP + buf * TILE_SZ;
        float* sp = sm + OFF_SP + buf * 64;
        const uint32_t op_peer = op_peer0 + (uint32_t)(buf * TILE_SZ) * 4u;
        const uint32_t sp_peer = sp_peer0 + (uint32_t)(buf * 64) * 4u;

        const size_t base = ((size_t)b * L_ + (size_t)c * 64) * 1024 + h * 64;
        const int lb = (b * 64 + c) * 64;
        const float li  = g_lrwd[lb + h];
        const float lo  = g_lrwd[lb + 16 + h];
        const float wdi = g_lrwd[lb + 32 + h];
        const float wdo = g_lrwd[lb + 48 + h];

        // ---- P1
        cp_wait<0>();
        __syncthreads();
        if (c + 1 < NCHUNK_) { prefetch(c + 1, buf ^ 1); cp_commit(); }

        // ---- P2 (mma): logits from bit shadows; exp fused into epilogue
        {
            const float* src = (w < 4) ? Q  : Kt;
            float*       dst = (w < 4) ? Pq : Pk;
            const int m0 = 16 * (w & 3);
            float C_[4][4];
#pragma unroll
            for (int j = 0; j < 4; j++)
#pragma unroll
                for (int x2 = 0; x2 < 4; x2++) C_[j][x2] = 0.f;
#pragma unroll
            for (int kk = 0; kk < 8; kk++) {
                const int k0 = kk * 8;
                uint32_t a0 = __float_as_uint(src[(m0 + g)     * P64 + k0 + t4]);
                uint32_t a1 = __float_as_uint(src[(m0 + g + 8) * P64 + k0 + t4]);
                uint32_t a2 = __float_as_uint(src[(m0 + g)     * P64 + k0 + t4 + 4]);
                uint32_t a3 = __float_as_uint(src[(m0 + g + 8) * P64 + k0 + t4 + 4]);
#pragma unroll
                for (int j = 0; j < 4; j++) {
                    uint32_t b0 = __float_as_uint(Wit[(8 * j + g) * P64 + k0 + t4]);
                    uint32_t b1 = __float_as_uint(Wit[(8 * j + g) * P64 + k0 + t4 + 4]);
                    mma_tf32(C_[j], a0, a1, a2, a3, b0, b1);
                }
            }
#pragma unroll
            for (int j = 0; j < 4; j++) {
                dst[(m0 + g)     * P32 + 8 * j + 2 * t4]     = __expf(C_[j][0]);
                dst[(m0 + g)     * P32 + 8 * j + 2 * t4 + 1] = __expf(C_[j][1]);
                dst[(m0 + g + 8) * P32 + 8 * j + 2 * t4]     = __expf(C_[j][2]);
                dst[(m0 + g + 8) * P32 + 8 * j + 2 * t4 + 1] = __expf(C_[j][3]);
            }
        }
        __syncthreads();

        // ---- P3: normalize + store tf32 bits
        {
            float* Pp = (task < 32) ? Pq : Pk;
            const int D = task & 31;
            float s = 0.f;
#pragma unroll
            for (int n = sg * 16; n < sg * 16 + 16; n++) s += Pp[n * P32 + D];
            red[sg * 64 + task] = s;
            __syncthreads();
            if (t < 64) cs[t] = 1.f / (red[t] + red[64 + t] + red[128 + t] + red[192 + t]);
            __syncthreads();
            float inv = cs[task];
#pragma unroll
            for (int n = sg * 16; n < sg * 16 + 16; n++)
                Pp[n * P32 + D] = cvt_tf32f(Pp[n * P32 + D] * inv);
        }
        __syncthreads();

        // ---- P4a (mma): op[n][d] = sum_Dl Pq[n][Dl] * Wo_[Dl][d]  (all bits)
        {
            const int m0 = 16 * (w & 3);
            const int nb = 32 * (w >> 2);
            float Co[4][4];
#pragma unroll
            for (int j = 0; j < 4; j++)
#pragma unroll
                for (int x2 = 0; x2 < 4; x2++) Co[j][x2] = 0.f;
#pragma unroll
            for (int kk = 0; kk < 4; kk++) {
                const int k0 = kk * 8;
                uint32_t a0 = __float_as_uint(Pq[(m0 + g)     * P32 + k0 + t4]);
                uint32_t a1 = __float_as_uint(Pq[(m0 + g + 8) * P32 + k0 + t4]);
                uint32_t a2 = __float_as_uint(Pq[(m0 + g)     * P32 + k0 + t4 + 4]);
                uint32_t a3 = __float_as_uint(Pq[(m0 + g + 8) * P32 + k0 + t4 + 4]);
#pragma unroll
                for (int j = 0; j < 4; j++) {
                    const int dcol = nb + 8 * j + g;
                    uint32_t b0 = __float_as_uint(Wot[(k0 + t4)     * P64 + dcol]);
                    uint32_t b1 = __float_as_uint(Wot[(k0 + t4 + 4) * P64 + dcol]);
                    mma_tf32(Co[j], a0, a1, a2, a3, b0, b1);
                }
            }
#pragma unroll
            for (int j = 0; j < 4; j++) {
                const int col = nb + 8 * j + 2 * t4;
                op[(m0 + g)     * P64 + col]     = Co[j][0];
                op[(m0 + g)     * P64 + col + 1] = Co[j][1];
                op[(m0 + g + 8) * P64 + col]     = Co[j][2];
                op[(m0 + g + 8) * P64 + col + 1] = Co[j][3];
            }
        }

        // ---- P4b (mma): Am[n][Dl] = sum_d V[n][d]*Wo_[Dl][d]  (bits)
        {
            const int m0 = 16 * (w & 3);
            const int nb = (w >> 2) * 16;
            float Ca[2][4];
#pragma unroll
            for (int j = 0; j < 2; j++)
#pragma unroll
                for (int x2 = 0; x2 < 4; x2++) Ca[j][x2] = 0.f;
#pragma unroll
            for (int kk = 0; kk < 8; kk++) {
                const int k0 = kk * 8;
                uint32_t a0 = __float_as_uint(V[(m0 + g)     * P64 + k0 + t4]);
                uint32_t a1 = __float_as_uint(V[(m0 + g + 8) * P64 + k0 + t4]);
                uint32_t a2 = __float_as_uint(V[(m0 + g)     * P64 + k0 + t4 + 4]);
                uint32_t a3 = __float_as_uint(V[(m0 + g + 8) * P64 + k0 + t4 + 4]);
#pragma unroll
                for (int j = 0; j < 2; j++) {
                    const int Dl = nb + 8 * j + g;
                    uint32_t b0 = __float_as_uint(Wot[Dl * P64 + k0 + t4]);
                    uint32_t b1 = __float_as_uint(Wot[Dl * P64 + k0 + t4 + 4]);
                    mma_tf32(Ca[j], a0, a1, a2, a3, b0, b1);
                }
            }
#pragma unroll
            for (int j = 0; j < 2; j++) {
                Am[(m0 + g)     * P32 + nb + 8 * j + 2 * t4]     = Ca[j][0];
                Am[(m0 + g)     * P32 + nb + 8 * j + 2 * t4 + 1] = Ca[j][1];
                Am[(m0 + g + 8) * P32 + nb + 8 * j + 2 * t4]     = Ca[j][2];
                Am[(m0 + g + 8) * P32 + nb + 8 * j + 2 * t4 + 1] = Ca[j][3];
            }
        }
        __syncthreads();

        // ---- sp, then ONE cluster sync
        if (t < 64) {
            float s = 0.f;
#pragma unroll 8
            for (int Dl = 0; Dl < 32; Dl++) s += Pk[t * P32 + Dl] * Am[t * P32 + Dl];
            sp[t] = s;
        }
        CLUSTER_SYNC();

        // ---- P5: o exchange + ss
        for (int i = t; i < 2048; i += 256) {
            int n = (int)rank * 32 + (i >> 6), d = i & 63;
            float v2 = op[n * P64 + d] + ld_dsmem(op_peer + (uint32_t)(n * P64 + d) * 4u);
            g_o[base + (size_t)n * 1024 + d] = cvt_tf32f(v2);
        }
        if (t < 64) ss[t] = sp[t] + ld_dsmem(sp_peer + (uint32_t)t * 4u);
        __syncthreads();

        // ---- P7 (mma): grads + state update (+ shadow refresh)
        {
            const int m0 = 16 * (w & 1);
            const int nb = (w >> 1) * 16;
            float Cgi[2][4], Cgo[2][4];
#pragma unroll
            for (int j = 0; j < 2; j++)
#pragma unroll
                for (int x2 = 0; x2 < 4; x2++) { Cgi[j][x2] = 0.f; Cgo[j][x2] = 0.f; }
#pragma unroll
            for (int kk = 0; kk < 8; kk++) {
                const int ka = kk * 8 + t4;
                const int kb2 = ka + 4;
                float ssa = ss[ka], ssb = ss[kb2];
                float pk0 = Pk[ka  * P32 + m0 + g],     am0 = Am[ka  * P32 + m0 + g];
                float pk1 = Pk[ka  * P32 + m0 + g + 8], am1 = Am[ka  * P32 + m0 + g + 8];
                float pk2 = Pk[kb2 * P32 + m0 + g],     am2 = Am[kb2 * P32 + m0 + g];
                float pk3 = Pk[kb2 * P32 + m0 + g + 8], am3 = Am[kb2 * P32 + m0 + g + 8];
                uint32_t gz0 = f2t(-pk0 * (am0 - ssa));
                uint32_t gz1 = f2t(-pk1 * (am1 - ssa));
                uint32_t gz2 = f2t(-pk2 * (am2 - ssb));
                uint32_t gz3 = f2t(-pk3 * (am3 - ssb));
                uint32_t p0 = __float_as_uint(pk0), p1 = __float_as_uint(pk1);
                uint32_t p2 = __float_as_uint(pk2), p3 = __float_as_uint(pk3);
#pragma unroll
                for (int j = 0; j < 2; j++) {
                    const int dcol = nb + 8 * j + g;
                    uint32_t bk0 = __float_as_uint(Kt[ka  * P64 + dcol]);
                    uint32_t bk1 = __float_as_uint(Kt[kb2 * P64 + dcol]);
                    uint32_t bv0 = __float_as_uint(V [ka  * P64 + dcol]);
                    uint32_t bv1 = __float_as_uint(V [kb2 * P64 + dcol]);
                    mma_tf32(Cgi[j], gz0, gz1, gz2, gz3, bk0, bk1);
                    mma_tf32(Cgo[j], p0,  p1,  p2,  p3,  bv0, bv1);
                }
            }
#pragma unroll
            for (int j = 0; j < 2; j++) {
                const int col = nb + 8 * j + 2 * t4;
                const int i0 = (m0 + g)     * P64 + col;
                const int i1 = (m0 + g + 8) * P64 + col;
                float n0 = wdi * Wi[i0]     - li * Cgi[j][0];
                float n1 = wdi * Wi[i0 + 1] - li * Cgi[j][1];
                float n2 = wdi * Wi[i1]     - li * Cgi[j][2];
                float n3 = wdi * Wi[i1 + 1] - li * Cgi[j][3];
                Wi[i0] = n0; Wi[i0 + 1] = n1; Wi[i1] = n2; Wi[i1 + 1] = n3;
                Wit[i0] = cvt_tf32f(n0); Wit[i0 + 1] = cvt_tf32f(n1);
                Wit[i1] = cvt_tf32f(n2); Wit[i1 + 1] = cvt_tf32f(n3);
                float m0_ = wdo * Wo_[i0]     + lo * Cgo[j][0];
                float m1_ = wdo * Wo_[i0 + 1] + lo * Cgo[j][1];
                float m2_ = wdo * Wo_[i1]     + lo * Cgo[j][2];
                float m3_ = wdo * Wo_[i1 + 1] + lo * Cgo[j][3];
                Wo_[i0] = m0_; Wo_[i0 + 1] = m1_; Wo_[i1] = m2_; Wo_[i1 + 1] = m3_;
                Wot[i0] = cvt_tf32f(m0_); Wot[i0 + 1] = cvt_tf32f(m1_);
                Wot[i1] = cvt_tf32f(m2_); Wot[i1 + 1] = cvt_tf32f(m3_);
            }
        }
        __syncthreads();
    }
    CLUSTER_SYNC();
}

// ---------------------------------------------------------------------------
// Launch
// ---------------------------------------------------------------------------
extern "C" void kernel_launch(void* const* d_in, const int* in_sizes, int n_in,
                              void* d_out, int out_size)
{
    (void)in_sizes; (void)n_in; (void)out_size;
    const float* x     = (const float*)d_in[0];
    const float* Wq    = (const float*)d_in[1];
    const float* Wk    = (const float*)d_in[2];
    const float* Wv    = (const float*)d_in[3];
    const float* Wlr   = (const float*)d_in[4];
    const float* Wbeta = (const float*)d_in[5];
    const float* Wo    = (const float*)d_in[6];
    const float* Win0  = (const float*)d_in[7];
    const float* Wout0 = (const float*)d_in[8];
    float* out = (float*)d_out;

    float *q, *k, *v, *om, *xt, *wcat, *wo, *lrx;
    cudaGetSymbolAddress((void**)&q,    g_q);
    cudaGetSymbolAddress((void**)&k,    g_k);
    cudaGetSymbolAddress((void**)&v,    g_v);
    cudaGetSymbolAddress((void**)&om,   g_o);
    cudaGetSymbolAddress((void**)&xt,   g_xt);
    cudaGetSymbolAddress((void**)&wcat, g_wcat);
    cudaGetSymbolAddress((void**)&wo,   g_wo);
    cudaGetSymbolAddress((void**)&lrx,  g_lrx);

    cudaFuncSetAttribute(gemm_qkv, cudaFuncAttributeMaxDynamicSharedMemorySize, GEMM_SMEM_BYTES);
    cudaFuncSetAttribute(gemm_out, cudaFuncAttributeMaxDynamicSharedMemorySize, GEMM_SMEM_BYTES);
    cudaFuncSetAttribute(scan_kernel, cudaFuncAttributeMaxDynamicSharedMemorySize,
                         SCAN_SMEM_FLOATS * (int)sizeof(float));

    const int NX4 = (M_ * 1024) / 4;
    const int NW4 = (1024 * 1024) / 4;
    const int NS4 = (32 * 1024) / 4;
    cvt_kernel<<<(NX4 + 255) / 256, 256>>>(x,     xt,                     NX4);
    cvt_kernel<<<(NW4 + 255) / 256, 256>>>(Wq,    wcat + 0u * 1024u * 1024u, NW4);
    cvt_kernel<<<(NW4 + 255) / 256, 256>>>(Wk,    wcat + 1u * 1024u * 1024u, NW4);
    cvt_kernel<<<(NW4 + 255) / 256, 256>>>(Wv,    wcat + 2u * 1024u * 1024u, NW4);
    cvt_kernel<<<(NS4 + 255) / 256, 256>>>(Wlr,   wcat + 3072u * 1024u,      NS4);
    cvt_kernel<<<(NS4 + 255) / 256, 256>>>(Wbeta, wcat + 3104u * 1024u,      NS4);
    cvt_kernel<<<(NW4 + 255) / 256, 256>>>(Wo,    wo,                        NW4);
    // wcat rows 3136..3199 never written -> stay zero (module-load zero init)

    // fused q/k/v + lr/wd projection: N = 3200
    dim3 grid_qkv(3200 / 128, M_ / 128);
    gemm_qkv<<<grid_qkv, 256, GEMM_SMEM_BYTES>>>(xt, wcat, q, k, v, lrx);
    lrwd_reduce<<<B_ * NCHUNK_, 64>>>(lrx);

    const int smem_bytes = SCAN_SMEM_FLOATS * (int)sizeof(float);
    scan_kernel<<<128, 256, smem_bytes>>>(Win0, Wout0);

    dim3 grid_o(1024 / 128, M_ / 128);
    gemm_out<<<grid_o, 256, GEMM_SMEM_BYTES>>>(om, wo, out);
}